// round 11
// baseline (speedup 1.0000x reference)
#include <cuda_runtime.h>
#include <cuda_bf16.h>
#include <cuda_fp16.h>
#include <cstdint>

// Problem constants
#define NB   32
#define NS   1024
#define DIN  512
#define DH   512
#define DOUT 512
#define NHD  2
#define DHH  256
#define ROWS (NB*NS)             // 32768
#define SCSZ (67108864L)         // NB*NHD*NS*NS

// ============================ helpers ============================
__device__ __forceinline__ uint32_t smem_to_u32(const void* p) {
    uint32_t a;
    asm("{ .reg .u64 t; cvta.to.shared.u64 t, %1; cvt.u32.u64 %0, t; }" : "=r"(a) : "l"(p));
    return a;
}
__device__ __forceinline__ void ldsm4(uint32_t* r, uint32_t addr) {
    asm volatile("ldmatrix.sync.aligned.m8n8.x4.shared.b16 {%0,%1,%2,%3}, [%4];"
                 : "=r"(r[0]), "=r"(r[1]), "=r"(r[2]), "=r"(r[3]) : "r"(addr));
}
__device__ __forceinline__ void mma16816(float* d, const uint32_t* a, const uint32_t* b) {
    asm volatile("mma.sync.aligned.m16n8k16.row.col.f32.f16.f16.f32 "
                 "{%0,%1,%2,%3}, {%4,%5,%6,%7}, {%8,%9}, {%0,%1,%2,%3};"
                 : "+f"(d[0]), "+f"(d[1]), "+f"(d[2]), "+f"(d[3])
                 : "r"(a[0]), "r"(a[1]), "r"(a[2]), "r"(a[3]), "r"(b[0]), "r"(b[1]));
}
__device__ __forceinline__ void cpa16(uint32_t s, const void* g) {
    asm volatile("cp.async.cg.shared.global [%0], [%1], 16;" :: "r"(s), "l"(g));
}
__device__ __forceinline__ void cpcommit() { asm volatile("cp.async.commit_group;"); }
template<int N> __device__ __forceinline__ void cpwait() {
    asm volatile("cp.async.wait_group %0;" :: "n"(N));
}

// smem: 3 tiles (Ah, Al, B) of 128 rows x 64B (32 fp16), XOR-swizzled, 4 stages
#define ATILEB 8192               // 128*64
#define STAGEB (3*ATILEB)         // 24576
#define NSTG   4
#define MMSMEM (NSTG*STAGEB)      // 98304
#define SWZ(row, chunk) ((uint32_t)(row)*64u + ((uint32_t)((chunk) ^ (((row)>>1)&3))*16u))

// ============================ scratch buffers ============================
__device__ float g_h   [ROWS*DH];
__device__ float g_sc  [SCSZ];
__device__ float g_t1  [ROWS*DH];
__device__ float g_x1  [ROWS*DH];
__device__ float g_x2  [ROWS*DH];
__device__ float g_poolp[NB*8*DH];
__device__ float g_pool[NB*DH];
__device__ unsigned int g_mskw [(long)NB*NS*32];   // bitmask adjacency, 4MB

__device__ __half g_xh[ROWS*DIN],   g_xl[ROWS*DIN];
__device__ __half g_hh[ROWS*DH],    g_hl[ROWS*DH];
__device__ __half g_qkvh[ROWS*3*DH],g_qkvl[ROWS*3*DH];
__device__ __half g_ah[SCSZ],       g_al[SCSZ];
__device__ __half g_vth[(long)NB*NHD*DHH*NS];
__device__ __half g_ctxh[ROWS*DH],  g_ctxl[ROWS*DH];
__device__ __half g_x1h[ROWS*DH],   g_x1l[ROWS*DH];
__device__ __half g_midh[ROWS*2*DH],g_midl[ROWS*2*DH];
__device__ __half g_nh[ROWS*DH],    g_nl[ROWS*DH];
__device__ __half g_cbh[ROWS*2*DH], g_cbl[ROWS*2*DH];
__device__ __half g_wh[4*1024*1024];

// weight offsets (elements)
#define WO_ENC 0
#define WO_IN  262144
#define WO_OUT 1048576
#define WO_F1  1310720
#define WO_F2  1835008
#define WO_GC  2359296

// ============================ HMMA GEMM (fp16x2, cp.async 4-stage, 2 CTA/SM) ============
template<int ACT, int RES, int WSPLIT, int WFP32>
__global__ void __launch_bounds__(256, 2)
mmagemm_k(const __half* __restrict__ Ah, const __half* __restrict__ Al,
          const __half* __restrict__ Bm,
          const float* __restrict__ bias, const float* __restrict__ Rres,
          float* __restrict__ C, __half* __restrict__ Ch, __half* __restrict__ Cl,
          int K, int lda, int ldb, int ldc,
          long sA1, long sA2, long sB1, long sB2, long sC1, long sC2, int HZ)
{
    extern __shared__ char sm[];
    uint32_t sb = smem_to_u32(sm);

    int tid = threadIdx.x, wid = tid >> 5, lid = tid & 31;
    int wm = wid >> 1, wn = wid & 1;
    int z = blockIdx.z, zb = z / HZ, zh = z - zb * HZ;
    long aoff = (long)zb * sA2 + (long)zh * sA1;
    long boff = (long)zb * sB2 + (long)zh * sB1;
    long coff = (long)zb * sC2 + (long)zh * sC1;
    int m0 = blockIdx.y * 128, n0 = blockIdx.x * 128;

    const __half* Ahp = Ah + aoff + (long)m0 * lda;
    const __half* Alp = Al + aoff + (long)m0 * lda;
    const __half* Bp  = Bm + boff + (long)n0 * ldb;

    int lrow = tid >> 1, c0 = (tid & 1) * 2;
    const char* pAh = (const char*)(Ahp + (long)lrow * lda) + c0 * 16;
    const char* pAl = (const char*)(Alp + (long)lrow * lda) + c0 * 16;
    const char* pB  = (const char*)(Bp  + (long)lrow * ldb) + c0 * 16;
    uint32_t d0 = SWZ(lrow, c0), d1 = SWZ(lrow, c0 + 1);

#define ISSUE(stg, c) do { long ob = (long)(c) * 64; uint32_t bp = sb + (stg) * STAGEB; \
    cpa16(bp + d0,            pAh + ob); cpa16(bp + d1,            pAh + ob + 16); \
    cpa16(bp + ATILEB + d0,   pAl + ob); cpa16(bp + ATILEB + d1,   pAl + ob + 16); \
    cpa16(bp + 2*ATILEB + d0, pB  + ob); cpa16(bp + 2*ATILEB + d1, pB  + ob + 16); } while (0)

    int arow = wm * 32 + ((lid >> 3) & 1) * 8 + (lid & 7);
    int acsel = (lid >> 4) & 1;
    uint32_t axor = (uint32_t)((arow >> 1) & 3);
    int brow = wn * 64 + ((lid >> 4) & 1) * 8 + (lid & 7);
    int bcsel = (lid >> 3) & 1;
    uint32_t bxor = (uint32_t)((brow >> 1) & 3);

    float d[2][8][4];
#pragma unroll
    for (int i = 0; i < 2; i++)
#pragma unroll
        for (int j = 0; j < 8; j++)
#pragma unroll
            for (int q = 0; q < 4; q++) d[i][j][q] = 0.f;

    const int nCh = K >> 5;
    ISSUE(0, 0); cpcommit();
    ISSUE(1, 1); cpcommit();
    ISSUE(2, 2); cpcommit();

    int stg = 0;
    for (int c = 0; c < nCh; c++) {
        cpwait<2>();
        __syncthreads();
        if (c + 3 < nCh) {
            int ns = stg + 3; if (ns >= NSTG) ns -= NSTG;
            ISSUE(ns, c + 3);
        }
        cpcommit();

        uint32_t cb = sb + stg * STAGEB;
#pragma unroll
        for (int ks = 0; ks < 2; ks++) {
            uint32_t fah[2][4], fal[2][4], fb[4][4];
#pragma unroll
            for (int mf = 0; mf < 2; mf++) {
                uint32_t ad = cb + (uint32_t)(arow + mf * 16) * 64u
                            + (((uint32_t)(ks * 2 + acsel) ^ axor) * 16u);
                ldsm4(fah[mf], ad);
                ldsm4(fal[mf], ad + ATILEB);
            }
#pragma unroll
            for (int np = 0; np < 4; np++) {
                uint32_t bd = cb + 2 * ATILEB + (uint32_t)(brow + np * 16) * 64u
                            + (((uint32_t)(ks * 2 + bcsel) ^ bxor) * 16u);
                ldsm4(fb[np], bd);
            }
#pragma unroll
            for (int mf = 0; mf < 2; mf++)
#pragma unroll
                for (int nf = 0; nf < 8; nf++)
                    mma16816(d[mf][nf], fah[mf], &fb[nf >> 1][(nf & 1) * 2]);
#pragma unroll
            for (int mf = 0; mf < 2; mf++)
#pragma unroll
                for (int nf = 0; nf < 8; nf++)
                    mma16816(d[mf][nf], fal[mf], &fb[nf >> 1][(nf & 1) * 2]);
        }
        if (++stg >= NSTG) stg = 0;
    }
#undef ISSUE

    int g = lid >> 2, tg = lid & 3;
#pragma unroll
    for (int mf = 0; mf < 2; mf++) {
#pragma unroll
        for (int cp = 0; cp < 2; cp++) {
            int m = m0 + wm * 32 + mf * 16 + cp * 8 + g;
            long rb = (long)m * ldc + coff;
#pragma unroll
            for (int nf = 0; nf < 8; nf++) {
                int n = n0 + wn * 64 + nf * 8 + tg * 2;
                float v0 = d[mf][nf][cp * 2];
                float v1 = d[mf][nf][cp * 2 + 1];
                if (bias) { v0 += bias[n]; v1 += bias[n + 1]; }
                if (ACT) { v0 = fmaxf(v0, 0.f); v1 = fmaxf(v1, 0.f); }
                if (RES) { v0 += Rres[rb + n]; v1 += Rres[rb + n + 1]; }
                if (WFP32)
                    *reinterpret_cast<float2*>(C + rb + n) = make_float2(v0, v1);
                if (WSPLIT) {
                    __half h0 = __float2half_rn(v0);
                    __half h1 = __float2half_rn(v1);
                    __half2 hh; hh.x = h0; hh.y = h1;
                    *reinterpret_cast<__half2*>(Ch + rb + n) = hh;
                    __half2 ll;
                    ll.x = __float2half_rn(v0 - __half2float(h0));
                    ll.y = __float2half_rn(v1 - __half2float(h1));
                    *reinterpret_cast<__half2*>(Cl + rb + n) = ll;
                }
            }
        }
    }
}

// ============================ SIMT GEMM (small final only) ============================
template<int TB, int ACT, int RES>
__global__ void gemm_k(const float* __restrict__ A, const float* __restrict__ Bm,
                       const float* __restrict__ bias, const float* __restrict__ R,
                       float* __restrict__ C,
                       int M, int N, int K, int lda, int ldb, int ldc)
{
    __shared__ float As[16][65];
    __shared__ float Bs[16][65];
    int tid = threadIdx.x;
    int tx = tid & 15, ty = tid >> 4;
    int m0 = blockIdx.y * 64, n0 = blockIdx.x * 64;
    float acc[4][4];
#pragma unroll
    for (int i = 0; i < 4; i++)
#pragma unroll
        for (int j = 0; j < 4; j++) acc[i][j] = 0.f;

    for (int k0 = 0; k0 < K; k0 += 16) {
#pragma unroll
        for (int i = 0; i < 4; i++) {
            int idx = tid + i * 256;
            int r = idx >> 4, kk = idx & 15;
            int m = m0 + r;
            As[kk][r] = (m < M) ? A[(long)m * lda + (k0 + kk)] : 0.f;
        }
#pragma unroll
        for (int i = 0; i < 4; i++) {
            int idx = tid + i * 256;
            int r = idx >> 4, kk = idx & 15;
            Bs[kk][r] = Bm[(long)(n0 + r) * ldb + (k0 + kk)];
        }
        __syncthreads();
#pragma unroll
        for (int kk = 0; kk < 16; kk++) {
            float a[4], b[4];
#pragma unroll
            for (int i = 0; i < 4; i++) a[i] = As[kk][ty + 16 * i];
#pragma unroll
            for (int j = 0; j < 4; j++) b[j] = Bs[kk][tx + 16 * j];
#pragma unroll
            for (int i = 0; i < 4; i++)
#pragma unroll
                for (int j = 0; j < 4; j++) acc[i][j] += a[i] * b[j];
        }
        __syncthreads();
    }
#pragma unroll
    for (int i = 0; i < 4; i++) {
        int m = m0 + ty + 16 * i;
        if (m >= M) continue;
#pragma unroll
        for (int j = 0; j < 4; j++) {
            int n = n0 + tx + 16 * j;
            float v = acc[i][j];
            if (bias) v += bias[n];
            if (ACT) v = fmaxf(v, 0.f);
            C[(long)m * ldc + n] = v;
        }
    }
}

// ============================ elementwise / reduction kernels ============================
__device__ __forceinline__ void split4_store(float4 v, __half* h, __half* l, long i)
{
    __half2 h0, h1, l0, l1;
    h0.x = __float2half_rn(v.x); h0.y = __float2half_rn(v.y);
    h1.x = __float2half_rn(v.z); h1.y = __float2half_rn(v.w);
    l0.x = __float2half_rn(v.x - __half2float(h0.x));
    l0.y = __float2half_rn(v.y - __half2float(h0.y));
    l1.x = __float2half_rn(v.z - __half2float(h1.x));
    l1.y = __float2half_rn(v.w - __half2float(h1.y));
    reinterpret_cast<__half2*>(h)[2 * i] = h0;
    reinterpret_cast<__half2*>(h)[2 * i + 1] = h1;
    reinterpret_cast<__half2*>(l)[2 * i] = l0;
    reinterpret_cast<__half2*>(l)[2 * i + 1] = l1;
}

__global__ void split_k(const float* __restrict__ s, __half* __restrict__ h,
                        __half* __restrict__ l, long n4)
{
    long i = (long)blockIdx.x * blockDim.x + threadIdx.x;
    if (i >= n4) return;
    split4_store(reinterpret_cast<const float4*>(s)[i], h, l, i);
}

__global__ void wsplit_k(const float* __restrict__ w0, const float* __restrict__ w1,
                         const float* __restrict__ w2, const float* __restrict__ w3,
                         const float* __restrict__ w4, const float* __restrict__ w5,
                         __half* __restrict__ h)
{
    long i = (long)blockIdx.x * blockDim.x + threadIdx.x;
    const float* src; long base;
    if      (i < 65536)  { src = w0; base = 0;      }
    else if (i < 262144) { src = w1; base = 65536;  }
    else if (i < 327680) { src = w2; base = 262144; }
    else if (i < 458752) { src = w3; base = 327680; }
    else if (i < 589824) { src = w4; base = 458752; }
    else if (i < 720896) { src = w5; base = 589824; }
    else return;
    float4 v = reinterpret_cast<const float4*>(src)[i - base];
    __half2 h0, h1;
    h0.x = __float2half_rn(v.x); h0.y = __float2half_rn(v.y);
    h1.x = __float2half_rn(v.z); h1.y = __float2half_rn(v.w);
    reinterpret_cast<__half2*>(h)[2 * i] = h0;
    reinterpret_cast<__half2*>(h)[2 * i + 1] = h1;
}

__global__ void vtrans_k(const __half* __restrict__ qh, const __half* __restrict__ ql,
                         __half* __restrict__ vth)
{
    int z = blockIdx.z, zb = z >> 1, zh = z & 1;
    int d0 = blockIdx.x * 32, k0 = blockIdx.y * 32;
    __shared__ float t[32][33];
    int tx = threadIdx.x, ty = threadIdx.y;
    long base = (long)zb * NS * 1536 + 1024 + zh * 256;
#pragma unroll
    for (int i = 0; i < 4; i++) {
        int k = k0 + ty + i * 8;
        long idx = base + (long)k * 1536 + d0 + tx;
        t[ty + i * 8][tx] = __half2float(qh[idx]) + __half2float(ql[idx]);
    }
    __syncthreads();
    __half* oh = vth + (long)z * DHH * NS;
#pragma unroll
    for (int i = 0; i < 4; i++) {
        int d = d0 + ty + i * 8;
        oh[(long)d * NS + k0 + tx] = __float2half_rn(t[tx][ty + i * 8]);
    }
}

// softmax (1/16 scale) + fp16 hi/lo split — shuffle reductions, 2 barriers
__global__ void softmax_split_k(const float* __restrict__ s,
                                __half* __restrict__ ah, __half* __restrict__ al)
{
    long row = blockIdx.x;
    const float* p = s + row * 1024;
    int t = threadIdx.x;              // 256
    float4 v4 = reinterpret_cast<const float4*>(p)[t];
    float v[4] = { v4.x * 0.0625f, v4.y * 0.0625f, v4.z * 0.0625f, v4.w * 0.0625f };
    float mx = fmaxf(fmaxf(v[0], v[1]), fmaxf(v[2], v[3]));
    __shared__ float wmax[8], wsum[8];
#pragma unroll
    for (int o = 16; o > 0; o >>= 1)
        mx = fmaxf(mx, __shfl_xor_sync(0xffffffffu, mx, o));
    if ((t & 31) == 0) wmax[t >> 5] = mx;
    __syncthreads();
#pragma unroll
    for (int w = 0; w < 8; w++) mx = fmaxf(mx, wmax[w]);
    float sum = 0.f;
#pragma unroll
    for (int i = 0; i < 4; i++) { v[i] = __expf(v[i] - mx); sum += v[i]; }
#pragma unroll
    for (int o = 16; o > 0; o >>= 1)
        sum += __shfl_xor_sync(0xffffffffu, sum, o);
    if ((t & 31) == 0) wsum[t >> 5] = sum;
    __syncthreads();
    sum = 0.f;
#pragma unroll
    for (int w = 0; w < 8; w++) sum += wsum[w];
    float inv = 1.f / sum;
    __half2 hh[2], ll[2];
#pragma unroll
    for (int i = 0; i < 4; i++) {
        float val = v[i] * inv;
        __half h = __float2half_rn(val);
        ((__half*)hh)[i] = h;
        ((__half*)ll)[i] = __float2half_rn(val - __half2float(h));
    }
    long ob = row * 1024 + t * 4;
    *reinterpret_cast<__half2*>(ah + ob)     = hh[0];
    *reinterpret_cast<__half2*>(ah + ob + 2) = hh[1];
    *reinterpret_cast<__half2*>(al + ob)     = ll[0];
    *reinterpret_cast<__half2*>(al + ob + 2) = ll[1];
}

// out = LN(a+r)*g+b — shuffle reductions, 1 barrier
__global__ void addln_k(const float* __restrict__ a, const float* __restrict__ r,
                        const float* __restrict__ g, const float* __restrict__ be,
                        float* __restrict__ o, __half* __restrict__ oh,
                        __half* __restrict__ ol)
{
    long row = blockIdx.x;
    int t = threadIdx.x;              // 256
    long base = row * 512;
    float v0 = a[base + t]       + r[base + t];
    float v1 = a[base + t + 256] + r[base + t + 256];
    float s = v0 + v1, sq = v0 * v0 + v1 * v1;
    __shared__ float ws[8], wq[8];
#pragma unroll
    for (int o2 = 16; o2 > 0; o2 >>= 1) {
        s  += __shfl_xor_sync(0xffffffffu, s,  o2);
        sq += __shfl_xor_sync(0xffffffffu, sq, o2);
    }
    if ((t & 31) == 0) { ws[t >> 5] = s; wq[t >> 5] = sq; }
    __syncthreads();
    s = 0.f; sq = 0.f;
#pragma unroll
    for (int w = 0; w < 8; w++) { s += ws[w]; sq += wq[w]; }
    float mu  = s * (1.f / 512.f);
    float var = sq * (1.f / 512.f) - mu * mu;
    float inv = rsqrtf(var + 1e-5f);
    float o0 = (v0 - mu) * inv * g[t]       + be[t];
    float o1 = (v1 - mu) * inv * g[t + 256] + be[t + 256];
    o[base + t] = o0; o[base + t + 256] = o1;
    if (oh) {
        __half h0 = __float2half_rn(o0), h1 = __float2half_rn(o1);
        oh[base + t] = h0; oh[base + t + 256] = h1;
        ol[base + t]       = __float2half_rn(o0 - __half2float(h0));
        ol[base + t + 256] = __float2half_rn(o1 - __half2float(h1));
    }
}

// row L2-normalize — shuffle reductions, 1 barrier
__global__ void rownorm_k(const float* __restrict__ x, __half* __restrict__ nh,
                          __half* __restrict__ nl)
{
    long row = blockIdx.x;
    int t = threadIdx.x;              // 256
    long base = row * 512;
    float v0 = x[base + t], v1 = x[base + t + 256];
    float sq = v0 * v0 + v1 * v1;
    __shared__ float wq[8];
#pragma unroll
    for (int o2 = 16; o2 > 0; o2 >>= 1)
        sq += __shfl_xor_sync(0xffffffffu, sq, o2);
    if ((t & 31) == 0) wq[t >> 5] = sq;
    __syncthreads();
    sq = 0.f;
#pragma unroll
    for (int w = 0; w < 8; w++) sq += wq[w];
    float sc = 1.f / fmaxf(sqrtf(sq), 1e-12f);
    float o0 = v0 * sc, o1 = v1 * sc;
    __half h0 = __float2half_rn(o0), h1 = __float2half_rn(o1);
    nh[base + t] = h0; nh[base + t + 256] = h1;
    nl[base + t]       = __float2half_rn(o0 - __half2float(h0));
    nl[base + t + 256] = __float2half_rn(o1 - __half2float(h1));
}

// merge two comparator-sorted top-4 lists -> top-4 (val desc, idx asc)
__device__ __forceinline__ void merge4(float* v, int* ix, const float* ov, const int* oi)
{
    float mv[4]; int mi[4];
    int a = 0, b = 0;
#pragma unroll
    for (int q = 0; q < 4; q++) {
        float av = v[a], bv = ov[b];
        int   ai = ix[a], bi = oi[b];
        bool ta = av > bv || (av == bv && ai < bi);
        if (ta) { mv[q] = av; mi[q] = ai; a++; }
        else    { mv[q] = bv; mi[q] = bi; b++; }
    }
#pragma unroll
    for (int q = 0; q < 4; q++) { v[q] = mv[q]; ix[q] = mi[q]; }
}

// exact top-4 per row + fused symmetric atomicOr scatter into bitmask
__global__ void topk_k(const float* __restrict__ sim, unsigned int* __restrict__ mskw)
{
    int row = blockIdx.x;
    int b = row >> 10, i = row & 1023;
    const float* p = sim + (long)row * 1024;
    int t = threadIdx.x;              // 128
    float v[4] = {-1e30f, -1e30f, -1e30f, -1e30f};
    int   ix[4] = {1 << 30, 1 << 30, 1 << 30, 1 << 30};
#pragma unroll
    for (int r = 0; r < 8; r++) {
        int j = t + r * 128;
        float val = p[j];
        if (val > v[3] || (val == v[3] && j < ix[3])) {
            v[3] = val; ix[3] = j;
#pragma unroll
            for (int q = 3; q > 0; q--) {
                bool up = v[q] > v[q-1] || (v[q] == v[q-1] && ix[q] < ix[q-1]);
                if (up) {
                    float tv = v[q]; v[q] = v[q-1]; v[q-1] = tv;
                    int ti = ix[q]; ix[q] = ix[q-1]; ix[q-1] = ti;
                }
            }
        }
    }
    // intra-warp butterfly merge (barrier-free)
#pragma unroll
    for (int off = 16; off > 0; off >>= 1) {
        float ov[4]; int oi[4];
#pragma unroll
        for (int q = 0; q < 4; q++) {
            ov[q] = __shfl_xor_sync(0xffffffffu, v[q], off);
            oi[q] = __shfl_xor_sync(0xffffffffu, ix[q], off);
        }
        merge4(v, ix, ov, oi);
    }
    __shared__ float sv[4][4];
    __shared__ int   si[4][4];
    if ((t & 31) == 0) {
#pragma unroll
        for (int q = 0; q < 4; q++) { sv[t >> 5][q] = v[q]; si[t >> 5][q] = ix[q]; }
    }
    __syncthreads();
    if (t == 0) {
        float fv[4]; int fi[4];
#pragma unroll
        for (int q = 0; q < 4; q++) { fv[q] = sv[0][q]; fi[q] = si[0][q]; }
        merge4(fv, fi, sv[1], si[1]);
        merge4(fv, fi, sv[2], si[2]);
        merge4(fv, fi, sv[3], si[3]);
        unsigned int* mb = mskw + (long)b * NS * 32;
#pragma unroll
        for (int q = 0; q < 4; q++) {
            int j = fi[q];
            if (j != i) {
                atomicOr(&mb[i * 32 + (j >> 5)], 1u << (j & 31));
                atomicOr(&mb[j * 32 + (i >> 5)], 1u << (i & 31));
            }
        }
    }
}

__global__ void zero_k(float4* __restrict__ p, long n)
{
    long i = (long)blockIdx.x * blockDim.x + threadIdx.x;
    if (i < n) p[i] = make_float4(0.f, 0.f, 0.f, 0.f);
}

// neighbor aggregate: extract compact list from bitmask first, then MLP-friendly gather
__global__ void combine_k(const float* __restrict__ x1, const float* __restrict__ sim,
                          const unsigned int* __restrict__ mskw,
                          __half* __restrict__ ch, __half* __restrict__ cl)
{
    int rr = blockIdx.x;
    int b = rr >> 10, i = rr & 1023;
    int d = threadIdx.x;              // 512
    __shared__ int lst[1024];
    __shared__ int nncnt;
    if (d < 32) {
        unsigned int m = mskw[(long)b * NS * 32 + i * 32 + d];
        int c = __popc(m);
        int pre = c;
#pragma unroll
        for (int o = 1; o < 32; o <<= 1) {
            int t2 = __shfl_up_sync(0xffffffffu, pre, o);
            if (d >= o) pre += t2;
        }
        int pos = pre - c;
        if (d == 31) nncnt = pre;
        while (m) {
            int bi = __ffs(m) - 1;
            m &= m - 1;
            lst[pos++] = d * 32 + bi;
        }
    }
    __syncthreads();
    int nn = nncnt;
    const float* srow = sim + (long)rr * 1024;
    const float* xb = x1 + (long)b * NS * 512 + d;
    float acc = 0.f, cnt = 0.f;
    int q = 0;
    for (; q + 4 <= nn; q += 4) {
        int j0 = lst[q], j1 = lst[q + 1], j2 = lst[q + 2], j3 = lst[q + 3];
        float w0 = srow[j0], w1 = srow[j1], w2 = srow[j2], w3 = srow[j3];
        float a0 = xb[(long)j0 * 512], a1 = xb[(long)j1 * 512];
        float a2 = xb[(long)j2 * 512], a3 = xb[(long)j3 * 512];
        acc += w0 * a0; cnt += w0;
        acc += w1 * a1; cnt += w1;
        acc += w2 * a2; cnt += w2;
        acc += w3 * a3; cnt += w3;
    }
    for (; q < nn; q++) {
        int j = lst[q];
        float w = srow[j];
        acc += w * xb[(long)j * 512];
        cnt += w;
    }
    float xv = x1[(long)rr * 512 + d];
    float nv = acc / fmaxf(cnt, 1.0f);
    __half hx = __float2half_rn(xv), hn = __float2half_rn(nv);
    long ob = (long)rr * 1024;
    ch[ob + d] = hx;       cl[ob + d]       = __float2half_rn(xv - __half2float(hx));
    ch[ob + 512 + d] = hn; cl[ob + 512 + d] = __float2half_rn(nv - __half2float(hn));
}

__global__ void pool1_k(const float* __restrict__ x2, float* __restrict__ part)
{
    int b = blockIdx.x, chunk = blockIdx.y;
    int d = threadIdx.x;
    const float* src = x2 + ((long)b * NS + chunk * 128) * 512;
    float s = 0.f;
#pragma unroll 8
    for (int sdx = 0; sdx < 128; sdx++)
        s += src[(long)sdx * 512 + d];
    part[((long)b * 8 + chunk) * 512 + d] = s;
}

__global__ void pool2_k(const float* __restrict__ part, float* __restrict__ pool)
{
    int b = blockIdx.x;
    int d = threadIdx.x;
    float s = 0.f;
#pragma unroll
    for (int c = 0; c < 8; c++)
        s += part[((long)b * 8 + c) * 512 + d];
    pool[b * 512 + d] = s * (1.f / 1024.f);
}

// =================================================================================
extern "C" void kernel_launch(void* const* d_in, const int* in_sizes, int n_in,
                              void* d_out, int out_size)
{
    const float* x      = (const float*)d_in[0];
    const float* enc_w  = (const float*)d_in[1];
    const float* enc_b  = (const float*)d_in[2];
    const float* in_w   = (const float*)d_in[3];
    const float* in_b   = (const float*)d_in[4];
    const float* out_w  = (const float*)d_in[5];
    const float* out_b  = (const float*)d_in[6];
    const float* ln1_g  = (const float*)d_in[7];
    const float* ln1_b  = (const float*)d_in[8];
    const float* ffn_w1 = (const float*)d_in[9];
    const float* ffn_b1 = (const float*)d_in[10];
    const float* ffn_w2 = (const float*)d_in[11];
    const float* ffn_b2 = (const float*)d_in[12];
    const float* gc_w   = (const float*)d_in[13];
    const float* gc_b   = (const float*)d_in[14];
    const float* ln2_g  = (const float*)d_in[15];
    const float* ln2_b  = (const float*)d_in[16];
    const float* dec_w  = (const float*)d_in[17];
    const float* dec_b  = (const float*)d_in[18];
    float* out = (float*)d_out;

    float *h_, *sc_, *t1_, *x1_, *x2_, *poolp_, *pool_;
    unsigned int* mskw_;
    __half *xh_, *xl_, *hh_, *hl_, *qkvh_, *qkvl_, *ah_, *al_, *vth_;
    __half *ctxh_, *ctxl_, *x1h_, *x1l_, *midh_, *midl_, *nh_, *nl_, *cbh_, *cbl_, *wh_;
    cudaGetSymbolAddress((void**)&h_,    g_h);
    cudaGetSymbolAddress((void**)&sc_,   g_sc);
    cudaGetSymbolAddress((void**)&t1_,   g_t1);
    cudaGetSymbolAddress((void**)&x1_,   g_x1);
    cudaGetSymbolAddress((void**)&x2_,   g_x2);
    cudaGetSymbolAddress((void**)&poolp_,g_poolp);
    cudaGetSymbolAddress((void**)&pool_, g_pool);
    cudaGetSymbolAddress((void**)&mskw_, g_mskw);
    cudaGetSymbolAddress((void**)&xh_,   g_xh);   cudaGetSymbolAddress((void**)&xl_,   g_xl);
    cudaGetSymbolAddress((void**)&hh_,   g_hh);   cudaGetSymbolAddress((void**)&hl_,   g_hl);
    cudaGetSymbolAddress((void**)&qkvh_, g_qkvh); cudaGetSymbolAddress((void**)&qkvl_, g_qkvl);
    cudaGetSymbolAddress((void**)&ah_,   g_ah);   cudaGetSymbolAddress((void**)&al_,   g_al);
    cudaGetSymbolAddress((void**)&vth_,  g_vth);
    cudaGetSymbolAddress((void**)&ctxh_, g_ctxh); cudaGetSymbolAddress((void**)&ctxl_, g_ctxl);
    cudaGetSymbolAddress((void**)&x1h_,  g_x1h);  cudaGetSymbolAddress((void**)&x1l_,  g_x1l);
    cudaGetSymbolAddress((void**)&midh_, g_midh); cudaGetSymbolAddress((void**)&midl_, g_midl);
    cudaGetSymbolAddress((void**)&nh_,   g_nh);   cudaGetSymbolAddress((void**)&nl_,   g_nl);
    cudaGetSymbolAddress((void**)&cbh_,  g_cbh);  cudaGetSymbolAddress((void**)&cbl_,  g_cbl);
    cudaGetSymbolAddress((void**)&wh_,   g_wh);

    cudaFuncSetAttribute(mmagemm_k<1,0,1,1>, cudaFuncAttributeMaxDynamicSharedMemorySize, MMSMEM);
    cudaFuncSetAttribute(mmagemm_k<0,0,0,1>, cudaFuncAttributeMaxDynamicSharedMemorySize, MMSMEM);
    cudaFuncSetAttribute(mmagemm_k<0,0,1,0>, cudaFuncAttributeMaxDynamicSharedMemorySize, MMSMEM);
    cudaFuncSetAttribute(mmagemm_k<1,0,1,0>, cudaFuncAttributeMaxDynamicSharedMemorySize, MMSMEM);
    cudaFuncSetAttribute(mmagemm_k<0,1,0,1>, cudaFuncAttributeMaxDynamicSharedMemorySize, MMSMEM);

    dim3 blk(256);

    // input split + fused weight conversion
    split_k<<<(ROWS*DIN/4 + 255)/256, blk>>>(x, xh_, xl_, (long)ROWS*DIN/4);
    wsplit_k<<<(720896 + 255)/256, blk>>>(enc_w, in_w, out_w, ffn_w1, ffn_w2, gc_w, wh_);

    // G1: h = relu(x @ enc_w^T + b), fp32 + split
    mmagemm_k<1,0,1,1><<<dim3(4,256,1), blk, MMSMEM>>>(xh_, xl_, wh_+WO_ENC,
        enc_b, nullptr, h_, hh_, hl_, 512, 512, 512, 512, 0,0,0,0,0,0, 1);

    // G2: qkv = h @ in_w^T + b, split only
    mmagemm_k<0,0,1,0><<<dim3(12,256,1), blk, MMSMEM>>>(hh_, hl_, wh_+WO_IN,
        in_b, nullptr, nullptr, qkvh_, qkvl_, 512, 512, 512, 1536, 0,0,0,0,0,0, 1);

    // v transpose (reads qkv hi/lo) -> vT fp16
    vtrans_k<<<dim3(8,32,64), dim3(32,8)>>>(qkvh_, qkvl_, vth_);

    // G3: scores = q @ k^T  (batched z=64)
    mmagemm_k<0,0,0,1><<<dim3(8,8,64), blk, MMSMEM>>>(qkvh_, qkvl_, qkvh_+512,
        nullptr, nullptr, sc_, nullptr, nullptr, 256, 1536, 1536, 1024,
        256, (long)NS*1536, 256, (long)NS*1536, (long)NS*NS, 2L*NS*NS, 2);

    // fused softmax + split
    softmax_split_k<<<NB*NHD*NS, 256>>>(sc_, ah_, al_);

    // G4: ctx = attn @ vT^T (batched z=64), split-out
    mmagemm_k<0,0,1,0><<<dim3(2,8,64), blk, MMSMEM>>>(ah_, al_, vth_,
        nullptr, nullptr, nullptr, ctxh_, ctxl_, 1024, 1024, 1024, 512,
        (long)NS*NS, 2L*NS*NS, (long)DHH*NS, 2L*DHH*NS, 256, (long)NS*512, 2);

    // G5: attn_out = ctx @ out_w^T + b -> t1 fp32
    mmagemm_k<0,0,0,1><<<dim3(4,256,1), blk, MMSMEM>>>(ctxh_, ctxl_, wh_+WO_OUT,
        out_b, nullptr, t1_, nullptr, nullptr, 512, 512, 512, 512, 0,0,0,0,0,0, 1);

    // x1 = LN(h + attn_out), fp32 + split
    addln_k<<<ROWS, 256>>>(h_, t1_, ln1_g, ln1_b, x1_, x1h_, x1l_);

    // G6: mid = relu(x1 @ ffn_w1^T + b1), split only
    mmagemm_k<1,0,1,0><<<dim3(8,256,1), blk, MMSMEM>>>(x1h_, x1l_, wh_+WO_F1,
        ffn_b1, nullptr, nullptr, midh_, midl_, 512, 512, 512, 1024, 0,0,0,0,0,0, 1);

    // G7: x1 = x1 + mid @ ffn_w2^T + b2 (residual), fp32
    mmagemm_k<0,1,0,1><<<dim3(4,256,1), blk, MMSMEM>>>(midh_, midl_, wh_+WO_F2,
        ffn_b2, x1_, x1_, nullptr, nullptr, 1024, 1024, 1024, 512, 0,0,0,0,0,0, 1);

    // nrm = rownorm(x1), split only
    rownorm_k<<<ROWS, 256>>>(x1_, nh_, nl_);

    // sim = nrm @ nrm^T (batched z=32)
    mmagemm_k<0,0,0,1><<<dim3(8,8,32), blk, MMSMEM>>>(nh_, nl_, nh_,
        nullptr, nullptr, sc_, nullptr, nullptr, 512, 512, 512, 1024,
        0, (long)NS*512, 0, (long)NS*512, 0, (long)NS*NS, 1);

    // adjacency: zero mask, then top-4 with fused symmetric scatter
    zero_k<<<(int)(((long)NB*NS*32*4/16 + 255)/256), blk>>>((float4*)mskw_, (long)NB*NS*32*4/16);
    topk_k<<<ROWS, 128>>>(sc_, mskw_);

    // combined = [x1 | nsum/cnt] -> fp16 hi/lo
    combine_k<<<ROWS, 512>>>(x1_, sc_, mskw_, cbh_, cbl_);

    // G8: gco = combined @ gc_w^T + b -> t1 fp32
    mmagemm_k<0,0,0,1><<<dim3(4,256,1), blk, MMSMEM>>>(cbh_, cbl_, wh_+WO_GC,
        gc_b, nullptr, t1_, nullptr, nullptr, 1024, 1024, 1024, 512, 0,0,0,0,0,0, 1);

    // x2 = LN(x1 + gco), fp32 only
    addln_k<<<ROWS, 256>>>(x1_, t1_, ln2_g, ln2_b, x2_, nullptr, nullptr);

    // pool (two-stage) + decoder
    pool1_k<<<dim3(NB,8), 512>>>(x2_, poolp_);
    pool2_k<<<NB, 512>>>(poolp_, pool_);
    gemm_k<1,0,0><<<dim3(8,1,1), blk>>>(pool_, dec_w, dec_b, nullptr, out,
        32, 512, 512, 512, 512, 512);
}

// round 12
// speedup vs baseline: 1.0609x; 1.0609x over previous
#include <cuda_runtime.h>
#include <cuda_bf16.h>
#include <cuda_fp16.h>
#include <cstdint>

// Problem constants
#define NB   32
#define NS   1024
#define DIN  512
#define DH   512
#define DOUT 512
#define NHD  2
#define DHH  256
#define ROWS (NB*NS)             // 32768
#define SCSZ (67108864L)         // NB*NHD*NS*NS

// ============================ helpers ============================
__device__ __forceinline__ uint32_t smem_to_u32(const void* p) {
    uint32_t a;
    asm("{ .reg .u64 t; cvta.to.shared.u64 t, %1; cvt.u32.u64 %0, t; }" : "=r"(a) : "l"(p));
    return a;
}
__device__ __forceinline__ void ldsm4(uint32_t* r, uint32_t addr) {
    asm volatile("ldmatrix.sync.aligned.m8n8.x4.shared.b16 {%0,%1,%2,%3}, [%4];"
                 : "=r"(r[0]), "=r"(r[1]), "=r"(r[2]), "=r"(r[3]) : "r"(addr));
}
__device__ __forceinline__ void mma16816(float* d, const uint32_t* a, const uint32_t* b) {
    asm volatile("mma.sync.aligned.m16n8k16.row.col.f32.f16.f16.f32 "
                 "{%0,%1,%2,%3}, {%4,%5,%6,%7}, {%8,%9}, {%0,%1,%2,%3};"
                 : "+f"(d[0]), "+f"(d[1]), "+f"(d[2]), "+f"(d[3])
                 : "r"(a[0]), "r"(a[1]), "r"(a[2]), "r"(a[3]), "r"(b[0]), "r"(b[1]));
}
__device__ __forceinline__ void cpa16(uint32_t s, const void* g) {
    asm volatile("cp.async.cg.shared.global [%0], [%1], 16;" :: "r"(s), "l"(g));
}
__device__ __forceinline__ void cpcommit() { asm volatile("cp.async.commit_group;"); }
template<int N> __device__ __forceinline__ void cpwait() {
    asm volatile("cp.async.wait_group %0;" :: "n"(N));
}

// smem: 3 tiles (Ah, Al, B) of 128 rows x 64B (32 fp16), XOR-swizzled, 4 stages
#define ATILEB 8192               // 128*64
#define STAGEB (3*ATILEB)         // 24576
#define NSTG   4
#define MMSMEM (NSTG*STAGEB)      // 98304
#define SWZ(row, chunk) ((uint32_t)(row)*64u + ((uint32_t)((chunk) ^ (((row)>>1)&3))*16u))

// ============================ scratch buffers ============================
__device__ float g_h   [ROWS*DH];
__device__ float g_sc  [SCSZ];
__device__ float g_t1  [ROWS*DH];
__device__ float g_x1  [ROWS*DH];
__device__ float g_x2  [ROWS*DH];
__device__ float g_poolp[NB*8*DH];
__device__ float g_pool[NB*DH];
__device__ int   g_idx [ROWS*4];
__device__ unsigned int g_mskw [(long)NB*NS*32];   // bitmask adjacency, 4MB

__device__ __half g_xh[ROWS*DIN],   g_xl[ROWS*DIN];
__device__ __half g_hh[ROWS*DH],    g_hl[ROWS*DH];
__device__ __half g_qkvh[ROWS*3*DH],g_qkvl[ROWS*3*DH];
__device__ __half g_ah[SCSZ],       g_al[SCSZ];
__device__ __half g_vth[(long)NB*NHD*DHH*NS];
__device__ __half g_ctxh[ROWS*DH],  g_ctxl[ROWS*DH];
__device__ __half g_x1h[ROWS*DH],   g_x1l[ROWS*DH];
__device__ __half g_midh[ROWS*2*DH],g_midl[ROWS*2*DH];
__device__ __half g_nh[ROWS*DH],    g_nl[ROWS*DH];
__device__ __half g_cbh[ROWS*2*DH], g_cbl[ROWS*2*DH];
__device__ __half g_wh[4*1024*1024];

// weight offsets (elements)
#define WO_ENC 0
#define WO_IN  262144
#define WO_OUT 1048576
#define WO_F1  1310720
#define WO_F2  1835008
#define WO_GC  2359296

// ============================ HMMA GEMM (fp16x2, cp.async 4-stage, 2 CTA/SM) ============
// C[M,N] = act((Ah+Al) @ B^T + bias) (+R).  A hi/lo fp16 [M,K] row-major, B fp16 [N,K].
// CTA tile 128x128, warp tile 32x64 (4x2 warps), K chunks of 32, swizzled smem.
// TRIU=1: blockIdx.x in [0,36) remapped to upper-triangle (bx,by) with by<=bx (symmetric C).
template<int ACT, int RES, int WSPLIT, int WFP32, int TRIU>
__global__ void __launch_bounds__(256, 2)
mmagemm_k(const __half* __restrict__ Ah, const __half* __restrict__ Al,
          const __half* __restrict__ Bm,
          const float* __restrict__ bias, const float* __restrict__ Rres,
          float* __restrict__ C, __half* __restrict__ Ch, __half* __restrict__ Cl,
          int K, int lda, int ldb, int ldc,
          long sA1, long sA2, long sB1, long sB2, long sC1, long sC2, int HZ)
{
    extern __shared__ char sm[];
    uint32_t sb = smem_to_u32(sm);

    int tid = threadIdx.x, wid = tid >> 5, lid = tid & 31;
    int wm = wid >> 1, wn = wid & 1;
    int z = blockIdx.z, zb = z / HZ, zh = z - zb * HZ;
    long aoff = (long)zb * sA2 + (long)zh * sA1;
    long boff = (long)zb * sB2 + (long)zh * sB1;
    long coff = (long)zb * sC2 + (long)zh * sC1;

    int bx, by;
    if (TRIU) {
        int p = blockIdx.x;
        by = 0;
        while (p >= 8 - by) { p -= 8 - by; by++; }
        bx = by + p;
    } else {
        bx = blockIdx.x; by = blockIdx.y;
    }
    int m0 = by * 128, n0 = bx * 128;

    const __half* Ahp = Ah + aoff + (long)m0 * lda;
    const __half* Alp = Al + aoff + (long)m0 * lda;
    const __half* Bp  = Bm + boff + (long)n0 * ldb;

    int lrow = tid >> 1, c0 = (tid & 1) * 2;
    const char* pAh = (const char*)(Ahp + (long)lrow * lda) + c0 * 16;
    const char* pAl = (const char*)(Alp + (long)lrow * lda) + c0 * 16;
    const char* pB  = (const char*)(Bp  + (long)lrow * ldb) + c0 * 16;
    uint32_t d0 = SWZ(lrow, c0), d1 = SWZ(lrow, c0 + 1);

#define ISSUE(stg, c) do { long ob = (long)(c) * 64; uint32_t bp = sb + (stg) * STAGEB; \
    cpa16(bp + d0,            pAh + ob); cpa16(bp + d1,            pAh + ob + 16); \
    cpa16(bp + ATILEB + d0,   pAl + ob); cpa16(bp + ATILEB + d1,   pAl + ob + 16); \
    cpa16(bp + 2*ATILEB + d0, pB  + ob); cpa16(bp + 2*ATILEB + d1, pB  + ob + 16); } while (0)

    int arow = wm * 32 + ((lid >> 3) & 1) * 8 + (lid & 7);
    int acsel = (lid >> 4) & 1;
    uint32_t axor = (uint32_t)((arow >> 1) & 3);
    int brow = wn * 64 + ((lid >> 4) & 1) * 8 + (lid & 7);
    int bcsel = (lid >> 3) & 1;
    uint32_t bxor = (uint32_t)((brow >> 1) & 3);

    float d[2][8][4];
#pragma unroll
    for (int i = 0; i < 2; i++)
#pragma unroll
        for (int j = 0; j < 8; j++)
#pragma unroll
            for (int q = 0; q < 4; q++) d[i][j][q] = 0.f;

    const int nCh = K >> 5;
    ISSUE(0, 0); cpcommit();
    ISSUE(1, 1); cpcommit();
    ISSUE(2, 2); cpcommit();

    int stg = 0;
    for (int c = 0; c < nCh; c++) {
        cpwait<2>();
        __syncthreads();
        if (c + 3 < nCh) {
            int ns = stg + 3; if (ns >= NSTG) ns -= NSTG;
            ISSUE(ns, c + 3);
        }
        cpcommit();

        uint32_t cb = sb + stg * STAGEB;
#pragma unroll
        for (int ks = 0; ks < 2; ks++) {
            uint32_t fah[2][4], fal[2][4], fb[4][4];
#pragma unroll
            for (int mf = 0; mf < 2; mf++) {
                uint32_t ad = cb + (uint32_t)(arow + mf * 16) * 64u
                            + (((uint32_t)(ks * 2 + acsel) ^ axor) * 16u);
                ldsm4(fah[mf], ad);
                ldsm4(fal[mf], ad + ATILEB);
            }
#pragma unroll
            for (int np = 0; np < 4; np++) {
                uint32_t bd = cb + 2 * ATILEB + (uint32_t)(brow + np * 16) * 64u
                            + (((uint32_t)(ks * 2 + bcsel) ^ bxor) * 16u);
                ldsm4(fb[np], bd);
            }
#pragma unroll
            for (int mf = 0; mf < 2; mf++)
#pragma unroll
                for (int nf = 0; nf < 8; nf++)
                    mma16816(d[mf][nf], fah[mf], &fb[nf >> 1][(nf & 1) * 2]);
#pragma unroll
            for (int mf = 0; mf < 2; mf++)
#pragma unroll
                for (int nf = 0; nf < 8; nf++)
                    mma16816(d[mf][nf], fal[mf], &fb[nf >> 1][(nf & 1) * 2]);
        }
        if (++stg >= NSTG) stg = 0;
    }
#undef ISSUE

    int g = lid >> 2, tg = lid & 3;
#pragma unroll
    for (int mf = 0; mf < 2; mf++) {
#pragma unroll
        for (int cp = 0; cp < 2; cp++) {
            int m = m0 + wm * 32 + mf * 16 + cp * 8 + g;
            long rb = (long)m * ldc + coff;
#pragma unroll
            for (int nf = 0; nf < 8; nf++) {
                int n = n0 + wn * 64 + nf * 8 + tg * 2;
                float v0 = d[mf][nf][cp * 2];
                float v1 = d[mf][nf][cp * 2 + 1];
                if (bias) { v0 += bias[n]; v1 += bias[n + 1]; }
                if (ACT) { v0 = fmaxf(v0, 0.f); v1 = fmaxf(v1, 0.f); }
                if (RES) { v0 += Rres[rb + n]; v1 += Rres[rb + n + 1]; }
                if (WFP32)
                    *reinterpret_cast<float2*>(C + rb + n) = make_float2(v0, v1);
                if (WSPLIT) {
                    __half h0 = __float2half_rn(v0);
                    __half h1 = __float2half_rn(v1);
                    __half2 hh; hh.x = h0; hh.y = h1;
                    *reinterpret_cast<__half2*>(Ch + rb + n) = hh;
                    __half2 ll;
                    ll.x = __float2half_rn(v0 - __half2float(h0));
                    ll.y = __float2half_rn(v1 - __half2float(h1));
                    *reinterpret_cast<__half2*>(Cl + rb + n) = ll;
                }
            }
        }
    }
}

// mirror upper-triangle 128-blocks of symmetric sim into lower triangle (32x32 transpose tiles)
__global__ void mirror_k(float* __restrict__ sc)
{
    int b = blockIdx.y;
    int p = blockIdx.x;               // [0, 28*16)
    int pair = p >> 4, t = p & 15;
    int BI = 1, acc = 0;
    while (pair >= acc + BI) { acc += BI; BI++; }
    int BJ = pair - acc;              // BI in 1..7, BJ < BI
    int tr = t >> 2, tc = t & 3;
    int r0 = BI * 128 + tr * 32;      // dest rows (lower)
    int c0 = BJ * 128 + tc * 32;      // dest cols
    long base = (long)b * NS * NS;
    __shared__ float tile[32][33];
    int tx = threadIdx.x, ty = threadIdx.y;   // (32, 8)
#pragma unroll
    for (int i = 0; i < 4; i++)
        tile[ty + i * 8][tx] = sc[base + (long)(c0 + ty + i * 8) * NS + r0 + tx];
    __syncthreads();
#pragma unroll
    for (int i = 0; i < 4; i++)
        sc[base + (long)(r0 + ty + i * 8) * NS + c0 + tx] = tile[tx][ty + i * 8];
}

// ============================ SIMT GEMM (small final only) ============================
template<int TB, int ACT, int RES>
__global__ void gemm_k(const float* __restrict__ A, const float* __restrict__ Bm,
                       const float* __restrict__ bias, const float* __restrict__ R,
                       float* __restrict__ C,
                       int M, int N, int K, int lda, int ldb, int ldc)
{
    __shared__ float As[16][65];
    __shared__ float Bs[16][65];
    int tid = threadIdx.x;
    int tx = tid & 15, ty = tid >> 4;
    int m0 = blockIdx.y * 64, n0 = blockIdx.x * 64;
    float acc[4][4];
#pragma unroll
    for (int i = 0; i < 4; i++)
#pragma unroll
        for (int j = 0; j < 4; j++) acc[i][j] = 0.f;

    for (int k0 = 0; k0 < K; k0 += 16) {
#pragma unroll
        for (int i = 0; i < 4; i++) {
            int idx = tid + i * 256;
            int r = idx >> 4, kk = idx & 15;
            int m = m0 + r;
            As[kk][r] = (m < M) ? A[(long)m * lda + (k0 + kk)] : 0.f;
        }
#pragma unroll
        for (int i = 0; i < 4; i++) {
            int idx = tid + i * 256;
            int r = idx >> 4, kk = idx & 15;
            Bs[kk][r] = Bm[(long)(n0 + r) * ldb + (k0 + kk)];
        }
        __syncthreads();
#pragma unroll
        for (int kk = 0; kk < 16; kk++) {
            float a[4], b[4];
#pragma unroll
            for (int i = 0; i < 4; i++) a[i] = As[kk][ty + 16 * i];
#pragma unroll
            for (int j = 0; j < 4; j++) b[j] = Bs[kk][tx + 16 * j];
#pragma unroll
            for (int i = 0; i < 4; i++)
#pragma unroll
                for (int j = 0; j < 4; j++) acc[i][j] += a[i] * b[j];
        }
        __syncthreads();
    }
#pragma unroll
    for (int i = 0; i < 4; i++) {
        int m = m0 + ty + 16 * i;
        if (m >= M) continue;
#pragma unroll
        for (int j = 0; j < 4; j++) {
            int n = n0 + tx + 16 * j;
            float v = acc[i][j];
            if (bias) v += bias[n];
            if (ACT) v = fmaxf(v, 0.f);
            C[(long)m * ldc + n] = v;
        }
    }
}

// ============================ elementwise / reduction kernels ============================
__device__ __forceinline__ void split4_store(float4 v, __half* h, __half* l, long i)
{
    __half2 h0, h1, l0, l1;
    h0.x = __float2half_rn(v.x); h0.y = __float2half_rn(v.y);
    h1.x = __float2half_rn(v.z); h1.y = __float2half_rn(v.w);
    l0.x = __float2half_rn(v.x - __half2float(h0.x));
    l0.y = __float2half_rn(v.y - __half2float(h0.y));
    l1.x = __float2half_rn(v.z - __half2float(h1.x));
    l1.y = __float2half_rn(v.w - __half2float(h1.y));
    reinterpret_cast<__half2*>(h)[2 * i] = h0;
    reinterpret_cast<__half2*>(h)[2 * i + 1] = h1;
    reinterpret_cast<__half2*>(l)[2 * i] = l0;
    reinterpret_cast<__half2*>(l)[2 * i + 1] = l1;
}

__global__ void split_k(const float* __restrict__ s, __half* __restrict__ h,
                        __half* __restrict__ l, long n4)
{
    long i = (long)blockIdx.x * blockDim.x + threadIdx.x;
    if (i >= n4) return;
    split4_store(reinterpret_cast<const float4*>(s)[i], h, l, i);
}

__global__ void wsplit_k(const float* __restrict__ w0, const float* __restrict__ w1,
                         const float* __restrict__ w2, const float* __restrict__ w3,
                         const float* __restrict__ w4, const float* __restrict__ w5,
                         __half* __restrict__ h)
{
    long i = (long)blockIdx.x * blockDim.x + threadIdx.x;
    const float* src; long base;
    if      (i < 65536)  { src = w0; base = 0;      }
    else if (i < 262144) { src = w1; base = 65536;  }
    else if (i < 327680) { src = w2; base = 262144; }
    else if (i < 458752) { src = w3; base = 327680; }
    else if (i < 589824) { src = w4; base = 458752; }
    else if (i < 720896) { src = w5; base = 589824; }
    else return;
    float4 v = reinterpret_cast<const float4*>(src)[i - base];
    __half2 h0, h1;
    h0.x = __float2half_rn(v.x); h0.y = __float2half_rn(v.y);
    h1.x = __float2half_rn(v.z); h1.y = __float2half_rn(v.w);
    reinterpret_cast<__half2*>(h)[2 * i] = h0;
    reinterpret_cast<__half2*>(h)[2 * i + 1] = h1;
}

__global__ void vtrans_k(const __half* __restrict__ qh, const __half* __restrict__ ql,
                         __half* __restrict__ vth)
{
    int z = blockIdx.z, zb = z >> 1, zh = z & 1;
    int d0 = blockIdx.x * 32, k0 = blockIdx.y * 32;
    __shared__ float t[32][33];
    int tx = threadIdx.x, ty = threadIdx.y;
    long base = (long)zb * NS * 1536 + 1024 + zh * 256;
#pragma unroll
    for (int i = 0; i < 4; i++) {
        int k = k0 + ty + i * 8;
        long idx = base + (long)k * 1536 + d0 + tx;
        t[ty + i * 8][tx] = __half2float(qh[idx]) + __half2float(ql[idx]);
    }
    __syncthreads();
    __half* oh = vth + (long)z * DHH * NS;
#pragma unroll
    for (int i = 0; i < 4; i++) {
        int d = d0 + ty + i * 8;
        oh[(long)d * NS + k0 + tx] = __float2half_rn(t[tx][ty + i * 8]);
    }
}

__global__ void softmax_split_k(const float* __restrict__ s,
                                __half* __restrict__ ah, __half* __restrict__ al)
{
    long row = blockIdx.x;
    const float* p = s + row * 1024;
    int t = threadIdx.x;              // 256
    float4 v4 = reinterpret_cast<const float4*>(p)[t];
    float v[4] = { v4.x * 0.0625f, v4.y * 0.0625f, v4.z * 0.0625f, v4.w * 0.0625f };
    float mx = fmaxf(fmaxf(v[0], v[1]), fmaxf(v[2], v[3]));
    __shared__ float red[256];
    red[t] = mx; __syncthreads();
    for (int o = 128; o > 0; o >>= 1) { if (t < o) red[t] = fmaxf(red[t], red[t + o]); __syncthreads(); }
    mx = red[0]; __syncthreads();
    float sum = 0.f;
#pragma unroll
    for (int i = 0; i < 4; i++) { v[i] = __expf(v[i] - mx); sum += v[i]; }
    red[t] = sum; __syncthreads();
    for (int o = 128; o > 0; o >>= 1) { if (t < o) red[t] += red[t + o]; __syncthreads(); }
    float inv = 1.f / red[0];
    __half2 hh[2], ll[2];
#pragma unroll
    for (int i = 0; i < 4; i++) {
        float val = v[i] * inv;
        __half h = __float2half_rn(val);
        ((__half*)hh)[i] = h;
        ((__half*)ll)[i] = __float2half_rn(val - __half2float(h));
    }
    long ob = row * 1024 + t * 4;
    *reinterpret_cast<__half2*>(ah + ob)     = hh[0];
    *reinterpret_cast<__half2*>(ah + ob + 2) = hh[1];
    *reinterpret_cast<__half2*>(al + ob)     = ll[0];
    *reinterpret_cast<__half2*>(al + ob + 2) = ll[1];
}

__global__ void addln_k(const float* __restrict__ a, const float* __restrict__ r,
                        const float* __restrict__ g, const float* __restrict__ be,
                        float* __restrict__ o, __half* __restrict__ oh,
                        __half* __restrict__ ol)
{
    long row = blockIdx.x;
    int t = threadIdx.x;
    long base = row * 512;
    float v0 = a[base + t]       + r[base + t];
    float v1 = a[base + t + 256] + r[base + t + 256];
    __shared__ float rs[256], rq[256];
    rs[t] = v0 + v1; rq[t] = v0 * v0 + v1 * v1;
    __syncthreads();
    for (int off = 128; off > 0; off >>= 1) {
        if (t < off) { rs[t] += rs[t + off]; rq[t] += rq[t + off]; }
        __syncthreads();
    }
    float mu  = rs[0] * (1.f / 512.f);
    float var = rq[0] * (1.f / 512.f) - mu * mu;
    float inv = rsqrtf(var + 1e-5f);
    float o0 = (v0 - mu) * inv * g[t]       + be[t];
    float o1 = (v1 - mu) * inv * g[t + 256] + be[t + 256];
    o[base + t] = o0; o[base + t + 256] = o1;
    if (oh) {
        __half h0 = __float2half_rn(o0), h1 = __float2half_rn(o1);
        oh[base + t] = h0; oh[base + t + 256] = h1;
        ol[base + t]       = __float2half_rn(o0 - __half2float(h0));
        ol[base + t + 256] = __float2half_rn(o1 - __half2float(h1));
    }
}

__global__ void rownorm_k(const float* __restrict__ x, __half* __restrict__ nh,
                          __half* __restrict__ nl)
{
    long row = blockIdx.x;
    int t = threadIdx.x;
    long base = row * 512;
    float v0 = x[base + t], v1 = x[base + t + 256];
    __shared__ float rq[256];
    rq[t] = v0 * v0 + v1 * v1;
    __syncthreads();
    for (int off = 128; off > 0; off >>= 1) {
        if (t < off) rq[t] += rq[t + off];
        __syncthreads();
    }
    float s = 1.f / fmaxf(sqrtf(rq[0]), 1e-12f);
    float o0 = v0 * s, o1 = v1 * s;
    __half h0 = __float2half_rn(o0), h1 = __float2half_rn(o1);
    nh[base + t] = h0; nh[base + t + 256] = h1;
    nl[base + t]       = __float2half_rn(o0 - __half2float(h0));
    nl[base + t + 256] = __float2half_rn(o1 - __half2float(h1));
}

// single-pass exact top-4 per row (comparator: value desc, index asc — jax tie rule)
__global__ void topk_k(const float* __restrict__ sim, int* __restrict__ idxo)
{
    int row = blockIdx.x;
    const float* p = sim + (long)row * 1024;
    int t = threadIdx.x;              // 128
    float v[4] = {-1e30f, -1e30f, -1e30f, -1e30f};
    int   ix[4] = {1 << 30, 1 << 30, 1 << 30, 1 << 30};
#pragma unroll
    for (int r = 0; r < 8; r++) {
        int j = t + r * 128;
        float val = p[j];
        if (val > v[3] || (val == v[3] && j < ix[3])) {
            v[3] = val; ix[3] = j;
#pragma unroll
            for (int q = 3; q > 0; q--) {
                bool up = v[q] > v[q-1] || (v[q] == v[q-1] && ix[q] < ix[q-1]);
                if (up) {
                    float tv = v[q]; v[q] = v[q-1]; v[q-1] = tv;
                    int ti = ix[q]; ix[q] = ix[q-1]; ix[q-1] = ti;
                }
            }
        }
    }
    __shared__ float sv[128][4];
    __shared__ int   si[128][4];
#pragma unroll
    for (int q = 0; q < 4; q++) { sv[t][q] = v[q]; si[t][q] = ix[q]; }
    __syncthreads();
    for (int off = 64; off > 0; off >>= 1) {
        if (t < off) {
            float mv[4]; int mi[4];
            int a = 0, b = 0;
#pragma unroll
            for (int q = 0; q < 4; q++) {
                float av = sv[t][a], bv = sv[t + off][b];
                int   ai = si[t][a], bi = si[t + off][b];
                bool ta = av > bv || (av == bv && ai < bi);
                if (ta) { mv[q] = av; mi[q] = ai; a++; }
                else    { mv[q] = bv; mi[q] = bi; b++; }
            }
#pragma unroll
            for (int q = 0; q < 4; q++) { sv[t][q] = mv[q]; si[t][q] = mi[q]; }
        }
        __syncthreads();
    }
    if (t < 4) idxo[row * 4 + t] = si[0][t];
}

__global__ void zero_k(float4* __restrict__ p, long n)
{
    long i = (long)blockIdx.x * blockDim.x + threadIdx.x;
    if (i < n) p[i] = make_float4(0.f, 0.f, 0.f, 0.f);
}

__global__ void scatter_k(const int* __restrict__ idx, unsigned int* __restrict__ mskw)
{
    int rr = blockIdx.x * blockDim.x + threadIdx.x;
    if (rr >= ROWS) return;
    int b = rr >> 10, i = rr & 1023;
    unsigned int* mb = mskw + (long)b * NS * 32;
#pragma unroll
    for (int t = 0; t < 4; t++) {
        int j = idx[rr * 4 + t];
        if (j != i) {
            atomicOr(&mb[i * 32 + (j >> 5)], 1u << (j & 31));
            atomicOr(&mb[j * 32 + (i >> 5)], 1u << (i & 31));
        }
    }
}

__global__ void combine_k(const float* __restrict__ x1, const float* __restrict__ sim,
                          const unsigned int* __restrict__ mskw,
                          __half* __restrict__ ch, __half* __restrict__ cl)
{
    int rr = blockIdx.x;
    int b = rr >> 10, i = rr & 1023;
    int d = threadIdx.x;              // 512
    __shared__ unsigned int smk[32];
    if (d < 32) smk[d] = mskw[(long)b * NS * 32 + i * 32 + d];
    __syncthreads();
    const float* srow = sim + (long)rr * 1024;
    float acc = 0.f, cnt = 0.f;
#pragma unroll 4
    for (int w = 0; w < 32; w++) {
        unsigned int m = smk[w];
        while (m) {
            int bi = __ffs(m) - 1;
            m &= m - 1;
            int j = w * 32 + bi;
            float wgt = srow[j];
            acc += wgt * x1[((long)(b * NS + j)) * 512 + d];
            cnt += wgt;
        }
    }
    float xv = x1[(long)rr * 512 + d];
    float nv = acc / fmaxf(cnt, 1.0f);
    __half hx = __float2half_rn(xv), hn = __float2half_rn(nv);
    long ob = (long)rr * 1024;
    ch[ob + d] = hx;       cl[ob + d]       = __float2half_rn(xv - __half2float(hx));
    ch[ob + 512 + d] = hn; cl[ob + 512 + d] = __float2half_rn(nv - __half2float(hn));
}

__global__ void pool1_k(const float* __restrict__ x2, float* __restrict__ part)
{
    int b = blockIdx.x, chunk = blockIdx.y;
    int d = threadIdx.x;
    const float* src = x2 + ((long)b * NS + chunk * 128) * 512;
    float s = 0.f;
#pragma unroll 8
    for (int sdx = 0; sdx < 128; sdx++)
        s += src[(long)sdx * 512 + d];
    part[((long)b * 8 + chunk) * 512 + d] = s;
}

__global__ void pool2_k(const float* __restrict__ part, float* __restrict__ pool)
{
    int b = blockIdx.x;
    int d = threadIdx.x;
    float s = 0.f;
#pragma unroll
    for (int c = 0; c < 8; c++)
        s += part[((long)b * 8 + c) * 512 + d];
    pool[b * 512 + d] = s * (1.f / 1024.f);
}

// =================================================================================
extern "C" void kernel_launch(void* const* d_in, const int* in_sizes, int n_in,
                              void* d_out, int out_size)
{
    const float* x      = (const float*)d_in[0];
    const float* enc_w  = (const float*)d_in[1];
    const float* enc_b  = (const float*)d_in[2];
    const float* in_w   = (const float*)d_in[3];
    const float* in_b   = (const float*)d_in[4];
    const float* out_w  = (const float*)d_in[5];
    const float* out_b  = (const float*)d_in[6];
    const float* ln1_g  = (const float*)d_in[7];
    const float* ln1_b  = (const float*)d_in[8];
    const float* ffn_w1 = (const float*)d_in[9];
    const float* ffn_b1 = (const float*)d_in[10];
    const float* ffn_w2 = (const float*)d_in[11];
    const float* ffn_b2 = (const float*)d_in[12];
    const float* gc_w   = (const float*)d_in[13];
    const float* gc_b   = (const float*)d_in[14];
    const float* ln2_g  = (const float*)d_in[15];
    const float* ln2_b  = (const float*)d_in[16];
    const float* dec_w  = (const float*)d_in[17];
    const float* dec_b  = (const float*)d_in[18];
    float* out = (float*)d_out;

    float *h_, *sc_, *t1_, *x1_, *x2_, *poolp_, *pool_;
    int* idx_;
    unsigned int* mskw_;
    __half *xh_, *xl_, *hh_, *hl_, *qkvh_, *qkvl_, *ah_, *al_, *vth_;
    __half *ctxh_, *ctxl_, *x1h_, *x1l_, *midh_, *midl_, *nh_, *nl_, *cbh_, *cbl_, *wh_;
    cudaGetSymbolAddress((void**)&h_,    g_h);
    cudaGetSymbolAddress((void**)&sc_,   g_sc);
    cudaGetSymbolAddress((void**)&t1_,   g_t1);
    cudaGetSymbolAddress((void**)&x1_,   g_x1);
    cudaGetSymbolAddress((void**)&x2_,   g_x2);
    cudaGetSymbolAddress((void**)&poolp_,g_poolp);
    cudaGetSymbolAddress((void**)&pool_, g_pool);
    cudaGetSymbolAddress((void**)&idx_,  g_idx);
    cudaGetSymbolAddress((void**)&mskw_, g_mskw);
    cudaGetSymbolAddress((void**)&xh_,   g_xh);   cudaGetSymbolAddress((void**)&xl_,   g_xl);
    cudaGetSymbolAddress((void**)&hh_,   g_hh);   cudaGetSymbolAddress((void**)&hl_,   g_hl);
    cudaGetSymbolAddress((void**)&qkvh_, g_qkvh); cudaGetSymbolAddress((void**)&qkvl_, g_qkvl);
    cudaGetSymbolAddress((void**)&ah_,   g_ah);   cudaGetSymbolAddress((void**)&al_,   g_al);
    cudaGetSymbolAddress((void**)&vth_,  g_vth);
    cudaGetSymbolAddress((void**)&ctxh_, g_ctxh); cudaGetSymbolAddress((void**)&ctxl_, g_ctxl);
    cudaGetSymbolAddress((void**)&x1h_,  g_x1h);  cudaGetSymbolAddress((void**)&x1l_,  g_x1l);
    cudaGetSymbolAddress((void**)&midh_, g_midh); cudaGetSymbolAddress((void**)&midl_, g_midl);
    cudaGetSymbolAddress((void**)&nh_,   g_nh);   cudaGetSymbolAddress((void**)&nl_,   g_nl);
    cudaGetSymbolAddress((void**)&cbh_,  g_cbh);  cudaGetSymbolAddress((void**)&cbl_,  g_cbl);
    cudaGetSymbolAddress((void**)&wh_,   g_wh);

    cudaFuncSetAttribute(mmagemm_k<1,0,1,1,0>, cudaFuncAttributeMaxDynamicSharedMemorySize, MMSMEM);
    cudaFuncSetAttribute(mmagemm_k<0,0,0,1,0>, cudaFuncAttributeMaxDynamicSharedMemorySize, MMSMEM);
    cudaFuncSetAttribute(mmagemm_k<0,0,0,1,1>, cudaFuncAttributeMaxDynamicSharedMemorySize, MMSMEM);
    cudaFuncSetAttribute(mmagemm_k<0,0,1,0,0>, cudaFuncAttributeMaxDynamicSharedMemorySize, MMSMEM);
    cudaFuncSetAttribute(mmagemm_k<1,0,1,0,0>, cudaFuncAttributeMaxDynamicSharedMemorySize, MMSMEM);
    cudaFuncSetAttribute(mmagemm_k<0,1,0,1,0>, cudaFuncAttributeMaxDynamicSharedMemorySize, MMSMEM);

    dim3 blk(256);

    // input split + fused weight conversion
    split_k<<<(ROWS*DIN/4 + 255)/256, blk>>>(x, xh_, xl_, (long)ROWS*DIN/4);
    wsplit_k<<<(720896 + 255)/256, blk>>>(enc_w, in_w, out_w, ffn_w1, ffn_w2, gc_w, wh_);

    // G1: h = relu(x @ enc_w^T + b), fp32 + split
    mmagemm_k<1,0,1,1,0><<<dim3(4,256,1), blk, MMSMEM>>>(xh_, xl_, wh_+WO_ENC,
        enc_b, nullptr, h_, hh_, hl_, 512, 512, 512, 512, 0,0,0,0,0,0, 1);

    // G2: qkv = h @ in_w^T + b, split only (v reconstructed in vtrans)
    mmagemm_k<0,0,1,0,0><<<dim3(12,256,1), blk, MMSMEM>>>(hh_, hl_, wh_+WO_IN,
        in_b, nullptr, nullptr, qkvh_, qkvl_, 512, 512, 512, 1536, 0,0,0,0,0,0, 1);

    // v transpose (reads qkv hi/lo) -> vT fp16
    vtrans_k<<<dim3(8,32,64), dim3(32,8)>>>(qkvh_, qkvl_, vth_);

    // G3: scores = q @ k^T  (batched z=64)
    mmagemm_k<0,0,0,1,0><<<dim3(8,8,64), blk, MMSMEM>>>(qkvh_, qkvl_, qkvh_+512,
        nullptr, nullptr, sc_, nullptr, nullptr, 256, 1536, 1536, 1024,
        256, (long)NS*1536, 256, (long)NS*1536, (long)NS*NS, 2L*NS*NS, 2);

    // fused softmax + split
    softmax_split_k<<<NB*NHD*NS, 256>>>(sc_, ah_, al_);

    // G4: ctx = attn @ vT^T (batched z=64), split-out
    mmagemm_k<0,0,1,0,0><<<dim3(2,8,64), blk, MMSMEM>>>(ah_, al_, vth_,
        nullptr, nullptr, nullptr, ctxh_, ctxl_, 1024, 1024, 1024, 512,
        (long)NS*NS, 2L*NS*NS, (long)DHH*NS, 2L*DHH*NS, 256, (long)NS*512, 2);

    // G5: attn_out = ctx @ out_w^T + b -> t1 fp32
    mmagemm_k<0,0,0,1,0><<<dim3(4,256,1), blk, MMSMEM>>>(ctxh_, ctxl_, wh_+WO_OUT,
        out_b, nullptr, t1_, nullptr, nullptr, 512, 512, 512, 512, 0,0,0,0,0,0, 1);

    // x1 = LN(h + attn_out), fp32 + split
    addln_k<<<ROWS, 256>>>(h_, t1_, ln1_g, ln1_b, x1_, x1h_, x1l_);

    // G6: mid = relu(x1 @ ffn_w1^T + b1), split only
    mmagemm_k<1,0,1,0,0><<<dim3(8,256,1), blk, MMSMEM>>>(x1h_, x1l_, wh_+WO_F1,
        ffn_b1, nullptr, nullptr, midh_, midl_, 512, 512, 512, 1024, 0,0,0,0,0,0, 1);

    // G7: x1 = x1 + mid @ ffn_w2^T + b2 (residual), fp32
    mmagemm_k<0,1,0,1,0><<<dim3(4,256,1), blk, MMSMEM>>>(midh_, midl_, wh_+WO_F2,
        ffn_b2, x1_, x1_, nullptr, nullptr, 1024, 1024, 1024, 512, 0,0,0,0,0,0, 1);

    // nrm = rownorm(x1), split only
    rownorm_k<<<ROWS, 256>>>(x1_, nh_, nl_);

    // sim = nrm @ nrm^T (batched z=32) — upper-triangle blocks only (symmetric)
    mmagemm_k<0,0,0,1,1><<<dim3(36,1,32), blk, MMSMEM>>>(nh_, nl_, nh_,
        nullptr, nullptr, sc_, nullptr, nullptr, 512, 512, 512, 1024,
        0, (long)NS*512, 0, (long)NS*512, 0, (long)NS*NS, 1);

    // mirror upper -> lower triangle
    mirror_k<<<dim3(28*16, NB), dim3(32,8)>>>(sc_);

    // adjacency (1-bit mask)
    zero_k<<<(int)(((long)NB*NS*32*4/16 + 255)/256), blk>>>((float4*)mskw_, (long)NB*NS*32*4/16);
    topk_k<<<ROWS, 128>>>(sc_, idx_);
    scatter_k<<<(ROWS+255)/256, blk>>>(idx_, mskw_);

    // combined = [x1 | nsum/cnt] -> fp16 hi/lo
    combine_k<<<ROWS, 512>>>(x1_, sc_, mskw_, cbh_, cbl_);

    // G8: gco = combined @ gc_w^T + b -> t1 fp32
    mmagemm_k<0,0,0,1,0><<<dim3(4,256,1), blk, MMSMEM>>>(cbh_, cbl_, wh_+WO_GC,
        gc_b, nullptr, t1_, nullptr, nullptr, 1024, 1024, 1024, 512, 0,0,0,0,0,0, 1);

    // x2 = LN(x1 + gco), fp32 only
    addln_k<<<ROWS, 256>>>(x1_, t1_, ln2_g, ln2_b, x2_, nullptr, nullptr);

    // pool (two-stage) + decoder
    pool1_k<<<dim3(NB,8), 512>>>(x2_, poolp_);
    pool2_k<<<NB, 512>>>(poolp_, pool_);
    gemm_k<1,0,0><<<dim3(8,1,1), blk>>>(pool_, dec_w, dec_b, nullptr, out,
        32, 512, 512, 512, 512, 512);
}

// round 13
// speedup vs baseline: 1.0984x; 1.0353x over previous
#include <cuda_runtime.h>
#include <cuda_bf16.h>
#include <cuda_fp16.h>
#include <cstdint>

// Problem constants
#define NB   32
#define NS   1024
#define DIN  512
#define DH   512
#define DOUT 512
#define NHD  2
#define DHH  256
#define ROWS (NB*NS)             // 32768
#define SCSZ (67108864L)         // NB*NHD*NS*NS

// ============================ helpers ============================
__device__ __forceinline__ uint32_t smem_to_u32(const void* p) {
    uint32_t a;
    asm("{ .reg .u64 t; cvta.to.shared.u64 t, %1; cvt.u32.u64 %0, t; }" : "=r"(a) : "l"(p));
    return a;
}
__device__ __forceinline__ void ldsm4(uint32_t* r, uint32_t addr) {
    asm volatile("ldmatrix.sync.aligned.m8n8.x4.shared.b16 {%0,%1,%2,%3}, [%4];"
                 : "=r"(r[0]), "=r"(r[1]), "=r"(r[2]), "=r"(r[3]) : "r"(addr));
}
__device__ __forceinline__ void mma16816(float* d, const uint32_t* a, const uint32_t* b) {
    asm volatile("mma.sync.aligned.m16n8k16.row.col.f32.f16.f16.f32 "
                 "{%0,%1,%2,%3}, {%4,%5,%6,%7}, {%8,%9}, {%0,%1,%2,%3};"
                 : "+f"(d[0]), "+f"(d[1]), "+f"(d[2]), "+f"(d[3])
                 : "r"(a[0]), "r"(a[1]), "r"(a[2]), "r"(a[3]), "r"(b[0]), "r"(b[1]));
}
__device__ __forceinline__ void cpa16(uint32_t s, const void* g) {
    asm volatile("cp.async.cg.shared.global [%0], [%1], 16;" :: "r"(s), "l"(g));
}
__device__ __forceinline__ void cpcommit() { asm volatile("cp.async.commit_group;"); }
template<int N> __device__ __forceinline__ void cpwait() {
    asm volatile("cp.async.wait_group %0;" :: "n"(N));
}

// smem: 3 tiles (Ah, Al, B) of 128 rows x 64B (32 fp16), XOR-swizzled, 4 stages
#define ATILEB 8192               // 128*64
#define STAGEB (3*ATILEB)         // 24576
#define NSTG   4
#define MMSMEM (NSTG*STAGEB)      // 98304
#define SWZ(row, chunk) ((uint32_t)(row)*64u + ((uint32_t)((chunk) ^ (((row)>>1)&3))*16u))

// ============================ scratch buffers ============================
__device__ float g_h   [ROWS*DH];
__device__ float g_sc  [SCSZ];
__device__ float g_t1  [ROWS*DH];
__device__ float g_x1  [ROWS*DH];
__device__ float g_x2  [ROWS*DH];
__device__ float g_poolp[NB*8*DH];
__device__ float g_pool[NB*DH];
__device__ int   g_idx [ROWS*4];
__device__ unsigned int g_mskw [(long)NB*NS*32];   // bitmask adjacency, 4MB

__device__ __half g_xh[ROWS*DIN],   g_xl[ROWS*DIN];
__device__ __half g_hh[ROWS*DH],    g_hl[ROWS*DH];
__device__ __half g_qkvh[ROWS*3*DH],g_qkvl[ROWS*3*DH];
__device__ __half g_ah[SCSZ];
__device__ __half g_vth[(long)NB*NHD*DHH*NS];
__device__ __half g_ctxh[ROWS*DH],  g_ctxl[ROWS*DH];
__device__ __half g_x1h[ROWS*DH],   g_x1l[ROWS*DH];
__device__ __half g_midh[ROWS*2*DH],g_midl[ROWS*2*DH];
__device__ __half g_nh[ROWS*DH],    g_nl[ROWS*DH];
__device__ __half g_cbh[ROWS*2*DH], g_cbl[ROWS*2*DH];
__device__ __half g_wh[4*1024*1024];

// weight offsets (elements)
#define WO_ENC 0
#define WO_IN  262144
#define WO_OUT 1048576
#define WO_F1  1310720
#define WO_F2  1835008
#define WO_GC  2359296

// ============================ HMMA GEMM (fp16x2, cp.async 4-stage, 2 CTA/SM) ============
// C[M,N] = act((Ah[+Al]) @ B^T + bias) (+R).  A hi/lo fp16 [M,K] row-major, B fp16 [N,K].
// CTA tile 128x128, warp tile 32x64 (4x2 warps), K chunks of 32, swizzled smem.
// TRIU=1: blockIdx.x in [0,36) remapped to upper-triangle (bx,by), by<=bx (symmetric C).
// ALO=0: skip the A-lo stream entirely (half the MMAs; Al pointer unused).
template<int ACT, int RES, int WSPLIT, int WFP32, int TRIU, int ALO>
__global__ void __launch_bounds__(256, 2)
mmagemm_k(const __half* __restrict__ Ah, const __half* __restrict__ Al,
          const __half* __restrict__ Bm,
          const float* __restrict__ bias, const float* __restrict__ Rres,
          float* __restrict__ C, __half* __restrict__ Ch, __half* __restrict__ Cl,
          int K, int lda, int ldb, int ldc,
          long sA1, long sA2, long sB1, long sB2, long sC1, long sC2, int HZ)
{
    extern __shared__ char sm[];
    uint32_t sb = smem_to_u32(sm);

    int tid = threadIdx.x, wid = tid >> 5, lid = tid & 31;
    int wm = wid >> 1, wn = wid & 1;
    int z = blockIdx.z, zb = z / HZ, zh = z - zb * HZ;
    long aoff = (long)zb * sA2 + (long)zh * sA1;
    long boff = (long)zb * sB2 + (long)zh * sB1;
    long coff = (long)zb * sC2 + (long)zh * sC1;

    int bx, by;
    if (TRIU) {
        int p = blockIdx.x;
        by = 0;
        while (p >= 8 - by) { p -= 8 - by; by++; }
        bx = by + p;
    } else {
        bx = blockIdx.x; by = blockIdx.y;
    }
    int m0 = by * 128, n0 = bx * 128;

    const __half* Ahp = Ah + aoff + (long)m0 * lda;
    const __half* Alp = ALO ? (Al + aoff + (long)m0 * lda) : Ahp;
    const __half* Bp  = Bm + boff + (long)n0 * ldb;

    int lrow = tid >> 1, c0 = (tid & 1) * 2;
    const char* pAh = (const char*)(Ahp + (long)lrow * lda) + c0 * 16;
    const char* pAl = (const char*)(Alp + (long)lrow * lda) + c0 * 16;
    const char* pB  = (const char*)(Bp  + (long)lrow * ldb) + c0 * 16;
    uint32_t d0 = SWZ(lrow, c0), d1 = SWZ(lrow, c0 + 1);

#define ISSUE(stg, c) do { long ob = (long)(c) * 64; uint32_t bp = sb + (stg) * STAGEB; \
    cpa16(bp + d0,            pAh + ob); cpa16(bp + d1,            pAh + ob + 16); \
    if (ALO) { cpa16(bp + ATILEB + d0, pAl + ob); cpa16(bp + ATILEB + d1, pAl + ob + 16); } \
    cpa16(bp + 2*ATILEB + d0, pB  + ob); cpa16(bp + 2*ATILEB + d1, pB  + ob + 16); } while (0)

    int arow = wm * 32 + ((lid >> 3) & 1) * 8 + (lid & 7);
    int acsel = (lid >> 4) & 1;
    uint32_t axor = (uint32_t)((arow >> 1) & 3);
    int brow = wn * 64 + ((lid >> 4) & 1) * 8 + (lid & 7);
    int bcsel = (lid >> 3) & 1;
    uint32_t bxor = (uint32_t)((brow >> 1) & 3);

    float d[2][8][4];
#pragma unroll
    for (int i = 0; i < 2; i++)
#pragma unroll
        for (int j = 0; j < 8; j++)
#pragma unroll
            for (int q = 0; q < 4; q++) d[i][j][q] = 0.f;

    const int nCh = K >> 5;
    ISSUE(0, 0); cpcommit();
    ISSUE(1, 1); cpcommit();
    ISSUE(2, 2); cpcommit();

    int stg = 0;
    for (int c = 0; c < nCh; c++) {
        cpwait<2>();
        __syncthreads();
        if (c + 3 < nCh) {
            int ns = stg + 3; if (ns >= NSTG) ns -= NSTG;
            ISSUE(ns, c + 3);
        }
        cpcommit();

        uint32_t cb = sb + stg * STAGEB;
#pragma unroll
        for (int ks = 0; ks < 2; ks++) {
            uint32_t fah[2][4], fal[2][4], fb[4][4];
#pragma unroll
            for (int mf = 0; mf < 2; mf++) {
                uint32_t ad = cb + (uint32_t)(arow + mf * 16) * 64u
                            + (((uint32_t)(ks * 2 + acsel) ^ axor) * 16u);
                ldsm4(fah[mf], ad);
                if (ALO) ldsm4(fal[mf], ad + ATILEB);
            }
#pragma unroll
            for (int np = 0; np < 4; np++) {
                uint32_t bd = cb + 2 * ATILEB + (uint32_t)(brow + np * 16) * 64u
                            + (((uint32_t)(ks * 2 + bcsel) ^ bxor) * 16u);
                ldsm4(fb[np], bd);
            }
#pragma unroll
            for (int mf = 0; mf < 2; mf++)
#pragma unroll
                for (int nf = 0; nf < 8; nf++)
                    mma16816(d[mf][nf], fah[mf], &fb[nf >> 1][(nf & 1) * 2]);
            if (ALO) {
#pragma unroll
                for (int mf = 0; mf < 2; mf++)
#pragma unroll
                    for (int nf = 0; nf < 8; nf++)
                        mma16816(d[mf][nf], fal[mf], &fb[nf >> 1][(nf & 1) * 2]);
            }
        }
        if (++stg >= NSTG) stg = 0;
    }
#undef ISSUE

    int g = lid >> 2, tg = lid & 3;
#pragma unroll
    for (int mf = 0; mf < 2; mf++) {
#pragma unroll
        for (int cp = 0; cp < 2; cp++) {
            int m = m0 + wm * 32 + mf * 16 + cp * 8 + g;
            long rb = (long)m * ldc + coff;
#pragma unroll
            for (int nf = 0; nf < 8; nf++) {
                int n = n0 + wn * 64 + nf * 8 + tg * 2;
                float v0 = d[mf][nf][cp * 2];
                float v1 = d[mf][nf][cp * 2 + 1];
                if (bias) { v0 += bias[n]; v1 += bias[n + 1]; }
                if (ACT) { v0 = fmaxf(v0, 0.f); v1 = fmaxf(v1, 0.f); }
                if (RES) { v0 += Rres[rb + n]; v1 += Rres[rb + n + 1]; }
                if (WFP32)
                    *reinterpret_cast<float2*>(C + rb + n) = make_float2(v0, v1);
                if (WSPLIT) {
                    __half h0 = __float2half_rn(v0);
                    __half h1 = __float2half_rn(v1);
                    __half2 hh; hh.x = h0; hh.y = h1;
                    *reinterpret_cast<__half2*>(Ch + rb + n) = hh;
                    __half2 ll;
                    ll.x = __float2half_rn(v0 - __half2float(h0));
                    ll.y = __float2half_rn(v1 - __half2float(h1));
                    *reinterpret_cast<__half2*>(Cl + rb + n) = ll;
                }
            }
        }
    }
}

// mirror upper-triangle 128-blocks of symmetric sim into lower triangle
__global__ void mirror_k(float* __restrict__ sc)
{
    int b = blockIdx.y;
    int p = blockIdx.x;               // [0, 28*16)
    int pair = p >> 4, t = p & 15;
    int BI = 1, acc = 0;
    while (pair >= acc + BI) { acc += BI; BI++; }
    int BJ = pair - acc;              // BI in 1..7, BJ < BI
    int tr = t >> 2, tc = t & 3;
    int r0 = BI * 128 + tr * 32;
    int c0 = BJ * 128 + tc * 32;
    long base = (long)b * NS * NS;
    __shared__ float tile[32][33];
    int tx = threadIdx.x, ty = threadIdx.y;   // (32, 8)
#pragma unroll
    for (int i = 0; i < 4; i++)
        tile[ty + i * 8][tx] = sc[base + (long)(c0 + ty + i * 8) * NS + r0 + tx];
    __syncthreads();
#pragma unroll
    for (int i = 0; i < 4; i++)
        sc[base + (long)(r0 + ty + i * 8) * NS + c0 + tx] = tile[tx][ty + i * 8];
}

// ============================ SIMT GEMM (small final only) ============================
template<int TB, int ACT, int RES>
__global__ void gemm_k(const float* __restrict__ A, const float* __restrict__ Bm,
                       const float* __restrict__ bias, const float* __restrict__ R,
                       float* __restrict__ C,
                       int M, int N, int K, int lda, int ldb, int ldc)
{
    __shared__ float As[16][65];
    __shared__ float Bs[16][65];
    int tid = threadIdx.x;
    int tx = tid & 15, ty = tid >> 4;
    int m0 = blockIdx.y * 64, n0 = blockIdx.x * 64;
    float acc[4][4];
#pragma unroll
    for (int i = 0; i < 4; i++)
#pragma unroll
        for (int j = 0; j < 4; j++) acc[i][j] = 0.f;

    for (int k0 = 0; k0 < K; k0 += 16) {
#pragma unroll
        for (int i = 0; i < 4; i++) {
            int idx = tid + i * 256;
            int r = idx >> 4, kk = idx & 15;
            int m = m0 + r;
            As[kk][r] = (m < M) ? A[(long)m * lda + (k0 + kk)] : 0.f;
        }
#pragma unroll
        for (int i = 0; i < 4; i++) {
            int idx = tid + i * 256;
            int r = idx >> 4, kk = idx & 15;
            Bs[kk][r] = Bm[(long)(n0 + r) * ldb + (k0 + kk)];
        }
        __syncthreads();
#pragma unroll
        for (int kk = 0; kk < 16; kk++) {
            float a[4], b[4];
#pragma unroll
            for (int i = 0; i < 4; i++) a[i] = As[kk][ty + 16 * i];
#pragma unroll
            for (int j = 0; j < 4; j++) b[j] = Bs[kk][tx + 16 * j];
#pragma unroll
            for (int i = 0; i < 4; i++)
#pragma unroll
                for (int j = 0; j < 4; j++) acc[i][j] += a[i] * b[j];
        }
        __syncthreads();
    }
#pragma unroll
    for (int i = 0; i < 4; i++) {
        int m = m0 + ty + 16 * i;
        if (m >= M) continue;
#pragma unroll
        for (int j = 0; j < 4; j++) {
            int n = n0 + tx + 16 * j;
            float v = acc[i][j];
            if (bias) v += bias[n];
            if (ACT) v = fmaxf(v, 0.f);
            C[(long)m * ldc + n] = v;
        }
    }
}

// ============================ elementwise / reduction kernels ============================
__device__ __forceinline__ void split4_store(float4 v, __half* h, __half* l, long i)
{
    __half2 h0, h1, l0, l1;
    h0.x = __float2half_rn(v.x); h0.y = __float2half_rn(v.y);
    h1.x = __float2half_rn(v.z); h1.y = __float2half_rn(v.w);
    l0.x = __float2half_rn(v.x - __half2float(h0.x));
    l0.y = __float2half_rn(v.y - __half2float(h0.y));
    l1.x = __float2half_rn(v.z - __half2float(h1.x));
    l1.y = __float2half_rn(v.w - __half2float(h1.y));
    reinterpret_cast<__half2*>(h)[2 * i] = h0;
    reinterpret_cast<__half2*>(h)[2 * i + 1] = h1;
    reinterpret_cast<__half2*>(l)[2 * i] = l0;
    reinterpret_cast<__half2*>(l)[2 * i + 1] = l1;
}

__global__ void split_k(const float* __restrict__ s, __half* __restrict__ h,
                        __half* __restrict__ l, long n4)
{
    long i = (long)blockIdx.x * blockDim.x + threadIdx.x;
    if (i >= n4) return;
    split4_store(reinterpret_cast<const float4*>(s)[i], h, l, i);
}

__global__ void wsplit_k(const float* __restrict__ w0, const float* __restrict__ w1,
                         const float* __restrict__ w2, const float* __restrict__ w3,
                         const float* __restrict__ w4, const float* __restrict__ w5,
                         __half* __restrict__ h)
{
    long i = (long)blockIdx.x * blockDim.x + threadIdx.x;
    const float* src; long base;
    if      (i < 65536)  { src = w0; base = 0;      }
    else if (i < 262144) { src = w1; base = 65536;  }
    else if (i < 327680) { src = w2; base = 262144; }
    else if (i < 458752) { src = w3; base = 327680; }
    else if (i < 589824) { src = w4; base = 458752; }
    else if (i < 720896) { src = w5; base = 589824; }
    else return;
    float4 v = reinterpret_cast<const float4*>(src)[i - base];
    __half2 h0, h1;
    h0.x = __float2half_rn(v.x); h0.y = __float2half_rn(v.y);
    h1.x = __float2half_rn(v.z); h1.y = __float2half_rn(v.w);
    reinterpret_cast<__half2*>(h)[2 * i] = h0;
    reinterpret_cast<__half2*>(h)[2 * i + 1] = h1;
}

__global__ void vtrans_k(const __half* __restrict__ qh, const __half* __restrict__ ql,
                         __half* __restrict__ vth)
{
    int z = blockIdx.z, zb = z >> 1, zh = z & 1;
    int d0 = blockIdx.x * 32, k0 = blockIdx.y * 32;
    __shared__ float t[32][33];
    int tx = threadIdx.x, ty = threadIdx.y;
    long base = (long)zb * NS * 1536 + 1024 + zh * 256;
#pragma unroll
    for (int i = 0; i < 4; i++) {
        int k = k0 + ty + i * 8;
        long idx = base + (long)k * 1536 + d0 + tx;
        t[ty + i * 8][tx] = __half2float(qh[idx]) + __half2float(ql[idx]);
    }
    __syncthreads();
    __half* oh = vth + (long)z * DHH * NS;
#pragma unroll
    for (int i = 0; i < 4; i++) {
        int d = d0 + ty + i * 8;
        oh[(long)d * NS + k0 + tx] = __float2half_rn(t[tx][ty + i * 8]);
    }
}

// softmax (1/16 scale) + fp16 hi output only (probs lo term dropped)
__global__ void softmax_split_k(const float* __restrict__ s, __half* __restrict__ ah)
{
    long row = blockIdx.x;
    const float* p = s + row * 1024;
    int t = threadIdx.x;              // 256
    float4 v4 = reinterpret_cast<const float4*>(p)[t];
    float v[4] = { v4.x * 0.0625f, v4.y * 0.0625f, v4.z * 0.0625f, v4.w * 0.0625f };
    float mx = fmaxf(fmaxf(v[0], v[1]), fmaxf(v[2], v[3]));
    __shared__ float red[256];
    red[t] = mx; __syncthreads();
    for (int o = 128; o > 0; o >>= 1) { if (t < o) red[t] = fmaxf(red[t], red[t + o]); __syncthreads(); }
    mx = red[0]; __syncthreads();
    float sum = 0.f;
#pragma unroll
    for (int i = 0; i < 4; i++) { v[i] = __expf(v[i] - mx); sum += v[i]; }
    red[t] = sum; __syncthreads();
    for (int o = 128; o > 0; o >>= 1) { if (t < o) red[t] += red[t + o]; __syncthreads(); }
    float inv = 1.f / red[0];
    __half2 hh[2];
#pragma unroll
    for (int i = 0; i < 4; i++)
        ((__half*)hh)[i] = __float2half_rn(v[i] * inv);
    long ob = row * 1024 + t * 4;
    *reinterpret_cast<__half2*>(ah + ob)     = hh[0];
    *reinterpret_cast<__half2*>(ah + ob + 2) = hh[1];
}

__global__ void addln_k(const float* __restrict__ a, const float* __restrict__ r,
                        const float* __restrict__ g, const float* __restrict__ be,
                        float* __restrict__ o, __half* __restrict__ oh,
                        __half* __restrict__ ol)
{
    long row = blockIdx.x;
    int t = threadIdx.x;
    long base = row * 512;
    float v0 = a[base + t]       + r[base + t];
    float v1 = a[base + t + 256] + r[base + t + 256];
    __shared__ float rs[256], rq[256];
    rs[t] = v0 + v1; rq[t] = v0 * v0 + v1 * v1;
    __syncthreads();
    for (int off = 128; off > 0; off >>= 1) {
        if (t < off) { rs[t] += rs[t + off]; rq[t] += rq[t + off]; }
        __syncthreads();
    }
    float mu  = rs[0] * (1.f / 512.f);
    float var = rq[0] * (1.f / 512.f) - mu * mu;
    float inv = rsqrtf(var + 1e-5f);
    float o0 = (v0 - mu) * inv * g[t]       + be[t];
    float o1 = (v1 - mu) * inv * g[t + 256] + be[t + 256];
    o[base + t] = o0; o[base + t + 256] = o1;
    if (oh) {
        __half h0 = __float2half_rn(o0), h1 = __float2half_rn(o1);
        oh[base + t] = h0; oh[base + t + 256] = h1;
        ol[base + t]       = __float2half_rn(o0 - __half2float(h0));
        ol[base + t + 256] = __float2half_rn(o1 - __half2float(h1));
    }
}

__global__ void rownorm_k(const float* __restrict__ x, __half* __restrict__ nh,
                          __half* __restrict__ nl)
{
    long row = blockIdx.x;
    int t = threadIdx.x;
    long base = row * 512;
    float v0 = x[base + t], v1 = x[base + t + 256];
    __shared__ float rq[256];
    rq[t] = v0 * v0 + v1 * v1;
    __syncthreads();
    for (int off = 128; off > 0; off >>= 1) {
        if (t < off) rq[t] += rq[t + off];
        __syncthreads();
    }
    float s = 1.f / fmaxf(sqrtf(rq[0]), 1e-12f);
    float o0 = v0 * s, o1 = v1 * s;
    __half h0 = __float2half_rn(o0), h1 = __float2half_rn(o1);
    nh[base + t] = h0; nh[base + t + 256] = h1;
    nl[base + t]       = __float2half_rn(o0 - __half2float(h0));
    nl[base + t + 256] = __float2half_rn(o1 - __half2float(h1));
}

// single-pass exact top-4 per row (comparator: value desc, index asc — jax tie rule)
__global__ void topk_k(const float* __restrict__ sim, int* __restrict__ idxo)
{
    int row = blockIdx.x;
    const float* p = sim + (long)row * 1024;
    int t = threadIdx.x;              // 128
    float v[4] = {-1e30f, -1e30f, -1e30f, -1e30f};
    int   ix[4] = {1 << 30, 1 << 30, 1 << 30, 1 << 30};
#pragma unroll
    for (int r = 0; r < 8; r++) {
        int j = t + r * 128;
        float val = p[j];
        if (val > v[3] || (val == v[3] && j < ix[3])) {
            v[3] = val; ix[3] = j;
#pragma unroll
            for (int q = 3; q > 0; q--) {
                bool up = v[q] > v[q-1] || (v[q] == v[q-1] && ix[q] < ix[q-1]);
                if (up) {
                    float tv = v[q]; v[q] = v[q-1]; v[q-1] = tv;
                    int ti = ix[q]; ix[q] = ix[q-1]; ix[q-1] = ti;
                }
            }
        }
    }
    __shared__ float sv[128][4];
    __shared__ int   si[128][4];
#pragma unroll
    for (int q = 0; q < 4; q++) { sv[t][q] = v[q]; si[t][q] = ix[q]; }
    __syncthreads();
    for (int off = 64; off > 0; off >>= 1) {
        if (t < off) {
            float mv[4]; int mi[4];
            int a = 0, b = 0;
#pragma unroll
            for (int q = 0; q < 4; q++) {
                float av = sv[t][a], bv = sv[t + off][b];
                int   ai = si[t][a], bi = si[t + off][b];
                bool ta = av > bv || (av == bv && ai < bi);
                if (ta) { mv[q] = av; mi[q] = ai; a++; }
                else    { mv[q] = bv; mi[q] = bi; b++; }
            }
#pragma unroll
            for (int q = 0; q < 4; q++) { sv[t][q] = mv[q]; si[t][q] = mi[q]; }
        }
        __syncthreads();
    }
    if (t < 4) idxo[row * 4 + t] = si[0][t];
}

__global__ void zero_k(float4* __restrict__ p, long n)
{
    long i = (long)blockIdx.x * blockDim.x + threadIdx.x;
    if (i < n) p[i] = make_float4(0.f, 0.f, 0.f, 0.f);
}

__global__ void scatter_k(const int* __restrict__ idx, unsigned int* __restrict__ mskw)
{
    int rr = blockIdx.x * blockDim.x + threadIdx.x;
    if (rr >= ROWS) return;
    int b = rr >> 10, i = rr & 1023;
    unsigned int* mb = mskw + (long)b * NS * 32;
#pragma unroll
    for (int t = 0; t < 4; t++) {
        int j = idx[rr * 4 + t];
        if (j != i) {
            atomicOr(&mb[i * 32 + (j >> 5)], 1u << (j & 31));
            atomicOr(&mb[j * 32 + (i >> 5)], 1u << (i & 31));
        }
    }
}

__global__ void combine_k(const float* __restrict__ x1, const float* __restrict__ sim,
                          const unsigned int* __restrict__ mskw,
                          __half* __restrict__ ch, __half* __restrict__ cl)
{
    int rr = blockIdx.x;
    int b = rr >> 10, i = rr & 1023;
    int d = threadIdx.x;              // 512
    __shared__ unsigned int smk[32];
    if (d < 32) smk[d] = mskw[(long)b * NS * 32 + i * 32 + d];
    __syncthreads();
    const float* srow = sim + (long)rr * 1024;
    float acc = 0.f, cnt = 0.f;
#pragma unroll 4
    for (int w = 0; w < 32; w++) {
        unsigned int m = smk[w];
        while (m) {
            int bi = __ffs(m) - 1;
            m &= m - 1;
            int j = w * 32 + bi;
            float wgt = srow[j];
            acc += wgt * x1[((long)(b * NS + j)) * 512 + d];
            cnt += wgt;
        }
    }
    float xv = x1[(long)rr * 512 + d];
    float nv = acc / fmaxf(cnt, 1.0f);
    __half hx = __float2half_rn(xv), hn = __float2half_rn(nv);
    long ob = (long)rr * 1024;
    ch[ob + d] = hx;       cl[ob + d]       = __float2half_rn(xv - __half2float(hx));
    ch[ob + 512 + d] = hn; cl[ob + 512 + d] = __float2half_rn(nv - __half2float(hn));
}

__global__ void pool1_k(const float* __restrict__ x2, float* __restrict__ part)
{
    int b = blockIdx.x, chunk = blockIdx.y;
    int d = threadIdx.x;
    const float* src = x2 + ((long)b * NS + chunk * 128) * 512;
    float s = 0.f;
#pragma unroll 8
    for (int sdx = 0; sdx < 128; sdx++)
        s += src[(long)sdx * 512 + d];
    part[((long)b * 8 + chunk) * 512 + d] = s;
}

__global__ void pool2_k(const float* __restrict__ part, float* __restrict__ pool)
{
    int b = blockIdx.x;
    int d = threadIdx.x;
    float s = 0.f;
#pragma unroll
    for (int c = 0; c < 8; c++)
        s += part[((long)b * 8 + c) * 512 + d];
    pool[b * 512 + d] = s * (1.f / 1024.f);
}

// =================================================================================
extern "C" void kernel_launch(void* const* d_in, const int* in_sizes, int n_in,
                              void* d_out, int out_size)
{
    const float* x      = (const float*)d_in[0];
    const float* enc_w  = (const float*)d_in[1];
    const float* enc_b  = (const float*)d_in[2];
    const float* in_w   = (const float*)d_in[3];
    const float* in_b   = (const float*)d_in[4];
    const float* out_w  = (const float*)d_in[5];
    const float* out_b  = (const float*)d_in[6];
    const float* ln1_g  = (const float*)d_in[7];
    const float* ln1_b  = (const float*)d_in[8];
    const float* ffn_w1 = (const float*)d_in[9];
    const float* ffn_b1 = (const float*)d_in[10];
    const float* ffn_w2 = (const float*)d_in[11];
    const float* ffn_b2 = (const float*)d_in[12];
    const float* gc_w   = (const float*)d_in[13];
    const float* gc_b   = (const float*)d_in[14];
    const float* ln2_g  = (const float*)d_in[15];
    const float* ln2_b  = (const float*)d_in[16];
    const float* dec_w  = (const float*)d_in[17];
    const float* dec_b  = (const float*)d_in[18];
    float* out = (float*)d_out;

    float *h_, *sc_, *t1_, *x1_, *x2_, *poolp_, *pool_;
    int* idx_;
    unsigned int* mskw_;
    __half *xh_, *xl_, *hh_, *hl_, *qkvh_, *qkvl_, *ah_, *vth_;
    __half *ctxh_, *ctxl_, *x1h_, *x1l_, *midh_, *midl_, *nh_, *nl_, *cbh_, *cbl_, *wh_;
    cudaGetSymbolAddress((void**)&h_,    g_h);
    cudaGetSymbolAddress((void**)&sc_,   g_sc);
    cudaGetSymbolAddress((void**)&t1_,   g_t1);
    cudaGetSymbolAddress((void**)&x1_,   g_x1);
    cudaGetSymbolAddress((void**)&x2_,   g_x2);
    cudaGetSymbolAddress((void**)&poolp_,g_poolp);
    cudaGetSymbolAddress((void**)&pool_, g_pool);
    cudaGetSymbolAddress((void**)&idx_,  g_idx);
    cudaGetSymbolAddress((void**)&mskw_, g_mskw);
    cudaGetSymbolAddress((void**)&xh_,   g_xh);   cudaGetSymbolAddress((void**)&xl_,   g_xl);
    cudaGetSymbolAddress((void**)&hh_,   g_hh);   cudaGetSymbolAddress((void**)&hl_,   g_hl);
    cudaGetSymbolAddress((void**)&qkvh_, g_qkvh); cudaGetSymbolAddress((void**)&qkvl_, g_qkvl);
    cudaGetSymbolAddress((void**)&ah_,   g_ah);
    cudaGetSymbolAddress((void**)&vth_,  g_vth);
    cudaGetSymbolAddress((void**)&ctxh_, g_ctxh); cudaGetSymbolAddress((void**)&ctxl_, g_ctxl);
    cudaGetSymbolAddress((void**)&x1h_,  g_x1h);  cudaGetSymbolAddress((void**)&x1l_,  g_x1l);
    cudaGetSymbolAddress((void**)&midh_, g_midh); cudaGetSymbolAddress((void**)&midl_, g_midl);
    cudaGetSymbolAddress((void**)&nh_,   g_nh);   cudaGetSymbolAddress((void**)&nl_,   g_nl);
    cudaGetSymbolAddress((void**)&cbh_,  g_cbh);  cudaGetSymbolAddress((void**)&cbl_,  g_cbl);
    cudaGetSymbolAddress((void**)&wh_,   g_wh);

    cudaFuncSetAttribute(mmagemm_k<1,0,1,1,0,1>, cudaFuncAttributeMaxDynamicSharedMemorySize, MMSMEM);
    cudaFuncSetAttribute(mmagemm_k<0,0,0,1,0,1>, cudaFuncAttributeMaxDynamicSharedMemorySize, MMSMEM);
    cudaFuncSetAttribute(mmagemm_k<0,0,0,1,1,1>, cudaFuncAttributeMaxDynamicSharedMemorySize, MMSMEM);
    cudaFuncSetAttribute(mmagemm_k<0,0,1,0,0,1>, cudaFuncAttributeMaxDynamicSharedMemorySize, MMSMEM);
    cudaFuncSetAttribute(mmagemm_k<0,0,1,0,0,0>, cudaFuncAttributeMaxDynamicSharedMemorySize, MMSMEM);
    cudaFuncSetAttribute(mmagemm_k<1,0,1,0,0,1>, cudaFuncAttributeMaxDynamicSharedMemorySize, MMSMEM);
    cudaFuncSetAttribute(mmagemm_k<0,1,0,1,0,1>, cudaFuncAttributeMaxDynamicSharedMemorySize, MMSMEM);

    dim3 blk(256);

    // input split + fused weight conversion
    split_k<<<(ROWS*DIN/4 + 255)/256, blk>>>(x, xh_, xl_, (long)ROWS*DIN/4);
    wsplit_k<<<(720896 + 255)/256, blk>>>(enc_w, in_w, out_w, ffn_w1, ffn_w2, gc_w, wh_);

    // G1: h = relu(x @ enc_w^T + b), fp32 + split
    mmagemm_k<1,0,1,1,0,1><<<dim3(4,256,1), blk, MMSMEM>>>(xh_, xl_, wh_+WO_ENC,
        enc_b, nullptr, h_, hh_, hl_, 512, 512, 512, 512, 0,0,0,0,0,0, 1);

    // G2: qkv = h @ in_w^T + b, split only (v reconstructed in vtrans)
    mmagemm_k<0,0,1,0,0,1><<<dim3(12,256,1), blk, MMSMEM>>>(hh_, hl_, wh_+WO_IN,
        in_b, nullptr, nullptr, qkvh_, qkvl_, 512, 512, 512, 1536, 0,0,0,0,0,0, 1);

    // v transpose (reads qkv hi/lo) -> vT fp16
    vtrans_k<<<dim3(8,32,64), dim3(32,8)>>>(qkvh_, qkvl_, vth_);

    // G3: scores = q @ k^T  (batched z=64)
    mmagemm_k<0,0,0,1,0,1><<<dim3(8,8,64), blk, MMSMEM>>>(qkvh_, qkvl_, qkvh_+512,
        nullptr, nullptr, sc_, nullptr, nullptr, 256, 1536, 1536, 1024,
        256, (long)NS*1536, 256, (long)NS*1536, (long)NS*NS, 2L*NS*NS, 2);

    // fused softmax + fp16 hi output
    softmax_split_k<<<NB*NHD*NS, 256>>>(sc_, ah_);

    // G4: ctx = attn @ vT^T (batched z=64), probs hi-only (ALO=0), split-out
    mmagemm_k<0,0,1,0,0,0><<<dim3(2,8,64), blk, MMSMEM>>>(ah_, nullptr, vth_,
        nullptr, nullptr, nullptr, ctxh_, ctxl_, 1024, 1024, 1024, 512,
        (long)NS*NS, 2L*NS*NS, (long)DHH*NS, 2L*DHH*NS, 256, (long)NS*512, 2);

    // G5: attn_out = ctx @ out_w^T + b -> t1 fp32
    mmagemm_k<0,0,0,1,0,1><<<dim3(4,256,1), blk, MMSMEM>>>(ctxh_, ctxl_, wh_+WO_OUT,
        out_b, nullptr, t1_, nullptr, nullptr, 512, 512, 512, 512, 0,0,0,0,0,0, 1);

    // x1 = LN(h + attn_out), fp32 + split
    addln_k<<<ROWS, 256>>>(h_, t1_, ln1_g, ln1_b, x1_, x1h_, x1l_);

    // G6: mid = relu(x1 @ ffn_w1^T + b1), split only
    mmagemm_k<1,0,1,0,0,1><<<dim3(8,256,1), blk, MMSMEM>>>(x1h_, x1l_, wh_+WO_F1,
        ffn_b1, nullptr, nullptr, midh_, midl_, 512, 512, 512, 1024, 0,0,0,0,0,0, 1);

    // G7: x1 = x1 + mid @ ffn_w2^T + b2 (residual), fp32
    mmagemm_k<0,1,0,1,0,1><<<dim3(4,256,1), blk, MMSMEM>>>(midh_, midl_, wh_+WO_F2,
        ffn_b2, x1_, x1_, nullptr, nullptr, 1024, 1024, 1024, 512, 0,0,0,0,0,0, 1);

    // nrm = rownorm(x1), split only
    rownorm_k<<<ROWS, 256>>>(x1_, nh_, nl_);

    // sim = nrm @ nrm^T (batched z=32) — upper-triangle blocks only (symmetric)
    mmagemm_k<0,0,0,1,1,1><<<dim3(36,1,32), blk, MMSMEM>>>(nh_, nl_, nh_,
        nullptr, nullptr, sc_, nullptr, nullptr, 512, 512, 512, 1024,
        0, (long)NS*512, 0, (long)NS*512, 0, (long)NS*NS, 1);

    // mirror upper -> lower triangle
    mirror_k<<<dim3(28*16, NB), dim3(32,8)>>>(sc_);

    // adjacency (1-bit mask)
    zero_k<<<(int)(((long)NB*NS*32*4/16 + 255)/256), blk>>>((float4*)mskw_, (long)NB*NS*32*4/16);
    topk_k<<<ROWS, 128>>>(sc_, idx_);
    scatter_k<<<(ROWS+255)/256, blk>>>(idx_, mskw_);

    // combined = [x1 | nsum/cnt] -> fp16 hi/lo
    combine_k<<<ROWS, 512>>>(x1_, sc_, mskw_, cbh_, cbl_);

    // G8: gco = combined @ gc_w^T + b -> t1 fp32
    mmagemm_k<0,0,0,1,0,1><<<dim3(4,256,1), blk, MMSMEM>>>(cbh_, cbl_, wh_+WO_GC,
        gc_b, nullptr, t1_, nullptr, nullptr, 1024, 1024, 1024, 512, 0,0,0,0,0,0, 1);

    // x2 = LN(x1 + gco), fp32 only
    addln_k<<<ROWS, 256>>>(x1_, t1_, ln2_g, ln2_b, x2_, nullptr, nullptr);

    // pool (two-stage) + decoder
    pool1_k<<<dim3(NB,8), 512>>>(x2_, poolp_);
    pool2_k<<<NB, 512>>>(poolp_, pool_);
    gemm_k<1,0,0><<<dim3(8,1,1), blk>>>(pool_, dec_w, dec_b, nullptr, out,
        32, 512, 512, 512, 512, 512);
}

// round 14
// speedup vs baseline: 1.1305x; 1.0292x over previous
#include <cuda_runtime.h>
#include <cuda_bf16.h>
#include <cuda_fp16.h>
#include <cstdint>

// Problem constants
#define NB   32
#define NS   1024
#define DIN  512
#define DH   512
#define DOUT 512
#define NHD  2
#define DHH  256
#define ROWS (NB*NS)             // 32768
#define SCSZ (67108864L)         // NB*NHD*NS*NS

// ============================ helpers ============================
__device__ __forceinline__ uint32_t smem_to_u32(const void* p) {
    uint32_t a;
    asm("{ .reg .u64 t; cvta.to.shared.u64 t, %1; cvt.u32.u64 %0, t; }" : "=r"(a) : "l"(p));
    return a;
}
__device__ __forceinline__ void ldsm4(uint32_t* r, uint32_t addr) {
    asm volatile("ldmatrix.sync.aligned.m8n8.x4.shared.b16 {%0,%1,%2,%3}, [%4];"
                 : "=r"(r[0]), "=r"(r[1]), "=r"(r[2]), "=r"(r[3]) : "r"(addr));
}
__device__ __forceinline__ void mma16816(float* d, const uint32_t* a, const uint32_t* b) {
    asm volatile("mma.sync.aligned.m16n8k16.row.col.f32.f16.f16.f32 "
                 "{%0,%1,%2,%3}, {%4,%5,%6,%7}, {%8,%9}, {%0,%1,%2,%3};"
                 : "+f"(d[0]), "+f"(d[1]), "+f"(d[2]), "+f"(d[3])
                 : "r"(a[0]), "r"(a[1]), "r"(a[2]), "r"(a[3]), "r"(b[0]), "r"(b[1]));
}
__device__ __forceinline__ void cpa16(uint32_t s, const void* g) {
    asm volatile("cp.async.cg.shared.global [%0], [%1], 16;" :: "r"(s), "l"(g));
}
__device__ __forceinline__ void cpcommit() { asm volatile("cp.async.commit_group;"); }
template<int N> __device__ __forceinline__ void cpwait() {
    asm volatile("cp.async.wait_group %0;" :: "n"(N));
}

// smem: 3 tiles (Ah, Al, B) of 128 rows x 64B (32 fp16), XOR-swizzled, 4 stages
#define ATILEB 8192               // 128*64
#define STAGEB (3*ATILEB)         // 24576
#define NSTG   4
#define MMSMEM (NSTG*STAGEB)      // 98304
#define SWZ(row, chunk) ((uint32_t)(row)*64u + ((uint32_t)((chunk) ^ (((row)>>1)&3))*16u))

// ============================ scratch buffers ============================
__device__ float g_h   [ROWS*DH];
__device__ float g_sc  [SCSZ];               // sim only now
__device__ float g_t1  [ROWS*DH];
__device__ float g_x1  [ROWS*DH];
__device__ float g_x2  [ROWS*DH];
__device__ float g_poolp[NB*8*DH];
__device__ float g_pool[NB*DH];
__device__ int   g_idx [ROWS*4];
__device__ unsigned int g_mskw [(long)NB*NS*32];   // bitmask adjacency, 4MB

__device__ __half g_xh[ROWS*DIN],   g_xl[ROWS*DIN];
__device__ __half g_hh[ROWS*DH],    g_hl[ROWS*DH];
__device__ __half g_qkvh[ROWS*3*DH],g_qkvl[ROWS*3*DH];
__device__ __half g_ah[SCSZ];                // scores, then probs (in-place softmax)
__device__ __half g_vth[(long)NB*NHD*DHH*NS];
__device__ __half g_ctxh[ROWS*DH],  g_ctxl[ROWS*DH];
__device__ __half g_x1h[ROWS*DH],   g_x1l[ROWS*DH];
__device__ __half g_midh[ROWS*2*DH],g_midl[ROWS*2*DH];
__device__ __half g_nh[ROWS*DH],    g_nl[ROWS*DH];
__device__ __half g_cbh[ROWS*2*DH], g_cbl[ROWS*2*DH];
__device__ __half g_wh[4*1024*1024];

// weight offsets (elements)
#define WO_ENC 0
#define WO_IN  262144
#define WO_OUT 1048576
#define WO_F1  1310720
#define WO_F2  1835008
#define WO_GC  2359296

// ============================ HMMA GEMM (fp16x2, cp.async 4-stage, 2 CTA/SM) ============
// C[M,N] = act((Ah[+Al]) @ B^T + bias) (+R).  A hi/lo fp16 [M,K] row-major, B fp16 [N,K].
// CTA tile 128x128, warp tile 32x64 (4x2 warps), K chunks of 32, swizzled smem.
// TRIU=1: blockIdx.x in [0,36) remapped to upper-triangle (bx,by), by<=bx (symmetric C).
// ALO=0: skip A-lo stream (half the MMAs).  WSPLIT: Cl==nullptr -> write hi only.
template<int ACT, int RES, int WSPLIT, int WFP32, int TRIU, int ALO>
__global__ void __launch_bounds__(256, 2)
mmagemm_k(const __half* __restrict__ Ah, const __half* __restrict__ Al,
          const __half* __restrict__ Bm,
          const float* __restrict__ bias, const float* __restrict__ Rres,
          float* __restrict__ C, __half* __restrict__ Ch, __half* __restrict__ Cl,
          int K, int lda, int ldb, int ldc,
          long sA1, long sA2, long sB1, long sB2, long sC1, long sC2, int HZ)
{
    extern __shared__ char sm[];
    uint32_t sb = smem_to_u32(sm);

    int tid = threadIdx.x, wid = tid >> 5, lid = tid & 31;
    int wm = wid >> 1, wn = wid & 1;
    int z = blockIdx.z, zb = z / HZ, zh = z - zb * HZ;
    long aoff = (long)zb * sA2 + (long)zh * sA1;
    long boff = (long)zb * sB2 + (long)zh * sB1;
    long coff = (long)zb * sC2 + (long)zh * sC1;

    int bx, by;
    if (TRIU) {
        int p = blockIdx.x;
        by = 0;
        while (p >= 8 - by) { p -= 8 - by; by++; }
        bx = by + p;
    } else {
        bx = blockIdx.x; by = blockIdx.y;
    }
    int m0 = by * 128, n0 = bx * 128;

    const __half* Ahp = Ah + aoff + (long)m0 * lda;
    const __half* Alp = ALO ? (Al + aoff + (long)m0 * lda) : Ahp;
    const __half* Bp  = Bm + boff + (long)n0 * ldb;

    int lrow = tid >> 1, c0 = (tid & 1) * 2;
    const char* pAh = (const char*)(Ahp + (long)lrow * lda) + c0 * 16;
    const char* pAl = (const char*)(Alp + (long)lrow * lda) + c0 * 16;
    const char* pB  = (const char*)(Bp  + (long)lrow * ldb) + c0 * 16;
    uint32_t d0 = SWZ(lrow, c0), d1 = SWZ(lrow, c0 + 1);

#define ISSUE(stg, c) do { long ob = (long)(c) * 64; uint32_t bp = sb + (stg) * STAGEB; \
    cpa16(bp + d0,            pAh + ob); cpa16(bp + d1,            pAh + ob + 16); \
    if (ALO) { cpa16(bp + ATILEB + d0, pAl + ob); cpa16(bp + ATILEB + d1, pAl + ob + 16); } \
    cpa16(bp + 2*ATILEB + d0, pB  + ob); cpa16(bp + 2*ATILEB + d1, pB  + ob + 16); } while (0)

    int arow = wm * 32 + ((lid >> 3) & 1) * 8 + (lid & 7);
    int acsel = (lid >> 4) & 1;
    uint32_t axor = (uint32_t)((arow >> 1) & 3);
    int brow = wn * 64 + ((lid >> 4) & 1) * 8 + (lid & 7);
    int bcsel = (lid >> 3) & 1;
    uint32_t bxor = (uint32_t)((brow >> 1) & 3);

    float d[2][8][4];
#pragma unroll
    for (int i = 0; i < 2; i++)
#pragma unroll
        for (int j = 0; j < 8; j++)
#pragma unroll
            for (int q = 0; q < 4; q++) d[i][j][q] = 0.f;

    const int nCh = K >> 5;
    ISSUE(0, 0); cpcommit();
    ISSUE(1, 1); cpcommit();
    ISSUE(2, 2); cpcommit();

    int stg = 0;
    for (int c = 0; c < nCh; c++) {
        cpwait<2>();
        __syncthreads();
        if (c + 3 < nCh) {
            int ns = stg + 3; if (ns >= NSTG) ns -= NSTG;
            ISSUE(ns, c + 3);
        }
        cpcommit();

        uint32_t cb = sb + stg * STAGEB;
#pragma unroll
        for (int ks = 0; ks < 2; ks++) {
            uint32_t fah[2][4], fal[2][4], fb[4][4];
#pragma unroll
            for (int mf = 0; mf < 2; mf++) {
                uint32_t ad = cb + (uint32_t)(arow + mf * 16) * 64u
                            + (((uint32_t)(ks * 2 + acsel) ^ axor) * 16u);
                ldsm4(fah[mf], ad);
                if (ALO) ldsm4(fal[mf], ad + ATILEB);
            }
#pragma unroll
            for (int np = 0; np < 4; np++) {
                uint32_t bd = cb + 2 * ATILEB + (uint32_t)(brow + np * 16) * 64u
                            + (((uint32_t)(ks * 2 + bcsel) ^ bxor) * 16u);
                ldsm4(fb[np], bd);
            }
#pragma unroll
            for (int mf = 0; mf < 2; mf++)
#pragma unroll
                for (int nf = 0; nf < 8; nf++)
                    mma16816(d[mf][nf], fah[mf], &fb[nf >> 1][(nf & 1) * 2]);
            if (ALO) {
#pragma unroll
                for (int mf = 0; mf < 2; mf++)
#pragma unroll
                    for (int nf = 0; nf < 8; nf++)
                        mma16816(d[mf][nf], fal[mf], &fb[nf >> 1][(nf & 1) * 2]);
            }
        }
        if (++stg >= NSTG) stg = 0;
    }
#undef ISSUE

    int g = lid >> 2, tg = lid & 3;
#pragma unroll
    for (int mf = 0; mf < 2; mf++) {
#pragma unroll
        for (int cp = 0; cp < 2; cp++) {
            int m = m0 + wm * 32 + mf * 16 + cp * 8 + g;
            long rb = (long)m * ldc + coff;
#pragma unroll
            for (int nf = 0; nf < 8; nf++) {
                int n = n0 + wn * 64 + nf * 8 + tg * 2;
                float v0 = d[mf][nf][cp * 2];
                float v1 = d[mf][nf][cp * 2 + 1];
                if (bias) { v0 += bias[n]; v1 += bias[n + 1]; }
                if (ACT) { v0 = fmaxf(v0, 0.f); v1 = fmaxf(v1, 0.f); }
                if (RES) { v0 += Rres[rb + n]; v1 += Rres[rb + n + 1]; }
                if (WFP32)
                    *reinterpret_cast<float2*>(C + rb + n) = make_float2(v0, v1);
                if (WSPLIT) {
                    __half h0 = __float2half_rn(v0);
                    __half h1 = __float2half_rn(v1);
                    __half2 hh; hh.x = h0; hh.y = h1;
                    *reinterpret_cast<__half2*>(Ch + rb + n) = hh;
                    if (Cl) {
                        __half2 ll;
                        ll.x = __float2half_rn(v0 - __half2float(h0));
                        ll.y = __float2half_rn(v1 - __half2float(h1));
                        *reinterpret_cast<__half2*>(Cl + rb + n) = ll;
                    }
                }
            }
        }
    }
}

// mirror upper-triangle 128-blocks of symmetric sim into lower triangle
__global__ void mirror_k(float* __restrict__ sc)
{
    int b = blockIdx.y;
    int p = blockIdx.x;               // [0, 28*16)
    int pair = p >> 4, t = p & 15;
    int BI = 1, acc = 0;
    while (pair >= acc + BI) { acc += BI; BI++; }
    int BJ = pair - acc;              // BI in 1..7, BJ < BI
    int tr = t >> 2, tc = t & 3;
    int r0 = BI * 128 + tr * 32;
    int c0 = BJ * 128 + tc * 32;
    long base = (long)b * NS * NS;
    __shared__ float tile[32][33];
    int tx = threadIdx.x, ty = threadIdx.y;   // (32, 8)
#pragma unroll
    for (int i = 0; i < 4; i++)
        tile[ty + i * 8][tx] = sc[base + (long)(c0 + ty + i * 8) * NS + r0 + tx];
    __syncthreads();
#pragma unroll
    for (int i = 0; i < 4; i++)
        sc[base + (long)(r0 + ty + i * 8) * NS + c0 + tx] = tile[tx][ty + i * 8];
}

// ============================ SIMT GEMM (small final only) ============================
template<int TB, int ACT, int RES>
__global__ void gemm_k(const float* __restrict__ A, const float* __restrict__ Bm,
                       const float* __restrict__ bias, const float* __restrict__ R,
                       float* __restrict__ C,
                       int M, int N, int K, int lda, int ldb, int ldc)
{
    __shared__ float As[16][65];
    __shared__ float Bs[16][65];
    int tid = threadIdx.x;
    int tx = tid & 15, ty = tid >> 4;
    int m0 = blockIdx.y * 64, n0 = blockIdx.x * 64;
    float acc[4][4];
#pragma unroll
    for (int i = 0; i < 4; i++)
#pragma unroll
        for (int j = 0; j < 4; j++) acc[i][j] = 0.f;

    for (int k0 = 0; k0 < K; k0 += 16) {
#pragma unroll
        for (int i = 0; i < 4; i++) {
            int idx = tid + i * 256;
            int r = idx >> 4, kk = idx & 15;
            int m = m0 + r;
            As[kk][r] = (m < M) ? A[(long)m * lda + (k0 + kk)] : 0.f;
        }
#pragma unroll
        for (int i = 0; i < 4; i++) {
            int idx = tid + i * 256;
            int r = idx >> 4, kk = idx & 15;
            Bs[kk][r] = Bm[(long)(n0 + r) * ldb + (k0 + kk)];
        }
        __syncthreads();
#pragma unroll
        for (int kk = 0; kk < 16; kk++) {
            float a[4], b[4];
#pragma unroll
            for (int i = 0; i < 4; i++) a[i] = As[kk][ty + 16 * i];
#pragma unroll
            for (int j = 0; j < 4; j++) b[j] = Bs[kk][tx + 16 * j];
#pragma unroll
            for (int i = 0; i < 4; i++)
#pragma unroll
                for (int j = 0; j < 4; j++) acc[i][j] += a[i] * b[j];
        }
        __syncthreads();
    }
#pragma unroll
    for (int i = 0; i < 4; i++) {
        int m = m0 + ty + 16 * i;
        if (m >= M) continue;
#pragma unroll
        for (int j = 0; j < 4; j++) {
            int n = n0 + tx + 16 * j;
            float v = acc[i][j];
            if (bias) v += bias[n];
            if (ACT) v = fmaxf(v, 0.f);
            C[(long)m * ldc + n] = v;
        }
    }
}

// ============================ elementwise / reduction kernels ============================
__device__ __forceinline__ void split4_store(float4 v, __half* h, __half* l, long i)
{
    __half2 h0, h1, l0, l1;
    h0.x = __float2half_rn(v.x); h0.y = __float2half_rn(v.y);
    h1.x = __float2half_rn(v.z); h1.y = __float2half_rn(v.w);
    l0.x = __float2half_rn(v.x - __half2float(h0.x));
    l0.y = __float2half_rn(v.y - __half2float(h0.y));
    l1.x = __float2half_rn(v.z - __half2float(h1.x));
    l1.y = __float2half_rn(v.w - __half2float(h1.y));
    reinterpret_cast<__half2*>(h)[2 * i] = h0;
    reinterpret_cast<__half2*>(h)[2 * i + 1] = h1;
    reinterpret_cast<__half2*>(l)[2 * i] = l0;
    reinterpret_cast<__half2*>(l)[2 * i + 1] = l1;
}

__global__ void split_k(const float* __restrict__ s, __half* __restrict__ h,
                        __half* __restrict__ l, long n4)
{
    long i = (long)blockIdx.x * blockDim.x + threadIdx.x;
    if (i >= n4) return;
    split4_store(reinterpret_cast<const float4*>(s)[i], h, l, i);
}

__global__ void wsplit_k(const float* __restrict__ w0, const float* __restrict__ w1,
                         const float* __restrict__ w2, const float* __restrict__ w3,
                         const float* __restrict__ w4, const float* __restrict__ w5,
                         __half* __restrict__ h)
{
    long i = (long)blockIdx.x * blockDim.x + threadIdx.x;
    const float* src; long base;
    if      (i < 65536)  { src = w0; base = 0;      }
    else if (i < 262144) { src = w1; base = 65536;  }
    else if (i < 327680) { src = w2; base = 262144; }
    else if (i < 458752) { src = w3; base = 327680; }
    else if (i < 589824) { src = w4; base = 458752; }
    else if (i < 720896) { src = w5; base = 589824; }
    else return;
    float4 v = reinterpret_cast<const float4*>(src)[i - base];
    __half2 h0, h1;
    h0.x = __float2half_rn(v.x); h0.y = __float2half_rn(v.y);
    h1.x = __float2half_rn(v.z); h1.y = __float2half_rn(v.w);
    reinterpret_cast<__half2*>(h)[2 * i] = h0;
    reinterpret_cast<__half2*>(h)[2 * i + 1] = h1;
}

__global__ void vtrans_k(const __half* __restrict__ qh, const __half* __restrict__ ql,
                         __half* __restrict__ vth)
{
    int z = blockIdx.z, zb = z >> 1, zh = z & 1;
    int d0 = blockIdx.x * 32, k0 = blockIdx.y * 32;
    __shared__ float t[32][33];
    int tx = threadIdx.x, ty = threadIdx.y;
    long base = (long)zb * NS * 1536 + 1024 + zh * 256;
#pragma unroll
    for (int i = 0; i < 4; i++) {
        int k = k0 + ty + i * 8;
        long idx = base + (long)k * 1536 + d0 + tx;
        t[ty + i * 8][tx] = __half2float(qh[idx]) + __half2float(ql[idx]);
    }
    __syncthreads();
    __half* oh = vth + (long)z * DHH * NS;
#pragma unroll
    for (int i = 0; i < 4; i++) {
        int d = d0 + ty + i * 8;
        oh[(long)d * NS + k0 + tx] = __float2half_rn(t[tx][ty + i * 8]);
    }
}

// in-place softmax over fp16 score rows (1/16 scale); writes fp16 probs
__global__ void softmax_split_k(__half* __restrict__ sp)
{
    long row = blockIdx.x;
    __half* p = sp + row * 1024;
    int t = threadIdx.x;              // 256
    uint2 raw = *reinterpret_cast<const uint2*>(p + t * 4);
    __half2 h01 = *reinterpret_cast<__half2*>(&raw.x);
    __half2 h23 = *reinterpret_cast<__half2*>(&raw.y);
    float v[4] = { __half2float(h01.x) * 0.0625f, __half2float(h01.y) * 0.0625f,
                   __half2float(h23.x) * 0.0625f, __half2float(h23.y) * 0.0625f };
    float mx = fmaxf(fmaxf(v[0], v[1]), fmaxf(v[2], v[3]));
    __shared__ float red[256];
    red[t] = mx; __syncthreads();
    for (int o = 128; o > 0; o >>= 1) { if (t < o) red[t] = fmaxf(red[t], red[t + o]); __syncthreads(); }
    mx = red[0]; __syncthreads();
    float sum = 0.f;
#pragma unroll
    for (int i = 0; i < 4; i++) { v[i] = __expf(v[i] - mx); sum += v[i]; }
    red[t] = sum; __syncthreads();
    for (int o = 128; o > 0; o >>= 1) { if (t < o) red[t] += red[t + o]; __syncthreads(); }
    float inv = 1.f / red[0];
    __half2 o01, o23;
    o01.x = __float2half_rn(v[0] * inv); o01.y = __float2half_rn(v[1] * inv);
    o23.x = __float2half_rn(v[2] * inv); o23.y = __float2half_rn(v[3] * inv);
    uint2 ow;
    ow.x = *reinterpret_cast<uint32_t*>(&o01);
    ow.y = *reinterpret_cast<uint32_t*>(&o23);
    *reinterpret_cast<uint2*>(p + t * 4) = ow;
}

__global__ void addln_k(const float* __restrict__ a, const float* __restrict__ r,
                        const float* __restrict__ g, const float* __restrict__ be,
                        float* __restrict__ o, __half* __restrict__ oh,
                        __half* __restrict__ ol)
{
    long row = blockIdx.x;
    int t = threadIdx.x;
    long base = row * 512;
    float v0 = a[base + t]       + r[base + t];
    float v1 = a[base + t + 256] + r[base + t + 256];
    __shared__ float rs[256], rq[256];
    rs[t] = v0 + v1; rq[t] = v0 * v0 + v1 * v1;
    __syncthreads();
    for (int off = 128; off > 0; off >>= 1) {
        if (t < off) { rs[t] += rs[t + off]; rq[t] += rq[t + off]; }
        __syncthreads();
    }
    float mu  = rs[0] * (1.f / 512.f);
    float var = rq[0] * (1.f / 512.f) - mu * mu;
    float inv = rsqrtf(var + 1e-5f);
    float o0 = (v0 - mu) * inv * g[t]       + be[t];
    float o1 = (v1 - mu) * inv * g[t + 256] + be[t + 256];
    o[base + t] = o0; o[base + t + 256] = o1;
    if (oh) {
        __half h0 = __float2half_rn(o0), h1 = __float2half_rn(o1);
        oh[base + t] = h0; oh[base + t + 256] = h1;
        ol[base + t]       = __float2half_rn(o0 - __half2float(h0));
        ol[base + t + 256] = __float2half_rn(o1 - __half2float(h1));
    }
}

__global__ void rownorm_k(const float* __restrict__ x, __half* __restrict__ nh,
                          __half* __restrict__ nl)
{
    long row = blockIdx.x;
    int t = threadIdx.x;
    long base = row * 512;
    float v0 = x[base + t], v1 = x[base + t + 256];
    __shared__ float rq[256];
    rq[t] = v0 * v0 + v1 * v1;
    __syncthreads();
    for (int off = 128; off > 0; off >>= 1) {
        if (t < off) rq[t] += rq[t + off];
        __syncthreads();
    }
    float s = 1.f / fmaxf(sqrtf(rq[0]), 1e-12f);
    float o0 = v0 * s, o1 = v1 * s;
    __half h0 = __float2half_rn(o0), h1 = __float2half_rn(o1);
    nh[base + t] = h0; nh[base + t + 256] = h1;
    nl[base + t]       = __float2half_rn(o0 - __half2float(h0));
    nl[base + t + 256] = __float2half_rn(o1 - __half2float(h1));
}

// single-pass exact top-4 per row (comparator: value desc, index asc — jax tie rule)
__global__ void topk_k(const float* __restrict__ sim, int* __restrict__ idxo)
{
    int row = blockIdx.x;
    const float* p = sim + (long)row * 1024;
    int t = threadIdx.x;              // 128
    float v[4] = {-1e30f, -1e30f, -1e30f, -1e30f};
    int   ix[4] = {1 << 30, 1 << 30, 1 << 30, 1 << 30};
#pragma unroll
    for (int r = 0; r < 8; r++) {
        int j = t + r * 128;
        float val = p[j];
        if (val > v[3] || (val == v[3] && j < ix[3])) {
            v[3] = val; ix[3] = j;
#pragma unroll
            for (int q = 3; q > 0; q--) {
                bool up = v[q] > v[q-1] || (v[q] == v[q-1] && ix[q] < ix[q-1]);
                if (up) {
                    float tv = v[q]; v[q] = v[q-1]; v[q-1] = tv;
                    int ti = ix[q]; ix[q] = ix[q-1]; ix[q-1] = ti;
                }
            }
        }
    }
    __shared__ float sv[128][4];
    __shared__ int   si[128][4];
#pragma unroll
    for (int q = 0; q < 4; q++) { sv[t][q] = v[q]; si[t][q] = ix[q]; }
    __syncthreads();
    for (int off = 64; off > 0; off >>= 1) {
        if (t < off) {
            float mv[4]; int mi[4];
            int a = 0, b = 0;
#pragma unroll
            for (int q = 0; q < 4; q++) {
                float av = sv[t][a], bv = sv[t + off][b];
                int   ai = si[t][a], bi = si[t + off][b];
                bool ta = av > bv || (av == bv && ai < bi);
                if (ta) { mv[q] = av; mi[q] = ai; a++; }
                else    { mv[q] = bv; mi[q] = bi; b++; }
            }
#pragma unroll
            for (int q = 0; q < 4; q++) { sv[t][q] = mv[q]; si[t][q] = mi[q]; }
        }
        __syncthreads();
    }
    if (t < 4) idxo[row * 4 + t] = si[0][t];
}

__global__ void zero_k(float4* __restrict__ p, long n)
{
    long i = (long)blockIdx.x * blockDim.x + threadIdx.x;
    if (i < n) p[i] = make_float4(0.f, 0.f, 0.f, 0.f);
}

__global__ void scatter_k(const int* __restrict__ idx, unsigned int* __restrict__ mskw)
{
    int rr = blockIdx.x * blockDim.x + threadIdx.x;
    if (rr >= ROWS) return;
    int b = rr >> 10, i = rr & 1023;
    unsigned int* mb = mskw + (long)b * NS * 32;
#pragma unroll
    for (int t = 0; t < 4; t++) {
        int j = idx[rr * 4 + t];
        if (j != i) {
            atomicOr(&mb[i * 32 + (j >> 5)], 1u << (j & 31));
            atomicOr(&mb[j * 32 + (i >> 5)], 1u << (i & 31));
        }
    }
}

__global__ void combine_k(const float* __restrict__ x1, const float* __restrict__ sim,
                          const unsigned int* __restrict__ mskw,
                          __half* __restrict__ ch, __half* __restrict__ cl)
{
    int rr = blockIdx.x;
    int b = rr >> 10, i = rr & 1023;
    int d = threadIdx.x;              // 512
    __shared__ unsigned int smk[32];
    if (d < 32) smk[d] = mskw[(long)b * NS * 32 + i * 32 + d];
    __syncthreads();
    const float* srow = sim + (long)rr * 1024;
    float acc = 0.f, cnt = 0.f;
#pragma unroll 4
    for (int w = 0; w < 32; w++) {
        unsigned int m = smk[w];
        while (m) {
            int bi = __ffs(m) - 1;
            m &= m - 1;
            int j = w * 32 + bi;
            float wgt = srow[j];
            acc += wgt * x1[((long)(b * NS + j)) * 512 + d];
            cnt += wgt;
        }
    }
    float xv = x1[(long)rr * 512 + d];
    float nv = acc / fmaxf(cnt, 1.0f);
    __half hx = __float2half_rn(xv), hn = __float2half_rn(nv);
    long ob = (long)rr * 1024;
    ch[ob + d] = hx;       cl[ob + d]       = __float2half_rn(xv - __half2float(hx));
    ch[ob + 512 + d] = hn; cl[ob + 512 + d] = __float2half_rn(nv - __half2float(hn));
}

__global__ void pool1_k(const float* __restrict__ x2, float* __restrict__ part)
{
    int b = blockIdx.x, chunk = blockIdx.y;
    int d = threadIdx.x;
    const float* src = x2 + ((long)b * NS + chunk * 128) * 512;
    float s = 0.f;
#pragma unroll 8
    for (int sdx = 0; sdx < 128; sdx++)
        s += src[(long)sdx * 512 + d];
    part[((long)b * 8 + chunk) * 512 + d] = s;
}

__global__ void pool2_k(const float* __restrict__ part, float* __restrict__ pool)
{
    int b = blockIdx.x;
    int d = threadIdx.x;
    float s = 0.f;
#pragma unroll
    for (int c = 0; c < 8; c++)
        s += part[((long)b * 8 + c) * 512 + d];
    pool[b * 512 + d] = s * (1.f / 1024.f);
}

// =================================================================================
extern "C" void kernel_launch(void* const* d_in, const int* in_sizes, int n_in,
                              void* d_out, int out_size)
{
    const float* x      = (const float*)d_in[0];
    const float* enc_w  = (const float*)d_in[1];
    const float* enc_b  = (const float*)d_in[2];
    const float* in_w   = (const float*)d_in[3];
    const float* in_b   = (const float*)d_in[4];
    const float* out_w  = (const float*)d_in[5];
    const float* out_b  = (const float*)d_in[6];
    const float* ln1_g  = (const float*)d_in[7];
    const float* ln1_b  = (const float*)d_in[8];
    const float* ffn_w1 = (const float*)d_in[9];
    const float* ffn_b1 = (const float*)d_in[10];
    const float* ffn_w2 = (const float*)d_in[11];
    const float* ffn_b2 = (const float*)d_in[12];
    const float* gc_w   = (const float*)d_in[13];
    const float* gc_b   = (const float*)d_in[14];
    const float* ln2_g  = (const float*)d_in[15];
    const float* ln2_b  = (const float*)d_in[16];
    const float* dec_w  = (const float*)d_in[17];
    const float* dec_b  = (const float*)d_in[18];
    float* out = (float*)d_out;

    float *h_, *sc_, *t1_, *x1_, *x2_, *poolp_, *pool_;
    int* idx_;
    unsigned int* mskw_;
    __half *xh_, *xl_, *hh_, *hl_, *qkvh_, *qkvl_, *ah_, *vth_;
    __half *ctxh_, *ctxl_, *x1h_, *x1l_, *midh_, *midl_, *nh_, *nl_, *cbh_, *cbl_, *wh_;
    cudaGetSymbolAddress((void**)&h_,    g_h);
    cudaGetSymbolAddress((void**)&sc_,   g_sc);
    cudaGetSymbolAddress((void**)&t1_,   g_t1);
    cudaGetSymbolAddress((void**)&x1_,   g_x1);
    cudaGetSymbolAddress((void**)&x2_,   g_x2);
    cudaGetSymbolAddress((void**)&poolp_,g_poolp);
    cudaGetSymbolAddress((void**)&pool_, g_pool);
    cudaGetSymbolAddress((void**)&idx_,  g_idx);
    cudaGetSymbolAddress((void**)&mskw_, g_mskw);
    cudaGetSymbolAddress((void**)&xh_,   g_xh);   cudaGetSymbolAddress((void**)&xl_,   g_xl);
    cudaGetSymbolAddress((void**)&hh_,   g_hh);   cudaGetSymbolAddress((void**)&hl_,   g_hl);
    cudaGetSymbolAddress((void**)&qkvh_, g_qkvh); cudaGetSymbolAddress((void**)&qkvl_, g_qkvl);
    cudaGetSymbolAddress((void**)&ah_,   g_ah);
    cudaGetSymbolAddress((void**)&vth_,  g_vth);
    cudaGetSymbolAddress((void**)&ctxh_, g_ctxh); cudaGetSymbolAddress((void**)&ctxl_, g_ctxl);
    cudaGetSymbolAddress((void**)&x1h_,  g_x1h);  cudaGetSymbolAddress((void**)&x1l_,  g_x1l);
    cudaGetSymbolAddress((void**)&midh_, g_midh); cudaGetSymbolAddress((void**)&midl_, g_midl);
    cudaGetSymbolAddress((void**)&nh_,   g_nh);   cudaGetSymbolAddress((void**)&nl_,   g_nl);
    cudaGetSymbolAddress((void**)&cbh_,  g_cbh);  cudaGetSymbolAddress((void**)&cbl_,  g_cbl);
    cudaGetSymbolAddress((void**)&wh_,   g_wh);

    cudaFuncSetAttribute(mmagemm_k<1,0,1,1,0,1>, cudaFuncAttributeMaxDynamicSharedMemorySize, MMSMEM);
    cudaFuncSetAttribute(mmagemm_k<0,0,0,1,0,1>, cudaFuncAttributeMaxDynamicSharedMemorySize, MMSMEM);
    cudaFuncSetAttribute(mmagemm_k<0,0,0,1,1,1>, cudaFuncAttributeMaxDynamicSharedMemorySize, MMSMEM);
    cudaFuncSetAttribute(mmagemm_k<0,0,1,0,0,1>, cudaFuncAttributeMaxDynamicSharedMemorySize, MMSMEM);
    cudaFuncSetAttribute(mmagemm_k<0,0,1,0,0,0>, cudaFuncAttributeMaxDynamicSharedMemorySize, MMSMEM);
    cudaFuncSetAttribute(mmagemm_k<1,0,1,0,0,1>, cudaFuncAttributeMaxDynamicSharedMemorySize, MMSMEM);
    cudaFuncSetAttribute(mmagemm_k<0,1,0,1,0,1>, cudaFuncAttributeMaxDynamicSharedMemorySize, MMSMEM);

    dim3 blk(256);

    // input split + fused weight conversion
    split_k<<<(ROWS*DIN/4 + 255)/256, blk>>>(x, xh_, xl_, (long)ROWS*DIN/4);
    wsplit_k<<<(720896 + 255)/256, blk>>>(enc_w, in_w, out_w, ffn_w1, ffn_w2, gc_w, wh_);

    // G1: h = relu(x @ enc_w^T + b), fp32 + split
    mmagemm_k<1,0,1,1,0,1><<<dim3(4,256,1), blk, MMSMEM>>>(xh_, xl_, wh_+WO_ENC,
        enc_b, nullptr, h_, hh_, hl_, 512, 512, 512, 512, 0,0,0,0,0,0, 1);

    // G2: qkv = h @ in_w^T + b, split only (v reconstructed in vtrans)
    mmagemm_k<0,0,1,0,0,1><<<dim3(12,256,1), blk, MMSMEM>>>(hh_, hl_, wh_+WO_IN,
        in_b, nullptr, nullptr, qkvh_, qkvl_, 512, 512, 512, 1536, 0,0,0,0,0,0, 1);

    // v transpose (reads qkv hi/lo) -> vT fp16
    vtrans_k<<<dim3(8,32,64), dim3(32,8)>>>(qkvh_, qkvl_, vth_);

    // G3: scores = q @ k^T (batched z=64), q hi-only (ALO=0), fp16 hi-only output -> g_ah
    mmagemm_k<0,0,1,0,0,0><<<dim3(8,8,64), blk, MMSMEM>>>(qkvh_, nullptr, qkvh_+512,
        nullptr, nullptr, nullptr, ah_, nullptr, 256, 1536, 1536, 1024,
        256, (long)NS*1536, 256, (long)NS*1536, (long)NS*NS, 2L*NS*NS, 2);

    // in-place fp16 softmax (1/16 scale)
    softmax_split_k<<<NB*NHD*NS, 256>>>(ah_);

    // G4: ctx = attn @ vT^T (batched z=64), probs hi-only (ALO=0), split-out
    mmagemm_k<0,0,1,0,0,0><<<dim3(2,8,64), blk, MMSMEM>>>(ah_, nullptr, vth_,
        nullptr, nullptr, nullptr, ctxh_, ctxl_, 1024, 1024, 1024, 512,
        (long)NS*NS, 2L*NS*NS, (long)DHH*NS, 2L*DHH*NS, 256, (long)NS*512, 2);

    // G5: attn_out = ctx @ out_w^T + b -> t1 fp32
    mmagemm_k<0,0,0,1,0,1><<<dim3(4,256,1), blk, MMSMEM>>>(ctxh_, ctxl_, wh_+WO_OUT,
        out_b, nullptr, t1_, nullptr, nullptr, 512, 512, 512, 512, 0,0,0,0,0,0, 1);

    // x1 = LN(h + attn_out), fp32 + split
    addln_k<<<ROWS, 256>>>(h_, t1_, ln1_g, ln1_b, x1_, x1h_, x1l_);

    // G6: mid = relu(x1 @ ffn_w1^T + b1), split only
    mmagemm_k<1,0,1,0,0,1><<<dim3(8,256,1), blk, MMSMEM>>>(x1h_, x1l_, wh_+WO_F1,
        ffn_b1, nullptr, nullptr, midh_, midl_, 512, 512, 512, 1024, 0,0,0,0,0,0, 1);

    // G7: x1 = x1 + mid @ ffn_w2^T + b2 (residual), fp32
    mmagemm_k<0,1,0,1,0,1><<<dim3(4,256,1), blk, MMSMEM>>>(midh_, midl_, wh_+WO_F2,
        ffn_b2, x1_, x1_, nullptr, nullptr, 1024, 1024, 1024, 512, 0,0,0,0,0,0, 1);

    // nrm = rownorm(x1), split only
    rownorm_k<<<ROWS, 256>>>(x1_, nh_, nl_);

    // sim = nrm @ nrm^T (batched z=32) — upper-triangle blocks only (symmetric)
    mmagemm_k<0,0,0,1,1,1><<<dim3(36,1,32), blk, MMSMEM>>>(nh_, nl_, nh_,
        nullptr, nullptr, sc_, nullptr, nullptr, 512, 512, 512, 1024,
        0, (long)NS*512, 0, (long)NS*512, 0, (long)NS*NS, 1);

    // mirror upper -> lower triangle
    mirror_k<<<dim3(28*16, NB), dim3(32,8)>>>(sc_);

    // adjacency (1-bit mask)
    zero_k<<<(int)(((long)NB*NS*32*4/16 + 255)/256), blk>>>((float4*)mskw_, (long)NB*NS*32*4/16);
    topk_k<<<ROWS, 128>>>(sc_, idx_);
    scatter_k<<<(ROWS+255)/256, blk>>>(idx_, mskw_);

    // combined = [x1 | nsum/cnt] -> fp16 hi/lo
    combine_k<<<ROWS, 512>>>(x1_, sc_, mskw_, cbh_, cbl_);

    // G8: gco = combined @ gc_w^T + b -> t1 fp32
    mmagemm_k<0,0,0,1,0,1><<<dim3(4,256,1), blk, MMSMEM>>>(cbh_, cbl_, wh_+WO_GC,
        gc_b, nullptr, t1_, nullptr, nullptr, 1024, 1024, 1024, 512, 0,0,0,0,0,0, 1);

    // x2 = LN(x1 + gco), fp32 only
    addln_k<<<ROWS, 256>>>(x1_, t1_, ln2_g, ln2_b, x2_, nullptr, nullptr);

    // pool (two-stage) + decoder
    pool1_k<<<dim3(NB,8), 512>>>(x2_, poolp_);
    pool2_k<<<NB, 512>>>(poolp_, pool_);
    gemm_k<1,0,0><<<dim3(8,1,1), blk>>>(pool_, dec_w, dec_b, nullptr, out,
        32, 512, 512, 512, 512, 512);
}

// round 15
// speedup vs baseline: 1.2146x; 1.0744x over previous
#include <cuda_runtime.h>
#include <cuda_bf16.h>
#include <cuda_fp16.h>
#include <cstdint>

// Problem constants
#define NB   32
#define NS   1024
#define DIN  512
#define DH   512
#define DOUT 512
#define NHD  2
#define DHH  256
#define ROWS (NB*NS)             // 32768
#define SCSZ (67108864L)         // NB*NHD*NS*NS

// ============================ helpers ============================
__device__ __forceinline__ uint32_t smem_to_u32(const void* p) {
    uint32_t a;
    asm("{ .reg .u64 t; cvta.to.shared.u64 t, %1; cvt.u32.u64 %0, t; }" : "=r"(a) : "l"(p));
    return a;
}
__device__ __forceinline__ void ldsm4(uint32_t* r, uint32_t addr) {
    asm volatile("ldmatrix.sync.aligned.m8n8.x4.shared.b16 {%0,%1,%2,%3}, [%4];"
                 : "=r"(r[0]), "=r"(r[1]), "=r"(r[2]), "=r"(r[3]) : "r"(addr));
}
__device__ __forceinline__ void mma16816(float* d, const uint32_t* a, const uint32_t* b) {
    asm volatile("mma.sync.aligned.m16n8k16.row.col.f32.f16.f16.f32 "
                 "{%0,%1,%2,%3}, {%4,%5,%6,%7}, {%8,%9}, {%0,%1,%2,%3};"
                 : "+f"(d[0]), "+f"(d[1]), "+f"(d[2]), "+f"(d[3])
                 : "r"(a[0]), "r"(a[1]), "r"(a[2]), "r"(a[3]), "r"(b[0]), "r"(b[1]));
}
__device__ __forceinline__ void cpa16(uint32_t s, const void* g) {
    asm volatile("cp.async.cg.shared.global [%0], [%1], 16;" :: "r"(s), "l"(g));
}
__device__ __forceinline__ void cpcommit() { asm volatile("cp.async.commit_group;"); }
template<int N> __device__ __forceinline__ void cpwait() {
    asm volatile("cp.async.wait_group %0;" :: "n"(N));
}

// smem: 3 tiles (Ah, Al, B) of 128 rows x 64B (32 fp16), XOR-swizzled, 4 stages
#define ATILEB 8192               // 128*64
#define STAGEB (3*ATILEB)         // 24576
#define NSTG   4
#define MMSMEM (NSTG*STAGEB)      // 98304
#define SWZ(row, chunk) ((uint32_t)(row)*64u + ((uint32_t)((chunk) ^ (((row)>>1)&3))*16u))

// ============================ scratch buffers ============================
__device__ float g_h   [ROWS*DH];
__device__ float g_sc  [SCSZ];               // sim only
__device__ float g_t1  [ROWS*DH];
__device__ float g_x1  [ROWS*DH];
__device__ float g_x2  [ROWS*DH];
__device__ float g_poolp[NB*8*DH];
__device__ float g_pool[NB*DH];
__device__ int   g_idx [ROWS*4];
__device__ unsigned int g_mskw [(long)NB*NS*32];   // bitmask adjacency, 4MB

__device__ __half g_xh[ROWS*DIN],   g_xl[ROWS*DIN];
__device__ __half g_hh[ROWS*DH];
__device__ __half g_qkvh[ROWS*3*DH];
__device__ __half g_ah[SCSZ];                // scores, then probs (in-place softmax)
__device__ __half g_vth[(long)NB*NHD*DHH*NS];
__device__ __half g_ctxh[ROWS*DH],  g_ctxl[ROWS*DH];
__device__ __half g_x1h[ROWS*DH],   g_x1l[ROWS*DH];
__device__ __half g_midh[ROWS*2*DH],g_midl[ROWS*2*DH];
__device__ __half g_nh[ROWS*DH],    g_nl[ROWS*DH];
__device__ __half g_cbh[ROWS*2*DH], g_cbl[ROWS*2*DH];
__device__ __half g_wh[4*1024*1024];

// weight offsets (elements)
#define WO_ENC 0
#define WO_IN  262144
#define WO_OUT 1048576
#define WO_F1  1310720
#define WO_F2  1835008
#define WO_GC  2359296

// ============================ HMMA GEMM (fp16x2, cp.async 4-stage, 2 CTA/SM) ============
// C[M,N] = act((Ah[+Al]) @ B^T + bias) (+R).  A hi/lo fp16 [M,K] row-major, B fp16 [N,K].
// CTA tile 128x128, warp tile 32x64 (4x2 warps), K chunks of 32, swizzled smem.
// TRIU=1: blockIdx.x in [0,36) remapped to upper-triangle (bx,by), by<=bx (symmetric C).
// ALO=0: skip A-lo stream (half the MMAs).  WSPLIT: Cl==nullptr -> write hi only.
template<int ACT, int RES, int WSPLIT, int WFP32, int TRIU, int ALO>
__global__ void __launch_bounds__(256, 2)
mmagemm_k(const __half* __restrict__ Ah, const __half* __restrict__ Al,
          const __half* __restrict__ Bm,
          const float* __restrict__ bias, const float* __restrict__ Rres,
          float* __restrict__ C, __half* __restrict__ Ch, __half* __restrict__ Cl,
          int K, int lda, int ldb, int ldc,
          long sA1, long sA2, long sB1, long sB2, long sC1, long sC2, int HZ)
{
    extern __shared__ char sm[];
    uint32_t sb = smem_to_u32(sm);

    int tid = threadIdx.x, wid = tid >> 5, lid = tid & 31;
    int wm = wid >> 1, wn = wid & 1;
    int z = blockIdx.z, zb = z / HZ, zh = z - zb * HZ;
    long aoff = (long)zb * sA2 + (long)zh * sA1;
    long boff = (long)zb * sB2 + (long)zh * sB1;
    long coff = (long)zb * sC2 + (long)zh * sC1;

    int bx, by;
    if (TRIU) {
        int p = blockIdx.x;
        by = 0;
        while (p >= 8 - by) { p -= 8 - by; by++; }
        bx = by + p;
    } else {
        bx = blockIdx.x; by = blockIdx.y;
    }
    int m0 = by * 128, n0 = bx * 128;

    const __half* Ahp = Ah + aoff + (long)m0 * lda;
    const __half* Alp = ALO ? (Al + aoff + (long)m0 * lda) : Ahp;
    const __half* Bp  = Bm + boff + (long)n0 * ldb;

    int lrow = tid >> 1, c0 = (tid & 1) * 2;
    const char* pAh = (const char*)(Ahp + (long)lrow * lda) + c0 * 16;
    const char* pAl = (const char*)(Alp + (long)lrow * lda) + c0 * 16;
    const char* pB  = (const char*)(Bp  + (long)lrow * ldb) + c0 * 16;
    uint32_t d0 = SWZ(lrow, c0), d1 = SWZ(lrow, c0 + 1);

#define ISSUE(stg, c) do { long ob = (long)(c) * 64; uint32_t bp = sb + (stg) * STAGEB; \
    cpa16(bp + d0,            pAh + ob); cpa16(bp + d1,            pAh + ob + 16); \
    if (ALO) { cpa16(bp + ATILEB + d0, pAl + ob); cpa16(bp + ATILEB + d1, pAl + ob + 16); } \
    cpa16(bp + 2*ATILEB + d0, pB  + ob); cpa16(bp + 2*ATILEB + d1, pB  + ob + 16); } while (0)

    int arow = wm * 32 + ((lid >> 3) & 1) * 8 + (lid & 7);
    int acsel = (lid >> 4) & 1;
    uint32_t axor = (uint32_t)((arow >> 1) & 3);
    int brow = wn * 64 + ((lid >> 4) & 1) * 8 + (lid & 7);
    int bcsel = (lid >> 3) & 1;
    uint32_t bxor = (uint32_t)((brow >> 1) & 3);

    float d[2][8][4];
#pragma unroll
    for (int i = 0; i < 2; i++)
#pragma unroll
        for (int j = 0; j < 8; j++)
#pragma unroll
            for (int q = 0; q < 4; q++) d[i][j][q] = 0.f;

    const int nCh = K >> 5;
    ISSUE(0, 0); cpcommit();
    ISSUE(1, 1); cpcommit();
    ISSUE(2, 2); cpcommit();

    int stg = 0;
    for (int c = 0; c < nCh; c++) {
        cpwait<2>();
        __syncthreads();
        if (c + 3 < nCh) {
            int ns = stg + 3; if (ns >= NSTG) ns -= NSTG;
            ISSUE(ns, c + 3);
        }
        cpcommit();

        uint32_t cb = sb + stg * STAGEB;
#pragma unroll
        for (int ks = 0; ks < 2; ks++) {
            uint32_t fah[2][4], fal[2][4], fb[4][4];
#pragma unroll
            for (int mf = 0; mf < 2; mf++) {
                uint32_t ad = cb + (uint32_t)(arow + mf * 16) * 64u
                            + (((uint32_t)(ks * 2 + acsel) ^ axor) * 16u);
                ldsm4(fah[mf], ad);
                if (ALO) ldsm4(fal[mf], ad + ATILEB);
            }
#pragma unroll
            for (int np = 0; np < 4; np++) {
                uint32_t bd = cb + 2 * ATILEB + (uint32_t)(brow + np * 16) * 64u
                            + (((uint32_t)(ks * 2 + bcsel) ^ bxor) * 16u);
                ldsm4(fb[np], bd);
            }
#pragma unroll
            for (int mf = 0; mf < 2; mf++)
#pragma unroll
                for (int nf = 0; nf < 8; nf++)
                    mma16816(d[mf][nf], fah[mf], &fb[nf >> 1][(nf & 1) * 2]);
            if (ALO) {
#pragma unroll
                for (int mf = 0; mf < 2; mf++)
#pragma unroll
                    for (int nf = 0; nf < 8; nf++)
                        mma16816(d[mf][nf], fal[mf], &fb[nf >> 1][(nf & 1) * 2]);
            }
        }
        if (++stg >= NSTG) stg = 0;
    }
#undef ISSUE

    int g = lid >> 2, tg = lid & 3;
#pragma unroll
    for (int mf = 0; mf < 2; mf++) {
#pragma unroll
        for (int cp = 0; cp < 2; cp++) {
            int m = m0 + wm * 32 + mf * 16 + cp * 8 + g;
            long rb = (long)m * ldc + coff;
#pragma unroll
            for (int nf = 0; nf < 8; nf++) {
                int n = n0 + wn * 64 + nf * 8 + tg * 2;
                float v0 = d[mf][nf][cp * 2];
                float v1 = d[mf][nf][cp * 2 + 1];
                if (bias) { v0 += bias[n]; v1 += bias[n + 1]; }
                if (ACT) { v0 = fmaxf(v0, 0.f); v1 = fmaxf(v1, 0.f); }
                if (RES) { v0 += Rres[rb + n]; v1 += Rres[rb + n + 1]; }
                if (WFP32)
                    *reinterpret_cast<float2*>(C + rb + n) = make_float2(v0, v1);
                if (WSPLIT) {
                    __half h0 = __float2half_rn(v0);
                    __half h1 = __float2half_rn(v1);
                    __half2 hh; hh.x = h0; hh.y = h1;
                    *reinterpret_cast<__half2*>(Ch + rb + n) = hh;
                    if (Cl) {
                        __half2 ll;
                        ll.x = __float2half_rn(v0 - __half2float(h0));
                        ll.y = __float2half_rn(v1 - __half2float(h1));
                        *reinterpret_cast<__half2*>(Cl + rb + n) = ll;
                    }
                }
            }
        }
    }
}

// mirror upper-triangle 128-blocks of symmetric sim into lower triangle
__global__ void mirror_k(float* __restrict__ sc)
{
    int b = blockIdx.y;
    int p = blockIdx.x;               // [0, 28*16)
    int pair = p >> 4, t = p & 15;
    int BI = 1, acc = 0;
    while (pair >= acc + BI) { acc += BI; BI++; }
    int BJ = pair - acc;              // BI in 1..7, BJ < BI
    int tr = t >> 2, tc = t & 3;
    int r0 = BI * 128 + tr * 32;
    int c0 = BJ * 128 + tc * 32;
    long base = (long)b * NS * NS;
    __shared__ float tile[32][33];
    int tx = threadIdx.x, ty = threadIdx.y;   // (32, 8)
#pragma unroll
    for (int i = 0; i < 4; i++)
        tile[ty + i * 8][tx] = sc[base + (long)(c0 + ty + i * 8) * NS + r0 + tx];
    __syncthreads();
#pragma unroll
    for (int i = 0; i < 4; i++)
        sc[base + (long)(r0 + ty + i * 8) * NS + c0 + tx] = tile[tx][ty + i * 8];
}

// ============================ SIMT GEMM (small final only) ============================
template<int TB, int ACT, int RES>
__global__ void gemm_k(const float* __restrict__ A, const float* __restrict__ Bm,
                       const float* __restrict__ bias, const float* __restrict__ R,
                       float* __restrict__ C,
                       int M, int N, int K, int lda, int ldb, int ldc)
{
    __shared__ float As[16][65];
    __shared__ float Bs[16][65];
    int tid = threadIdx.x;
    int tx = tid & 15, ty = tid >> 4;
    int m0 = blockIdx.y * 64, n0 = blockIdx.x * 64;
    float acc[4][4];
#pragma unroll
    for (int i = 0; i < 4; i++)
#pragma unroll
        for (int j = 0; j < 4; j++) acc[i][j] = 0.f;

    for (int k0 = 0; k0 < K; k0 += 16) {
#pragma unroll
        for (int i = 0; i < 4; i++) {
            int idx = tid + i * 256;
            int r = idx >> 4, kk = idx & 15;
            int m = m0 + r;
            As[kk][r] = (m < M) ? A[(long)m * lda + (k0 + kk)] : 0.f;
        }
#pragma unroll
        for (int i = 0; i < 4; i++) {
            int idx = tid + i * 256;
            int r = idx >> 4, kk = idx & 15;
            Bs[kk][r] = Bm[(long)(n0 + r) * ldb + (k0 + kk)];
        }
        __syncthreads();
#pragma unroll
        for (int kk = 0; kk < 16; kk++) {
            float a[4], b[4];
#pragma unroll
            for (int i = 0; i < 4; i++) a[i] = As[kk][ty + 16 * i];
#pragma unroll
            for (int j = 0; j < 4; j++) b[j] = Bs[kk][tx + 16 * j];
#pragma unroll
            for (int i = 0; i < 4; i++)
#pragma unroll
                for (int j = 0; j < 4; j++) acc[i][j] += a[i] * b[j];
        }
        __syncthreads();
    }
#pragma unroll
    for (int i = 0; i < 4; i++) {
        int m = m0 + ty + 16 * i;
        if (m >= M) continue;
#pragma unroll
        for (int j = 0; j < 4; j++) {
            int n = n0 + tx + 16 * j;
            float v = acc[i][j];
            if (bias) v += bias[n];
            if (ACT) v = fmaxf(v, 0.f);
            C[(long)m * ldc + n] = v;
        }
    }
}

// ============================ elementwise / reduction kernels ============================
__device__ __forceinline__ void split4_store(float4 v, __half* h, __half* l, long i)
{
    __half2 h0, h1, l0, l1;
    h0.x = __float2half_rn(v.x); h0.y = __float2half_rn(v.y);
    h1.x = __float2half_rn(v.z); h1.y = __float2half_rn(v.w);
    l0.x = __float2half_rn(v.x - __half2float(h0.x));
    l0.y = __float2half_rn(v.y - __half2float(h0.y));
    l1.x = __float2half_rn(v.z - __half2float(h1.x));
    l1.y = __float2half_rn(v.w - __half2float(h1.y));
    reinterpret_cast<__half2*>(h)[2 * i] = h0;
    reinterpret_cast<__half2*>(h)[2 * i + 1] = h1;
    reinterpret_cast<__half2*>(l)[2 * i] = l0;
    reinterpret_cast<__half2*>(l)[2 * i + 1] = l1;
}

__global__ void split_k(const float* __restrict__ s, __half* __restrict__ h,
                        __half* __restrict__ l, long n4)
{
    long i = (long)blockIdx.x * blockDim.x + threadIdx.x;
    if (i >= n4) return;
    split4_store(reinterpret_cast<const float4*>(s)[i], h, l, i);
}

__global__ void wsplit_k(const float* __restrict__ w0, const float* __restrict__ w1,
                         const float* __restrict__ w2, const float* __restrict__ w3,
                         const float* __restrict__ w4, const float* __restrict__ w5,
                         __half* __restrict__ h)
{
    long i = (long)blockIdx.x * blockDim.x + threadIdx.x;
    const float* src; long base;
    if      (i < 65536)  { src = w0; base = 0;      }
    else if (i < 262144) { src = w1; base = 65536;  }
    else if (i < 327680) { src = w2; base = 262144; }
    else if (i < 458752) { src = w3; base = 327680; }
    else if (i < 589824) { src = w4; base = 458752; }
    else if (i < 720896) { src = w5; base = 589824; }
    else return;
    float4 v = reinterpret_cast<const float4*>(src)[i - base];
    __half2 h0, h1;
    h0.x = __float2half_rn(v.x); h0.y = __float2half_rn(v.y);
    h1.x = __float2half_rn(v.z); h1.y = __float2half_rn(v.w);
    reinterpret_cast<__half2*>(h)[2 * i] = h0;
    reinterpret_cast<__half2*>(h)[2 * i + 1] = h1;
}

// transpose v from qkv hi: vT[z][d][k] = qh[b, k, 1024 + h*256 + d]
__global__ void vtrans_k(const __half* __restrict__ qh, __half* __restrict__ vth)
{
    int z = blockIdx.z, zb = z >> 1, zh = z & 1;
    int d0 = blockIdx.x * 32, k0 = blockIdx.y * 32;
    __shared__ __half t[32][34];
    int tx = threadIdx.x, ty = threadIdx.y;
    long base = (long)zb * NS * 1536 + 1024 + zh * 256;
#pragma unroll
    for (int i = 0; i < 4; i++) {
        int k = k0 + ty + i * 8;
        t[ty + i * 8][tx] = qh[base + (long)k * 1536 + d0 + tx];
    }
    __syncthreads();
    __half* oh = vth + (long)z * DHH * NS;
#pragma unroll
    for (int i = 0; i < 4; i++) {
        int d = d0 + ty + i * 8;
        oh[(long)d * NS + k0 + tx] = t[tx][ty + i * 8];
    }
}

// in-place softmax over fp16 score rows (1/16 scale); writes fp16 probs
__global__ void softmax_split_k(__half* __restrict__ sp)
{
    long row = blockIdx.x;
    __half* p = sp + row * 1024;
    int t = threadIdx.x;              // 256
    uint2 raw = *reinterpret_cast<const uint2*>(p + t * 4);
    __half2 h01 = *reinterpret_cast<__half2*>(&raw.x);
    __half2 h23 = *reinterpret_cast<__half2*>(&raw.y);
    float v[4] = { __half2float(h01.x) * 0.0625f, __half2float(h01.y) * 0.0625f,
                   __half2float(h23.x) * 0.0625f, __half2float(h23.y) * 0.0625f };
    float mx = fmaxf(fmaxf(v[0], v[1]), fmaxf(v[2], v[3]));
    __shared__ float red[256];
    red[t] = mx; __syncthreads();
    for (int o = 128; o > 0; o >>= 1) { if (t < o) red[t] = fmaxf(red[t], red[t + o]); __syncthreads(); }
    mx = red[0]; __syncthreads();
    float sum = 0.f;
#pragma unroll
    for (int i = 0; i < 4; i++) { v[i] = __expf(v[i] - mx); sum += v[i]; }
    red[t] = sum; __syncthreads();
    for (int o = 128; o > 0; o >>= 1) { if (t < o) red[t] += red[t + o]; __syncthreads(); }
    float inv = 1.f / red[0];
    __half2 o01, o23;
    o01.x = __float2half_rn(v[0] * inv); o01.y = __float2half_rn(v[1] * inv);
    o23.x = __float2half_rn(v[2] * inv); o23.y = __float2half_rn(v[3] * inv);
    uint2 ow;
    ow.x = *reinterpret_cast<uint32_t*>(&o01);
    ow.y = *reinterpret_cast<uint32_t*>(&o23);
    *reinterpret_cast<uint2*>(p + t * 4) = ow;
}

__global__ void addln_k(const float* __restrict__ a, const float* __restrict__ r,
                        const float* __restrict__ g, const float* __restrict__ be,
                        float* __restrict__ o, __half* __restrict__ oh,
                        __half* __restrict__ ol)
{
    long row = blockIdx.x;
    int t = threadIdx.x;
    long base = row * 512;
    float v0 = a[base + t]       + r[base + t];
    float v1 = a[base + t + 256] + r[base + t + 256];
    __shared__ float rs[256], rq[256];
    rs[t] = v0 + v1; rq[t] = v0 * v0 + v1 * v1;
    __syncthreads();
    for (int off = 128; off > 0; off >>= 1) {
        if (t < off) { rs[t] += rs[t + off]; rq[t] += rq[t + off]; }
        __syncthreads();
    }
    float mu  = rs[0] * (1.f / 512.f);
    float var = rq[0] * (1.f / 512.f) - mu * mu;
    float inv = rsqrtf(var + 1e-5f);
    float o0 = (v0 - mu) * inv * g[t]       + be[t];
    float o1 = (v1 - mu) * inv * g[t + 256] + be[t + 256];
    o[base + t] = o0; o[base + t + 256] = o1;
    if (oh) {
        __half h0 = __float2half_rn(o0), h1 = __float2half_rn(o1);
        oh[base + t] = h0; oh[base + t + 256] = h1;
        ol[base + t]       = __float2half_rn(o0 - __half2float(h0));
        ol[base + t + 256] = __float2half_rn(o1 - __half2float(h1));
    }
}

__global__ void rownorm_k(const float* __restrict__ x, __half* __restrict__ nh,
                          __half* __restrict__ nl)
{
    long row = blockIdx.x;
    int t = threadIdx.x;
    long base = row * 512;
    float v0 = x[base + t], v1 = x[base + t + 256];
    __shared__ float rq[256];
    rq[t] = v0 * v0 + v1 * v1;
    __syncthreads();
    for (int off = 128; off > 0; off >>= 1) {
        if (t < off) rq[t] += rq[t + off];
        __syncthreads();
    }
    float s = 1.f / fmaxf(sqrtf(rq[0]), 1e-12f);
    float o0 = v0 * s, o1 = v1 * s;
    __half h0 = __float2half_rn(o0), h1 = __float2half_rn(o1);
    nh[base + t] = h0; nh[base + t + 256] = h1;
    nl[base + t]       = __float2half_rn(o0 - __half2float(h0));
    nl[base + t + 256] = __float2half_rn(o1 - __half2float(h1));
}

// single-pass exact top-4 per row (comparator: value desc, index asc — jax tie rule)
__global__ void topk_k(const float* __restrict__ sim, int* __restrict__ idxo)
{
    int row = blockIdx.x;
    const float* p = sim + (long)row * 1024;
    int t = threadIdx.x;              // 128
    float v[4] = {-1e30f, -1e30f, -1e30f, -1e30f};
    int   ix[4] = {1 << 30, 1 << 30, 1 << 30, 1 << 30};
#pragma unroll
    for (int r = 0; r < 8; r++) {
        int j = t + r * 128;
        float val = p[j];
        if (val > v[3] || (val == v[3] && j < ix[3])) {
            v[3] = val; ix[3] = j;
#pragma unroll
            for (int q = 3; q > 0; q--) {
                bool up = v[q] > v[q-1] || (v[q] == v[q-1] && ix[q] < ix[q-1]);
                if (up) {
                    float tv = v[q]; v[q] = v[q-1]; v[q-1] = tv;
                    int ti = ix[q]; ix[q] = ix[q-1]; ix[q-1] = ti;
                }
            }
        }
    }
    __shared__ float sv[128][4];
    __shared__ int   si[128][4];
#pragma unroll
    for (int q = 0; q < 4; q++) { sv[t][q] = v[q]; si[t][q] = ix[q]; }
    __syncthreads();
    for (int off = 64; off > 0; off >>= 1) {
        if (t < off) {
            float mv[4]; int mi[4];
            int a = 0, b = 0;
#pragma unroll
            for (int q = 0; q < 4; q++) {
                float av = sv[t][a], bv = sv[t + off][b];
                int   ai = si[t][a], bi = si[t + off][b];
                bool ta = av > bv || (av == bv && ai < bi);
                if (ta) { mv[q] = av; mi[q] = ai; a++; }
                else    { mv[q] = bv; mi[q] = bi; b++; }
            }
#pragma unroll
            for (int q = 0; q < 4; q++) { sv[t][q] = mv[q]; si[t][q] = mi[q]; }
        }
        __syncthreads();
    }
    if (t < 4) idxo[row * 4 + t] = si[0][t];
}

__global__ void zero_k(float4* __restrict__ p, long n)
{
    long i = (long)blockIdx.x * blockDim.x + threadIdx.x;
    if (i < n) p[i] = make_float4(0.f, 0.f, 0.f, 0.f);
}

__global__ void scatter_k(const int* __restrict__ idx, unsigned int* __restrict__ mskw)
{
    int rr = blockIdx.x * blockDim.x + threadIdx.x;
    if (rr >= ROWS) return;
    int b = rr >> 10, i = rr & 1023;
    unsigned int* mb = mskw + (long)b * NS * 32;
#pragma unroll
    for (int t = 0; t < 4; t++) {
        int j = idx[rr * 4 + t];
        if (j != i) {
            atomicOr(&mb[i * 32 + (j >> 5)], 1u << (j & 31));
            atomicOr(&mb[j * 32 + (i >> 5)], 1u << (i & 31));
        }
    }
}

__global__ void combine_k(const float* __restrict__ x1, const float* __restrict__ sim,
                          const unsigned int* __restrict__ mskw,
                          __half* __restrict__ ch, __half* __restrict__ cl)
{
    int rr = blockIdx.x;
    int b = rr >> 10, i = rr & 1023;
    int d = threadIdx.x;              // 512
    __shared__ unsigned int smk[32];
    if (d < 32) smk[d] = mskw[(long)b * NS * 32 + i * 32 + d];
    __syncthreads();
    const float* srow = sim + (long)rr * 1024;
    float acc = 0.f, cnt = 0.f;
#pragma unroll 4
    for (int w = 0; w < 32; w++) {
        unsigned int m = smk[w];
        while (m) {
            int bi = __ffs(m) - 1;
            m &= m - 1;
            int j = w * 32 + bi;
            float wgt = srow[j];
            acc += wgt * x1[((long)(b * NS + j)) * 512 + d];
            cnt += wgt;
        }
    }
    float xv = x1[(long)rr * 512 + d];
    float nv = acc / fmaxf(cnt, 1.0f);
    __half hx = __float2half_rn(xv), hn = __float2half_rn(nv);
    long ob = (long)rr * 1024;
    ch[ob + d] = hx;       cl[ob + d]       = __float2half_rn(xv - __half2float(hx));
    ch[ob + 512 + d] = hn; cl[ob + 512 + d] = __float2half_rn(nv - __half2float(hn));
}

__global__ void pool1_k(const float* __restrict__ x2, float* __restrict__ part)
{
    int b = blockIdx.x, chunk = blockIdx.y;
    int d = threadIdx.x;
    const float* src = x2 + ((long)b * NS + chunk * 128) * 512;
    float s = 0.f;
#pragma unroll 8
    for (int sdx = 0; sdx < 128; sdx++)
        s += src[(long)sdx * 512 + d];
    part[((long)b * 8 + chunk) * 512 + d] = s;
}

__global__ void pool2_k(const float* __restrict__ part, float* __restrict__ pool)
{
    int b = blockIdx.x;
    int d = threadIdx.x;
    float s = 0.f;
#pragma unroll
    for (int c = 0; c < 8; c++)
        s += part[((long)b * 8 + c) * 512 + d];
    pool[b * 512 + d] = s * (1.f / 1024.f);
}

// =================================================================================
extern "C" void kernel_launch(void* const* d_in, const int* in_sizes, int n_in,
                              void* d_out, int out_size)
{
    const float* x      = (const float*)d_in[0];
    const float* enc_w  = (const float*)d_in[1];
    const float* enc_b  = (const float*)d_in[2];
    const float* in_w   = (const float*)d_in[3];
    const float* in_b   = (const float*)d_in[4];
    const float* out_w  = (const float*)d_in[5];
    const float* out_b  = (const float*)d_in[6];
    const float* ln1_g  = (const float*)d_in[7];
    const float* ln1_b  = (const float*)d_in[8];
    const float* ffn_w1 = (const float*)d_in[9];
    const float* ffn_b1 = (const float*)d_in[10];
    const float* ffn_w2 = (const float*)d_in[11];
    const float* ffn_b2 = (const float*)d_in[12];
    const float* gc_w   = (const float*)d_in[13];
    const float* gc_b   = (const float*)d_in[14];
    const float* ln2_g  = (const float*)d_in[15];
    const float* ln2_b  = (const float*)d_in[16];
    const float* dec_w  = (const float*)d_in[17];
    const float* dec_b  = (const float*)d_in[18];
    float* out = (float*)d_out;

    float *h_, *sc_, *t1_, *x1_, *x2_, *poolp_, *pool_;
    int* idx_;
    unsigned int* mskw_;
    __half *xh_, *xl_, *hh_, *qkvh_, *ah_, *vth_;
    __half *ctxh_, *ctxl_, *x1h_, *x1l_, *midh_, *midl_, *nh_, *nl_, *cbh_, *cbl_, *wh_;
    cudaGetSymbolAddress((void**)&h_,    g_h);
    cudaGetSymbolAddress((void**)&sc_,   g_sc);
    cudaGetSymbolAddress((void**)&t1_,   g_t1);
    cudaGetSymbolAddress((void**)&x1_,   g_x1);
    cudaGetSymbolAddress((void**)&x2_,   g_x2);
    cudaGetSymbolAddress((void**)&poolp_,g_poolp);
    cudaGetSymbolAddress((void**)&pool_, g_pool);
    cudaGetSymbolAddress((void**)&idx_,  g_idx);
    cudaGetSymbolAddress((void**)&mskw_, g_mskw);
    cudaGetSymbolAddress((void**)&xh_,   g_xh);   cudaGetSymbolAddress((void**)&xl_,   g_xl);
    cudaGetSymbolAddress((void**)&hh_,   g_hh);
    cudaGetSymbolAddress((void**)&qkvh_, g_qkvh);
    cudaGetSymbolAddress((void**)&ah_,   g_ah);
    cudaGetSymbolAddress((void**)&vth_,  g_vth);
    cudaGetSymbolAddress((void**)&ctxh_, g_ctxh); cudaGetSymbolAddress((void**)&ctxl_, g_ctxl);
    cudaGetSymbolAddress((void**)&x1h_,  g_x1h);  cudaGetSymbolAddress((void**)&x1l_,  g_x1l);
    cudaGetSymbolAddress((void**)&midh_, g_midh); cudaGetSymbolAddress((void**)&midl_, g_midl);
    cudaGetSymbolAddress((void**)&nh_,   g_nh);   cudaGetSymbolAddress((void**)&nl_,   g_nl);
    cudaGetSymbolAddress((void**)&cbh_,  g_cbh);  cudaGetSymbolAddress((void**)&cbl_,  g_cbl);
    cudaGetSymbolAddress((void**)&wh_,   g_wh);

    cudaFuncSetAttribute(mmagemm_k<1,0,1,1,0,1>, cudaFuncAttributeMaxDynamicSharedMemorySize, MMSMEM);
    cudaFuncSetAttribute(mmagemm_k<0,0,0,1,0,1>, cudaFuncAttributeMaxDynamicSharedMemorySize, MMSMEM);
    cudaFuncSetAttribute(mmagemm_k<0,0,0,1,1,1>, cudaFuncAttributeMaxDynamicSharedMemorySize, MMSMEM);
    cudaFuncSetAttribute(mmagemm_k<0,0,1,0,0,1>, cudaFuncAttributeMaxDynamicSharedMemorySize, MMSMEM);
    cudaFuncSetAttribute(mmagemm_k<0,0,1,0,0,0>, cudaFuncAttributeMaxDynamicSharedMemorySize, MMSMEM);
    cudaFuncSetAttribute(mmagemm_k<1,0,1,0,0,1>, cudaFuncAttributeMaxDynamicSharedMemorySize, MMSMEM);
    cudaFuncSetAttribute(mmagemm_k<0,1,0,1,0,1>, cudaFuncAttributeMaxDynamicSharedMemorySize, MMSMEM);

    dim3 blk(256);

    // input split + fused weight conversion
    split_k<<<(ROWS*DIN/4 + 255)/256, blk>>>(x, xh_, xl_, (long)ROWS*DIN/4);
    wsplit_k<<<(720896 + 255)/256, blk>>>(enc_w, in_w, out_w, ffn_w1, ffn_w2, gc_w, wh_);

    // G1: h = relu(x @ enc_w^T + b), fp32 + fp16 hi (lo no longer consumed)
    mmagemm_k<1,0,1,1,0,1><<<dim3(4,256,1), blk, MMSMEM>>>(xh_, xl_, wh_+WO_ENC,
        enc_b, nullptr, h_, hh_, nullptr, 512, 512, 512, 512, 0,0,0,0,0,0, 1);

    // G2: qkv = h @ in_w^T + b, h hi-only (ALO=0), fp16 hi output only
    mmagemm_k<0,0,1,0,0,0><<<dim3(12,256,1), blk, MMSMEM>>>(hh_, nullptr, wh_+WO_IN,
        in_b, nullptr, nullptr, qkvh_, nullptr, 512, 512, 512, 1536, 0,0,0,0,0,0, 1);

    // v transpose (reads qkv hi) -> vT fp16
    vtrans_k<<<dim3(8,32,64), dim3(32,8)>>>(qkvh_, vth_);

    // G3: scores = q @ k^T (batched z=64), q hi-only (ALO=0), fp16 hi output -> g_ah
    mmagemm_k<0,0,1,0,0,0><<<dim3(8,8,64), blk, MMSMEM>>>(qkvh_, nullptr, qkvh_+512,
        nullptr, nullptr, nullptr, ah_, nullptr, 256, 1536, 1536, 1024,
        256, (long)NS*1536, 256, (long)NS*1536, (long)NS*NS, 2L*NS*NS, 2);

    // in-place fp16 softmax (1/16 scale)
    softmax_split_k<<<NB*NHD*NS, 256>>>(ah_);

    // G4: ctx = attn @ vT^T (batched z=64), probs hi-only (ALO=0), split-out
    mmagemm_k<0,0,1,0,0,0><<<dim3(2,8,64), blk, MMSMEM>>>(ah_, nullptr, vth_,
        nullptr, nullptr, nullptr, ctxh_, ctxl_, 1024, 1024, 1024, 512,
        (long)NS*NS, 2L*NS*NS, (long)DHH*NS, 2L*DHH*NS, 256, (long)NS*512, 2);

    // G5: attn_out = ctx @ out_w^T + b -> t1 fp32
    mmagemm_k<0,0,0,1,0,1><<<dim3(4,256,1), blk, MMSMEM>>>(ctxh_, ctxl_, wh_+WO_OUT,
        out_b, nullptr, t1_, nullptr, nullptr, 512, 512, 512, 512, 0,0,0,0,0,0, 1);

    // x1 = LN(h + attn_out), fp32 + split
    addln_k<<<ROWS, 256>>>(h_, t1_, ln1_g, ln1_b, x1_, x1h_, x1l_);

    // G6: mid = relu(x1 @ ffn_w1^T + b1), split only
    mmagemm_k<1,0,1,0,0,1><<<dim3(8,256,1), blk, MMSMEM>>>(x1h_, x1l_, wh_+WO_F1,
        ffn_b1, nullptr, nullptr, midh_, midl_, 512, 512, 512, 1024, 0,0,0,0,0,0, 1);

    // G7: x1 = x1 + mid @ ffn_w2^T + b2 (residual), fp32
    mmagemm_k<0,1,0,1,0,1><<<dim3(4,256,1), blk, MMSMEM>>>(midh_, midl_, wh_+WO_F2,
        ffn_b2, x1_, x1_, nullptr, nullptr, 1024, 1024, 1024, 512, 0,0,0,0,0,0, 1);

    // nrm = rownorm(x1), split only
    rownorm_k<<<ROWS, 256>>>(x1_, nh_, nl_);

    // sim = nrm @ nrm^T (batched z=32) — upper-triangle blocks only (symmetric)
    mmagemm_k<0,0,0,1,1,1><<<dim3(36,1,32), blk, MMSMEM>>>(nh_, nl_, nh_,
        nullptr, nullptr, sc_, nullptr, nullptr, 512, 512, 512, 1024,
        0, (long)NS*512, 0, (long)NS*512, 0, (long)NS*NS, 1);

    // mirror upper -> lower triangle
    mirror_k<<<dim3(28*16, NB), dim3(32,8)>>>(sc_);

    // adjacency (1-bit mask)
    zero_k<<<(int)(((long)NB*NS*32*4/16 + 255)/256), blk>>>((float4*)mskw_, (long)NB*NS*32*4/16);
    topk_k<<<ROWS, 128>>>(sc_, idx_);
    scatter_k<<<(ROWS+255)/256, blk>>>(idx_, mskw_);

    // combined = [x1 | nsum/cnt] -> fp16 hi/lo
    combine_k<<<ROWS, 512>>>(x1_, sc_, mskw_, cbh_, cbl_);

    // G8: gco = combined @ gc_w^T + b -> t1 fp32
    mmagemm_k<0,0,0,1,0,1><<<dim3(4,256,1), blk, MMSMEM>>>(cbh_, cbl_, wh_+WO_GC,
        gc_b, nullptr, t1_, nullptr, nullptr, 1024, 1024, 1024, 512, 0,0,0,0,0,0, 1);

    // x2 = LN(x1 + gco), fp32 only
    addln_k<<<ROWS, 256>>>(x1_, t1_, ln2_g, ln2_b, x2_, nullptr, nullptr);

    // pool (two-stage) + decoder
    pool1_k<<<dim3(NB,8), 512>>>(x2_, poolp_);
    pool2_k<<<NB, 512>>>(poolp_, pool_);
    gemm_k<1,0,0><<<dim3(8,1,1), blk>>>(pool_, dec_w, dec_b, nullptr, out,
        32, 512, 512, 512, 512, 512);
}

// round 16
// speedup vs baseline: 1.4117x; 1.1623x over previous
#include <cuda_runtime.h>
#include <cuda_bf16.h>
#include <cuda_fp16.h>
#include <cstdint>

// Problem constants
#define NB   32
#define NS   1024
#define DIN  512
#define DH   512
#define DOUT 512
#define NHD  2
#define DHH  256
#define ROWS (NB*NS)             // 32768
#define SCSZ (67108864L)         // NB*NHD*NS*NS

// ============================ helpers ============================
__device__ __forceinline__ uint32_t smem_to_u32(const void* p) {
    uint32_t a;
    asm("{ .reg .u64 t; cvta.to.shared.u64 t, %1; cvt.u32.u64 %0, t; }" : "=r"(a) : "l"(p));
    return a;
}
__device__ __forceinline__ void ldsm4(uint32_t* r, uint32_t addr) {
    asm volatile("ldmatrix.sync.aligned.m8n8.x4.shared.b16 {%0,%1,%2,%3}, [%4];"
                 : "=r"(r[0]), "=r"(r[1]), "=r"(r[2]), "=r"(r[3]) : "r"(addr));
}
__device__ __forceinline__ void mma16816(float* d, const uint32_t* a, const uint32_t* b) {
    asm volatile("mma.sync.aligned.m16n8k16.row.col.f32.f16.f16.f32 "
                 "{%0,%1,%2,%3}, {%4,%5,%6,%7}, {%8,%9}, {%0,%1,%2,%3};"
                 : "+f"(d[0]), "+f"(d[1]), "+f"(d[2]), "+f"(d[3])
                 : "r"(a[0]), "r"(a[1]), "r"(a[2]), "r"(a[3]), "r"(b[0]), "r"(b[1]));
}
__device__ __forceinline__ void cpa16(uint32_t s, const void* g) {
    asm volatile("cp.async.cg.shared.global [%0], [%1], 16;" :: "r"(s), "l"(g));
}
__device__ __forceinline__ void cpcommit() { asm volatile("cp.async.commit_group;"); }
template<int N> __device__ __forceinline__ void cpwait() {
    asm volatile("cp.async.wait_group %0;" :: "n"(N));
}

// smem: 3 tiles (Ah, Al, B) of 128 rows x 64B (32 fp16), XOR-swizzled, 4 stages
#define ATILEB 8192               // 128*64
#define STAGEB (3*ATILEB)         // 24576
#define NSTG   4
#define MMSMEM (NSTG*STAGEB)      // 98304
#define SWZ(row, chunk) ((uint32_t)(row)*64u + ((uint32_t)((chunk) ^ (((row)>>1)&3))*16u))

// ============================ scratch buffers ============================
__device__ float g_h   [ROWS*DH];
__device__ float g_sc  [SCSZ];               // sim only
__device__ float g_t1  [ROWS*DH];
__device__ float g_x1  [ROWS*DH];
__device__ float g_x2  [ROWS*DH];
__device__ float g_poolp[NB*8*DH];
__device__ float g_pool[NB*DH];
__device__ int   g_idx [ROWS*4];
__device__ unsigned int g_mskw [(long)NB*NS*32];   // bitmask adjacency, 4MB

__device__ __half g_xh[ROWS*DIN],   g_xl[ROWS*DIN];
__device__ __half g_hh[ROWS*DH];
__device__ __half g_qkvh[ROWS*3*DH];
__device__ __half g_ah[SCSZ];                // scores, then probs (in-place softmax)
__device__ __half g_vth[(long)NB*NHD*DHH*NS];
__device__ __half g_ctxh[ROWS*DH];
__device__ __half g_x1h[ROWS*DH];
__device__ __half g_midh[ROWS*2*DH];
__device__ __half g_nh[ROWS*DH],    g_nl[ROWS*DH];
__device__ __half g_cbh[ROWS*2*DH];
__device__ __half g_wh[4*1024*1024];

// weight offsets (elements)
#define WO_ENC 0
#define WO_IN  262144
#define WO_OUT 1048576
#define WO_F1  1310720
#define WO_F2  1835008
#define WO_GC  2359296

// ============================ HMMA GEMM (fp16x2, cp.async 4-stage, 2 CTA/SM) ============
// C[M,N] = act((Ah[+Al]) @ B^T + bias) (+R).  A hi/lo fp16 [M,K] row-major, B fp16 [N,K].
// CTA tile 128x128, warp tile 32x64 (4x2 warps), K chunks of 32, swizzled smem.
// TRIU=1: blockIdx.x in [0,36) remapped to upper-triangle (bx,by), by<=bx (symmetric C).
// ALO=0: skip A-lo stream (half the MMAs).  WSPLIT: Cl==nullptr -> write hi only.
template<int ACT, int RES, int WSPLIT, int WFP32, int TRIU, int ALO>
__global__ void __launch_bounds__(256, 2)
mmagemm_k(const __half* __restrict__ Ah, const __half* __restrict__ Al,
          const __half* __restrict__ Bm,
          const float* __restrict__ bias, const float* __restrict__ Rres,
          float* __restrict__ C, __half* __restrict__ Ch, __half* __restrict__ Cl,
          int K, int lda, int ldb, int ldc,
          long sA1, long sA2, long sB1, long sB2, long sC1, long sC2, int HZ)
{
    extern __shared__ char sm[];
    uint32_t sb = smem_to_u32(sm);

    int tid = threadIdx.x, wid = tid >> 5, lid = tid & 31;
    int wm = wid >> 1, wn = wid & 1;
    int z = blockIdx.z, zb = z / HZ, zh = z - zb * HZ;
    long aoff = (long)zb * sA2 + (long)zh * sA1;
    long boff = (long)zb * sB2 + (long)zh * sB1;
    long coff = (long)zb * sC2 + (long)zh * sC1;

    int bx, by;
    if (TRIU) {
        int p = blockIdx.x;
        by = 0;
        while (p >= 8 - by) { p -= 8 - by; by++; }
        bx = by + p;
    } else {
        bx = blockIdx.x; by = blockIdx.y;
    }
    int m0 = by * 128, n0 = bx * 128;

    const __half* Ahp = Ah + aoff + (long)m0 * lda;
    const __half* Alp = ALO ? (Al + aoff + (long)m0 * lda) : Ahp;
    const __half* Bp  = Bm + boff + (long)n0 * ldb;

    int lrow = tid >> 1, c0 = (tid & 1) * 2;
    const char* pAh = (const char*)(Ahp + (long)lrow * lda) + c0 * 16;
    const char* pAl = (const char*)(Alp + (long)lrow * lda) + c0 * 16;
    const char* pB  = (const char*)(Bp  + (long)lrow * ldb) + c0 * 16;
    uint32_t d0 = SWZ(lrow, c0), d1 = SWZ(lrow, c0 + 1);

#define ISSUE(stg, c) do { long ob = (long)(c) * 64; uint32_t bp = sb + (stg) * STAGEB; \
    cpa16(bp + d0,            pAh + ob); cpa16(bp + d1,            pAh + ob + 16); \
    if (ALO) { cpa16(bp + ATILEB + d0, pAl + ob); cpa16(bp + ATILEB + d1, pAl + ob + 16); } \
    cpa16(bp + 2*ATILEB + d0, pB  + ob); cpa16(bp + 2*ATILEB + d1, pB  + ob + 16); } while (0)

    int arow = wm * 32 + ((lid >> 3) & 1) * 8 + (lid & 7);
    int acsel = (lid >> 4) & 1;
    uint32_t axor = (uint32_t)((arow >> 1) & 3);
    int brow = wn * 64 + ((lid >> 4) & 1) * 8 + (lid & 7);
    int bcsel = (lid >> 3) & 1;
    uint32_t bxor = (uint32_t)((brow >> 1) & 3);

    float d[2][8][4];
#pragma unroll
    for (int i = 0; i < 2; i++)
#pragma unroll
        for (int j = 0; j < 8; j++)
#pragma unroll
            for (int q = 0; q < 4; q++) d[i][j][q] = 0.f;

    const int nCh = K >> 5;
    ISSUE(0, 0); cpcommit();
    ISSUE(1, 1); cpcommit();
    ISSUE(2, 2); cpcommit();

    int stg = 0;
    for (int c = 0; c < nCh; c++) {
        cpwait<2>();
        __syncthreads();
        if (c + 3 < nCh) {
            int ns = stg + 3; if (ns >= NSTG) ns -= NSTG;
            ISSUE(ns, c + 3);
        }
        cpcommit();

        uint32_t cb = sb + stg * STAGEB;
#pragma unroll
        for (int ks = 0; ks < 2; ks++) {
            uint32_t fah[2][4], fal[2][4], fb[4][4];
#pragma unroll
            for (int mf = 0; mf < 2; mf++) {
                uint32_t ad = cb + (uint32_t)(arow + mf * 16) * 64u
                            + (((uint32_t)(ks * 2 + acsel) ^ axor) * 16u);
                ldsm4(fah[mf], ad);
                if (ALO) ldsm4(fal[mf], ad + ATILEB);
            }
#pragma unroll
            for (int np = 0; np < 4; np++) {
                uint32_t bd = cb + 2 * ATILEB + (uint32_t)(brow + np * 16) * 64u
                            + (((uint32_t)(ks * 2 + bcsel) ^ bxor) * 16u);
                ldsm4(fb[np], bd);
            }
#pragma unroll
            for (int mf = 0; mf < 2; mf++)
#pragma unroll
                for (int nf = 0; nf < 8; nf++)
                    mma16816(d[mf][nf], fah[mf], &fb[nf >> 1][(nf & 1) * 2]);
            if (ALO) {
#pragma unroll
                for (int mf = 0; mf < 2; mf++)
#pragma unroll
                    for (int nf = 0; nf < 8; nf++)
                        mma16816(d[mf][nf], fal[mf], &fb[nf >> 1][(nf & 1) * 2]);
            }
        }
        if (++stg >= NSTG) stg = 0;
    }
#undef ISSUE

    int g = lid >> 2, tg = lid & 3;
#pragma unroll
    for (int mf = 0; mf < 2; mf++) {
#pragma unroll
        for (int cp = 0; cp < 2; cp++) {
            int m = m0 + wm * 32 + mf * 16 + cp * 8 + g;
            long rb = (long)m * ldc + coff;
#pragma unroll
            for (int nf = 0; nf < 8; nf++) {
                int n = n0 + wn * 64 + nf * 8 + tg * 2;
                float v0 = d[mf][nf][cp * 2];
                float v1 = d[mf][nf][cp * 2 + 1];
                if (bias) { v0 += bias[n]; v1 += bias[n + 1]; }
                if (ACT) { v0 = fmaxf(v0, 0.f); v1 = fmaxf(v1, 0.f); }
                if (RES) { v0 += Rres[rb + n]; v1 += Rres[rb + n + 1]; }
                if (WFP32)
                    *reinterpret_cast<float2*>(C + rb + n) = make_float2(v0, v1);
                if (WSPLIT) {
                    __half h0 = __float2half_rn(v0);
                    __half h1 = __float2half_rn(v1);
                    __half2 hh; hh.x = h0; hh.y = h1;
                    *reinterpret_cast<__half2*>(Ch + rb + n) = hh;
                    if (Cl) {
                        __half2 ll;
                        ll.x = __float2half_rn(v0 - __half2float(h0));
                        ll.y = __float2half_rn(v1 - __half2float(h1));
                        *reinterpret_cast<__half2*>(Cl + rb + n) = ll;
                    }
                }
            }
        }
    }
}

// mirror upper-triangle 128-blocks of symmetric sim into lower triangle
__global__ void mirror_k(float* __restrict__ sc)
{
    int b = blockIdx.y;
    int p = blockIdx.x;               // [0, 28*16)
    int pair = p >> 4, t = p & 15;
    int BI = 1, acc = 0;
    while (pair >= acc + BI) { acc += BI; BI++; }
    int BJ = pair - acc;              // BI in 1..7, BJ < BI
    int tr = t >> 2, tc = t & 3;
    int r0 = BI * 128 + tr * 32;
    int c0 = BJ * 128 + tc * 32;
    long base = (long)b * NS * NS;
    __shared__ float tile[32][33];
    int tx = threadIdx.x, ty = threadIdx.y;   // (32, 8)
#pragma unroll
    for (int i = 0; i < 4; i++)
        tile[ty + i * 8][tx] = sc[base + (long)(c0 + ty + i * 8) * NS + r0 + tx];
    __syncthreads();
#pragma unroll
    for (int i = 0; i < 4; i++)
        sc[base + (long)(r0 + ty + i * 8) * NS + c0 + tx] = tile[tx][ty + i * 8];
}

// ============================ SIMT GEMM (small final only) ============================
template<int TB, int ACT, int RES>
__global__ void gemm_k(const float* __restrict__ A, const float* __restrict__ Bm,
                       const float* __restrict__ bias, const float* __restrict__ R,
                       float* __restrict__ C,
                       int M, int N, int K, int lda, int ldb, int ldc)
{
    __shared__ float As[16][65];
    __shared__ float Bs[16][65];
    int tid = threadIdx.x;
    int tx = tid & 15, ty = tid >> 4;
    int m0 = blockIdx.y * 64, n0 = blockIdx.x * 64;
    float acc[4][4];
#pragma unroll
    for (int i = 0; i < 4; i++)
#pragma unroll
        for (int j = 0; j < 4; j++) acc[i][j] = 0.f;

    for (int k0 = 0; k0 < K; k0 += 16) {
#pragma unroll
        for (int i = 0; i < 4; i++) {
            int idx = tid + i * 256;
            int r = idx >> 4, kk = idx & 15;
            int m = m0 + r;
            As[kk][r] = (m < M) ? A[(long)m * lda + (k0 + kk)] : 0.f;
        }
#pragma unroll
        for (int i = 0; i < 4; i++) {
            int idx = tid + i * 256;
            int r = idx >> 4, kk = idx & 15;
            Bs[kk][r] = Bm[(long)(n0 + r) * ldb + (k0 + kk)];
        }
        __syncthreads();
#pragma unroll
        for (int kk = 0; kk < 16; kk++) {
            float a[4], b[4];
#pragma unroll
            for (int i = 0; i < 4; i++) a[i] = As[kk][ty + 16 * i];
#pragma unroll
            for (int j = 0; j < 4; j++) b[j] = Bs[kk][tx + 16 * j];
#pragma unroll
            for (int i = 0; i < 4; i++)
#pragma unroll
                for (int j = 0; j < 4; j++) acc[i][j] += a[i] * b[j];
        }
        __syncthreads();
    }
#pragma unroll
    for (int i = 0; i < 4; i++) {
        int m = m0 + ty + 16 * i;
        if (m >= M) continue;
#pragma unroll
        for (int j = 0; j < 4; j++) {
            int n = n0 + tx + 16 * j;
            float v = acc[i][j];
            if (bias) v += bias[n];
            if (ACT) v = fmaxf(v, 0.f);
            C[(long)m * ldc + n] = v;
        }
    }
}

// ============================ elementwise / reduction kernels ============================
__device__ __forceinline__ void split4_store(float4 v, __half* h, __half* l, long i)
{
    __half2 h0, h1, l0, l1;
    h0.x = __float2half_rn(v.x); h0.y = __float2half_rn(v.y);
    h1.x = __float2half_rn(v.z); h1.y = __float2half_rn(v.w);
    l0.x = __float2half_rn(v.x - __half2float(h0.x));
    l0.y = __float2half_rn(v.y - __half2float(h0.y));
    l1.x = __float2half_rn(v.z - __half2float(h1.x));
    l1.y = __float2half_rn(v.w - __half2float(h1.y));
    reinterpret_cast<__half2*>(h)[2 * i] = h0;
    reinterpret_cast<__half2*>(h)[2 * i + 1] = h1;
    reinterpret_cast<__half2*>(l)[2 * i] = l0;
    reinterpret_cast<__half2*>(l)[2 * i + 1] = l1;
}

__global__ void split_k(const float* __restrict__ s, __half* __restrict__ h,
                        __half* __restrict__ l, long n4)
{
    long i = (long)blockIdx.x * blockDim.x + threadIdx.x;
    if (i >= n4) return;
    split4_store(reinterpret_cast<const float4*>(s)[i], h, l, i);
}

__global__ void wsplit_k(const float* __restrict__ w0, const float* __restrict__ w1,
                         const float* __restrict__ w2, const float* __restrict__ w3,
                         const float* __restrict__ w4, const float* __restrict__ w5,
                         __half* __restrict__ h)
{
    long i = (long)blockIdx.x * blockDim.x + threadIdx.x;
    const float* src; long base;
    if      (i < 65536)  { src = w0; base = 0;      }
    else if (i < 262144) { src = w1; base = 65536;  }
    else if (i < 327680) { src = w2; base = 262144; }
    else if (i < 458752) { src = w3; base = 327680; }
    else if (i < 589824) { src = w4; base = 458752; }
    else if (i < 720896) { src = w5; base = 589824; }
    else return;
    float4 v = reinterpret_cast<const float4*>(src)[i - base];
    __half2 h0, h1;
    h0.x = __float2half_rn(v.x); h0.y = __float2half_rn(v.y);
    h1.x = __float2half_rn(v.z); h1.y = __float2half_rn(v.w);
    reinterpret_cast<__half2*>(h)[2 * i] = h0;
    reinterpret_cast<__half2*>(h)[2 * i + 1] = h1;
}

// transpose v from qkv hi: vT[z][d][k] = qh[b, k, 1024 + h*256 + d]
__global__ void vtrans_k(const __half* __restrict__ qh, __half* __restrict__ vth)
{
    int z = blockIdx.z, zb = z >> 1, zh = z & 1;
    int d0 = blockIdx.x * 32, k0 = blockIdx.y * 32;
    __shared__ __half t[32][34];
    int tx = threadIdx.x, ty = threadIdx.y;
    long base = (long)zb * NS * 1536 + 1024 + zh * 256;
#pragma unroll
    for (int i = 0; i < 4; i++) {
        int k = k0 + ty + i * 8;
        t[ty + i * 8][tx] = qh[base + (long)k * 1536 + d0 + tx];
    }
    __syncthreads();
    __half* oh = vth + (long)z * DHH * NS;
#pragma unroll
    for (int i = 0; i < 4; i++) {
        int d = d0 + ty + i * 8;
        oh[(long)d * NS + k0 + tx] = t[tx][ty + i * 8];
    }
}

// in-place softmax over fp16 score rows (1/16 scale); writes fp16 probs
__global__ void softmax_split_k(__half* __restrict__ sp)
{
    long row = blockIdx.x;
    __half* p = sp + row * 1024;
    int t = threadIdx.x;              // 256
    uint2 raw = *reinterpret_cast<const uint2*>(p + t * 4);
    __half2 h01 = *reinterpret_cast<__half2*>(&raw.x);
    __half2 h23 = *reinterpret_cast<__half2*>(&raw.y);
    float v[4] = { __half2float(h01.x) * 0.0625f, __half2float(h01.y) * 0.0625f,
                   __half2float(h23.x) * 0.0625f, __half2float(h23.y) * 0.0625f };
    float mx = fmaxf(fmaxf(v[0], v[1]), fmaxf(v[2], v[3]));
    __shared__ float red[256];
    red[t] = mx; __syncthreads();
    for (int o = 128; o > 0; o >>= 1) { if (t < o) red[t] = fmaxf(red[t], red[t + o]); __syncthreads(); }
    mx = red[0]; __syncthreads();
    float sum = 0.f;
#pragma unroll
    for (int i = 0; i < 4; i++) { v[i] = __expf(v[i] - mx); sum += v[i]; }
    red[t] = sum; __syncthreads();
    for (int o = 128; o > 0; o >>= 1) { if (t < o) red[t] += red[t + o]; __syncthreads(); }
    float inv = 1.f / red[0];
    __half2 o01, o23;
    o01.x = __float2half_rn(v[0] * inv); o01.y = __float2half_rn(v[1] * inv);
    o23.x = __float2half_rn(v[2] * inv); o23.y = __float2half_rn(v[3] * inv);
    uint2 ow;
    ow.x = *reinterpret_cast<uint32_t*>(&o01);
    ow.y = *reinterpret_cast<uint32_t*>(&o23);
    *reinterpret_cast<uint2*>(p + t * 4) = ow;
}

__global__ void addln_k(const float* __restrict__ a, const float* __restrict__ r,
                        const float* __restrict__ g, const float* __restrict__ be,
                        float* __restrict__ o, __half* __restrict__ oh,
                        __half* __restrict__ ol)
{
    long row = blockIdx.x;
    int t = threadIdx.x;
    long base = row * 512;
    float v0 = a[base + t]       + r[base + t];
    float v1 = a[base + t + 256] + r[base + t + 256];
    __shared__ float rs[256], rq[256];
    rs[t] = v0 + v1; rq[t] = v0 * v0 + v1 * v1;
    __syncthreads();
    for (int off = 128; off > 0; off >>= 1) {
        if (t < off) { rs[t] += rs[t + off]; rq[t] += rq[t + off]; }
        __syncthreads();
    }
    float mu  = rs[0] * (1.f / 512.f);
    float var = rq[0] * (1.f / 512.f) - mu * mu;
    float inv = rsqrtf(var + 1e-5f);
    float o0 = (v0 - mu) * inv * g[t]       + be[t];
    float o1 = (v1 - mu) * inv * g[t + 256] + be[t + 256];
    o[base + t] = o0; o[base + t + 256] = o1;
    if (oh) {
        __half h0 = __float2half_rn(o0), h1 = __float2half_rn(o1);
        oh[base + t] = h0; oh[base + t + 256] = h1;
        if (ol) {
            ol[base + t]       = __float2half_rn(o0 - __half2float(h0));
            ol[base + t + 256] = __float2half_rn(o1 - __half2float(h1));
        }
    }
}

__global__ void rownorm_k(const float* __restrict__ x, __half* __restrict__ nh,
                          __half* __restrict__ nl)
{
    long row = blockIdx.x;
    int t = threadIdx.x;
    long base = row * 512;
    float v0 = x[base + t], v1 = x[base + t + 256];
    __shared__ float rq[256];
    rq[t] = v0 * v0 + v1 * v1;
    __syncthreads();
    for (int off = 128; off > 0; off >>= 1) {
        if (t < off) rq[t] += rq[t + off];
        __syncthreads();
    }
    float s = 1.f / fmaxf(sqrtf(rq[0]), 1e-12f);
    float o0 = v0 * s, o1 = v1 * s;
    __half h0 = __float2half_rn(o0), h1 = __float2half_rn(o1);
    nh[base + t] = h0; nh[base + t + 256] = h1;
    nl[base + t]       = __float2half_rn(o0 - __half2float(h0));
    nl[base + t + 256] = __float2half_rn(o1 - __half2float(h1));
}

// single-pass exact top-4 per row (comparator: value desc, index asc — jax tie rule)
__global__ void topk_k(const float* __restrict__ sim, int* __restrict__ idxo)
{
    int row = blockIdx.x;
    const float* p = sim + (long)row * 1024;
    int t = threadIdx.x;              // 128
    float v[4] = {-1e30f, -1e30f, -1e30f, -1e30f};
    int   ix[4] = {1 << 30, 1 << 30, 1 << 30, 1 << 30};
#pragma unroll
    for (int r = 0; r < 8; r++) {
        int j = t + r * 128;
        float val = p[j];
        if (val > v[3] || (val == v[3] && j < ix[3])) {
            v[3] = val; ix[3] = j;
#pragma unroll
            for (int q = 3; q > 0; q--) {
                bool up = v[q] > v[q-1] || (v[q] == v[q-1] && ix[q] < ix[q-1]);
                if (up) {
                    float tv = v[q]; v[q] = v[q-1]; v[q-1] = tv;
                    int ti = ix[q]; ix[q] = ix[q-1]; ix[q-1] = ti;
                }
            }
        }
    }
    __shared__ float sv[128][4];
    __shared__ int   si[128][4];
#pragma unroll
    for (int q = 0; q < 4; q++) { sv[t][q] = v[q]; si[t][q] = ix[q]; }
    __syncthreads();
    for (int off = 64; off > 0; off >>= 1) {
        if (t < off) {
            float mv[4]; int mi[4];
            int a = 0, b = 0;
#pragma unroll
            for (int q = 0; q < 4; q++) {
                float av = sv[t][a], bv = sv[t + off][b];
                int   ai = si[t][a], bi = si[t + off][b];
                bool ta = av > bv || (av == bv && ai < bi);
                if (ta) { mv[q] = av; mi[q] = ai; a++; }
                else    { mv[q] = bv; mi[q] = bi; b++; }
            }
#pragma unroll
            for (int q = 0; q < 4; q++) { sv[t][q] = mv[q]; si[t][q] = mi[q]; }
        }
        __syncthreads();
    }
    if (t < 4) idxo[row * 4 + t] = si[0][t];
}

__global__ void zero_k(float4* __restrict__ p, long n)
{
    long i = (long)blockIdx.x * blockDim.x + threadIdx.x;
    if (i < n) p[i] = make_float4(0.f, 0.f, 0.f, 0.f);
}

__global__ void scatter_k(const int* __restrict__ idx, unsigned int* __restrict__ mskw)
{
    int rr = blockIdx.x * blockDim.x + threadIdx.x;
    if (rr >= ROWS) return;
    int b = rr >> 10, i = rr & 1023;
    unsigned int* mb = mskw + (long)b * NS * 32;
#pragma unroll
    for (int t = 0; t < 4; t++) {
        int j = idx[rr * 4 + t];
        if (j != i) {
            atomicOr(&mb[i * 32 + (j >> 5)], 1u << (j & 31));
            atomicOr(&mb[j * 32 + (i >> 5)], 1u << (i & 31));
        }
    }
}

// combined = [x1 | nsum/cnt] -> fp16 hi only
__global__ void combine_k(const float* __restrict__ x1, const float* __restrict__ sim,
                          const unsigned int* __restrict__ mskw,
                          __half* __restrict__ ch)
{
    int rr = blockIdx.x;
    int b = rr >> 10, i = rr & 1023;
    int d = threadIdx.x;              // 512
    __shared__ unsigned int smk[32];
    if (d < 32) smk[d] = mskw[(long)b * NS * 32 + i * 32 + d];
    __syncthreads();
    const float* srow = sim + (long)rr * 1024;
    float acc = 0.f, cnt = 0.f;
#pragma unroll 4
    for (int w = 0; w < 32; w++) {
        unsigned int m = smk[w];
        while (m) {
            int bi = __ffs(m) - 1;
            m &= m - 1;
            int j = w * 32 + bi;
            float wgt = srow[j];
            acc += wgt * x1[((long)(b * NS + j)) * 512 + d];
            cnt += wgt;
        }
    }
    float xv = x1[(long)rr * 512 + d];
    float nv = acc / fmaxf(cnt, 1.0f);
    long ob = (long)rr * 1024;
    ch[ob + d]       = __float2half_rn(xv);
    ch[ob + 512 + d] = __float2half_rn(nv);
}

__global__ void pool1_k(const float* __restrict__ x2, float* __restrict__ part)
{
    int b = blockIdx.x, chunk = blockIdx.y;
    int d = threadIdx.x;
    const float* src = x2 + ((long)b * NS + chunk * 128) * 512;
    float s = 0.f;
#pragma unroll 8
    for (int sdx = 0; sdx < 128; sdx++)
        s += src[(long)sdx * 512 + d];
    part[((long)b * 8 + chunk) * 512 + d] = s;
}

__global__ void pool2_k(const float* __restrict__ part, float* __restrict__ pool)
{
    int b = blockIdx.x;
    int d = threadIdx.x;
    float s = 0.f;
#pragma unroll
    for (int c = 0; c < 8; c++)
        s += part[((long)b * 8 + c) * 512 + d];
    pool[b * 512 + d] = s * (1.f / 1024.f);
}

// =================================================================================
extern "C" void kernel_launch(void* const* d_in, const int* in_sizes, int n_in,
                              void* d_out, int out_size)
{
    const float* x      = (const float*)d_in[0];
    const float* enc_w  = (const float*)d_in[1];
    const float* enc_b  = (const float*)d_in[2];
    const float* in_w   = (const float*)d_in[3];
    const float* in_b   = (const float*)d_in[4];
    const float* out_w  = (const float*)d_in[5];
    const float* out_b  = (const float*)d_in[6];
    const float* ln1_g  = (const float*)d_in[7];
    const float* ln1_b  = (const float*)d_in[8];
    const float* ffn_w1 = (const float*)d_in[9];
    const float* ffn_b1 = (const float*)d_in[10];
    const float* ffn_w2 = (const float*)d_in[11];
    const float* ffn_b2 = (const float*)d_in[12];
    const float* gc_w   = (const float*)d_in[13];
    const float* gc_b   = (const float*)d_in[14];
    const float* ln2_g  = (const float*)d_in[15];
    const float* ln2_b  = (const float*)d_in[16];
    const float* dec_w  = (const float*)d_in[17];
    const float* dec_b  = (const float*)d_in[18];
    float* out = (float*)d_out;

    float *h_, *sc_, *t1_, *x1_, *x2_, *poolp_, *pool_;
    int* idx_;
    unsigned int* mskw_;
    __half *xh_, *xl_, *hh_, *qkvh_, *ah_, *vth_;
    __half *ctxh_, *x1h_, *midh_, *nh_, *nl_, *cbh_, *wh_;
    cudaGetSymbolAddress((void**)&h_,    g_h);
    cudaGetSymbolAddress((void**)&sc_,   g_sc);
    cudaGetSymbolAddress((void**)&t1_,   g_t1);
    cudaGetSymbolAddress((void**)&x1_,   g_x1);
    cudaGetSymbolAddress((void**)&x2_,   g_x2);
    cudaGetSymbolAddress((void**)&poolp_,g_poolp);
    cudaGetSymbolAddress((void**)&pool_, g_pool);
    cudaGetSymbolAddress((void**)&idx_,  g_idx);
    cudaGetSymbolAddress((void**)&mskw_, g_mskw);
    cudaGetSymbolAddress((void**)&xh_,   g_xh);   cudaGetSymbolAddress((void**)&xl_,   g_xl);
    cudaGetSymbolAddress((void**)&hh_,   g_hh);
    cudaGetSymbolAddress((void**)&qkvh_, g_qkvh);
    cudaGetSymbolAddress((void**)&ah_,   g_ah);
    cudaGetSymbolAddress((void**)&vth_,  g_vth);
    cudaGetSymbolAddress((void**)&ctxh_, g_ctxh);
    cudaGetSymbolAddress((void**)&x1h_,  g_x1h);
    cudaGetSymbolAddress((void**)&midh_, g_midh);
    cudaGetSymbolAddress((void**)&nh_,   g_nh);   cudaGetSymbolAddress((void**)&nl_,   g_nl);
    cudaGetSymbolAddress((void**)&cbh_,  g_cbh);
    cudaGetSymbolAddress((void**)&wh_,   g_wh);

    cudaFuncSetAttribute(mmagemm_k<1,0,1,1,0,1>, cudaFuncAttributeMaxDynamicSharedMemorySize, MMSMEM);
    cudaFuncSetAttribute(mmagemm_k<0,0,1,0,0,0>, cudaFuncAttributeMaxDynamicSharedMemorySize, MMSMEM);
    cudaFuncSetAttribute(mmagemm_k<0,0,0,1,0,0>, cudaFuncAttributeMaxDynamicSharedMemorySize, MMSMEM);
    cudaFuncSetAttribute(mmagemm_k<1,0,1,0,0,0>, cudaFuncAttributeMaxDynamicSharedMemorySize, MMSMEM);
    cudaFuncSetAttribute(mmagemm_k<0,1,0,1,0,0>, cudaFuncAttributeMaxDynamicSharedMemorySize, MMSMEM);
    cudaFuncSetAttribute(mmagemm_k<0,0,0,1,1,1>, cudaFuncAttributeMaxDynamicSharedMemorySize, MMSMEM);

    dim3 blk(256);

    // input split + fused weight conversion
    split_k<<<(ROWS*DIN/4 + 255)/256, blk>>>(x, xh_, xl_, (long)ROWS*DIN/4);
    wsplit_k<<<(720896 + 255)/256, blk>>>(enc_w, in_w, out_w, ffn_w1, ffn_w2, gc_w, wh_);

    // G1: h = relu(x @ enc_w^T + b), fp32 + fp16 hi (x keeps hi/lo — input fidelity)
    mmagemm_k<1,0,1,1,0,1><<<dim3(4,256,1), blk, MMSMEM>>>(xh_, xl_, wh_+WO_ENC,
        enc_b, nullptr, h_, hh_, nullptr, 512, 512, 512, 512, 0,0,0,0,0,0, 1);

    // G2: qkv = h @ in_w^T + b, h hi-only, fp16 hi output only
    mmagemm_k<0,0,1,0,0,0><<<dim3(12,256,1), blk, MMSMEM>>>(hh_, nullptr, wh_+WO_IN,
        in_b, nullptr, nullptr, qkvh_, nullptr, 512, 512, 512, 1536, 0,0,0,0,0,0, 1);

    // v transpose (reads qkv hi) -> vT fp16
    vtrans_k<<<dim3(8,32,64), dim3(32,8)>>>(qkvh_, vth_);

    // G3: scores = q @ k^T (batched z=64), q hi-only, fp16 hi output -> g_ah
    mmagemm_k<0,0,1,0,0,0><<<dim3(8,8,64), blk, MMSMEM>>>(qkvh_, nullptr, qkvh_+512,
        nullptr, nullptr, nullptr, ah_, nullptr, 256, 1536, 1536, 1024,
        256, (long)NS*1536, 256, (long)NS*1536, (long)NS*NS, 2L*NS*NS, 2);

    // in-place fp16 softmax (1/16 scale)
    softmax_split_k<<<NB*NHD*NS, 256>>>(ah_);

    // G4: ctx = attn @ vT^T (batched z=64), probs hi-only, ctx hi output only
    mmagemm_k<0,0,1,0,0,0><<<dim3(2,8,64), blk, MMSMEM>>>(ah_, nullptr, vth_,
        nullptr, nullptr, nullptr, ctxh_, nullptr, 1024, 1024, 1024, 512,
        (long)NS*NS, 2L*NS*NS, (long)DHH*NS, 2L*DHH*NS, 256, (long)NS*512, 2);

    // G5: attn_out = ctx @ out_w^T + b -> t1 fp32, ctx hi-only (ALO=0)
    mmagemm_k<0,0,0,1,0,0><<<dim3(4,256,1), blk, MMSMEM>>>(ctxh_, nullptr, wh_+WO_OUT,
        out_b, nullptr, t1_, nullptr, nullptr, 512, 512, 512, 512, 0,0,0,0,0,0, 1);

    // x1 = LN(h + attn_out), fp32 + fp16 hi only
    addln_k<<<ROWS, 256>>>(h_, t1_, ln1_g, ln1_b, x1_, x1h_, nullptr);

    // G6: mid = relu(x1 @ ffn_w1^T + b1), x1 hi-only (ALO=0), mid hi output only
    mmagemm_k<1,0,1,0,0,0><<<dim3(8,256,1), blk, MMSMEM>>>(x1h_, nullptr, wh_+WO_F1,
        ffn_b1, nullptr, nullptr, midh_, nullptr, 512, 512, 512, 1024, 0,0,0,0,0,0, 1);

    // G7: x1 = x1 + mid @ ffn_w2^T + b2 (residual), mid hi-only (ALO=0), fp32
    mmagemm_k<0,1,0,1,0,0><<<dim3(4,256,1), blk, MMSMEM>>>(midh_, nullptr, wh_+WO_F2,
        ffn_b2, x1_, x1_, nullptr, nullptr, 1024, 1024, 1024, 512, 0,0,0,0,0,0, 1);

    // nrm = rownorm(x1), hi/lo (sim stays exact — feeds discrete top-k)
    rownorm_k<<<ROWS, 256>>>(x1_, nh_, nl_);

    // sim = nrm @ nrm^T (batched z=32) — upper-triangle blocks only (symmetric)
    mmagemm_k<0,0,0,1,1,1><<<dim3(36,1,32), blk, MMSMEM>>>(nh_, nl_, nh_,
        nullptr, nullptr, sc_, nullptr, nullptr, 512, 512, 512, 1024,
        0, (long)NS*512, 0, (long)NS*512, 0, (long)NS*NS, 1);

    // mirror upper -> lower triangle
    mirror_k<<<dim3(28*16, NB), dim3(32,8)>>>(sc_);

    // adjacency (1-bit mask)
    zero_k<<<(int)(((long)NB*NS*32*4/16 + 255)/256), blk>>>((float4*)mskw_, (long)NB*NS*32*4/16);
    topk_k<<<ROWS, 128>>>(sc_, idx_);
    scatter_k<<<(ROWS+255)/256, blk>>>(idx_, mskw_);

    // combined = [x1 | nsum/cnt] -> fp16 hi only
    combine_k<<<ROWS, 512>>>(x1_, sc_, mskw_, cbh_);

    // G8: gco = combined @ gc_w^T + b -> t1 fp32, combined hi-only (ALO=0)
    mmagemm_k<0,0,0,1,0,0><<<dim3(4,256,1), blk, MMSMEM>>>(cbh_, nullptr, wh_+WO_GC,
        gc_b, nullptr, t1_, nullptr, nullptr, 1024, 1024, 1024, 512, 0,0,0,0,0,0, 1);

    // x2 = LN(x1 + gco), fp32 only
    addln_k<<<ROWS, 256>>>(x1_, t1_, ln2_g, ln2_b, x2_, nullptr, nullptr);

    // pool (two-stage) + decoder
    pool1_k<<<dim3(NB,8), 512>>>(x2_, poolp_);
    pool2_k<<<NB, 512>>>(poolp_, pool_);
    gemm_k<1,0,0><<<dim3(8,1,1), blk>>>(pool_, dec_w, dec_b, nullptr, out,
        32, 512, 512, 512, 512, 512);
}

// round 17
// speedup vs baseline: 1.4823x; 1.0500x over previous
#include <cuda_runtime.h>
#include <cuda_bf16.h>
#include <cuda_fp16.h>
#include <cstdint>

// Problem constants
#define NB   32
#define NS   1024
#define DIN  512
#define DH   512
#define DOUT 512
#define NHD  2
#define DHH  256
#define ROWS (NB*NS)             // 32768
#define SCSZ (67108864L)         // NB*NHD*NS*NS

// ============================ helpers ============================
__device__ __forceinline__ uint32_t smem_to_u32(const void* p) {
    uint32_t a;
    asm("{ .reg .u64 t; cvta.to.shared.u64 t, %1; cvt.u32.u64 %0, t; }" : "=r"(a) : "l"(p));
    return a;
}
__device__ __forceinline__ void ldsm4(uint32_t* r, uint32_t addr) {
    asm volatile("ldmatrix.sync.aligned.m8n8.x4.shared.b16 {%0,%1,%2,%3}, [%4];"
                 : "=r"(r[0]), "=r"(r[1]), "=r"(r[2]), "=r"(r[3]) : "r"(addr));
}
__device__ __forceinline__ void mma16816(float* d, const uint32_t* a, const uint32_t* b) {
    asm volatile("mma.sync.aligned.m16n8k16.row.col.f32.f16.f16.f32 "
                 "{%0,%1,%2,%3}, {%4,%5,%6,%7}, {%8,%9}, {%0,%1,%2,%3};"
                 : "+f"(d[0]), "+f"(d[1]), "+f"(d[2]), "+f"(d[3])
                 : "r"(a[0]), "r"(a[1]), "r"(a[2]), "r"(a[3]), "r"(b[0]), "r"(b[1]));
}
__device__ __forceinline__ void cpa16(uint32_t s, const void* g) {
    asm volatile("cp.async.cg.shared.global [%0], [%1], 16;" :: "r"(s), "l"(g));
}
__device__ __forceinline__ void cpcommit() { asm volatile("cp.async.commit_group;"); }
template<int N> __device__ __forceinline__ void cpwait() {
    asm volatile("cp.async.wait_group %0;" :: "n"(N));
}

// smem: 3 tiles (Ah, Al, B) of 128 rows x 64B (32 fp16), XOR-swizzled, 4 stages
#define ATILEB 8192               // 128*64
#define STAGEB (3*ATILEB)         // 24576
#define NSTG   4
#define MMSMEM (NSTG*STAGEB)      // 98304
#define SWZ(row, chunk) ((uint32_t)(row)*64u + ((uint32_t)((chunk) ^ (((row)>>1)&3))*16u))

// ============================ scratch buffers ============================
__device__ float g_h   [ROWS*DH];
__device__ float g_sc  [SCSZ];               // sim only
__device__ float g_t1  [ROWS*DH];
__device__ float g_x1  [ROWS*DH];
__device__ float g_x2  [ROWS*DH];
__device__ float g_poolp[NB*8*DH];
__device__ float g_pool[NB*DH];
__device__ int   g_idx [ROWS*4];
__device__ unsigned int g_mskw [(long)NB*NS*32];   // bitmask adjacency, 4MB

__device__ __half g_xh[ROWS*DIN];
__device__ __half g_hh[ROWS*DH];
__device__ __half g_qkvh[ROWS*3*DH];
__device__ __half g_ah[SCSZ];                // scores, then probs (in-place softmax)
__device__ __half g_vth[(long)NB*NHD*DHH*NS];
__device__ __half g_ctxh[ROWS*DH];
__device__ __half g_x1h[ROWS*DH];
__device__ __half g_midh[ROWS*2*DH];
__device__ __half g_nh[ROWS*DH];
__device__ __half g_cbh[ROWS*2*DH];
__device__ __half g_wh[4*1024*1024];

// weight offsets (elements)
#define WO_ENC 0
#define WO_IN  262144
#define WO_OUT 1048576
#define WO_F1  1310720
#define WO_F2  1835008
#define WO_GC  2359296

// ============================ HMMA GEMM (fp16x2, cp.async 4-stage, 2 CTA/SM) ============
// C[M,N] = act((Ah[+Al]) @ B^T + bias) (+R).  A hi/lo fp16 [M,K] row-major, B fp16 [N,K].
// CTA tile 128x128, warp tile 32x64 (4x2 warps), K chunks of 32, swizzled smem.
// TRIU=1: blockIdx.x in [0,36) remapped to upper-triangle (bx,by), by<=bx (symmetric C).
// ALO=0: skip A-lo stream (half the MMAs).  WSPLIT: Cl==nullptr -> write hi only.
template<int ACT, int RES, int WSPLIT, int WFP32, int TRIU, int ALO>
__global__ void __launch_bounds__(256, 2)
mmagemm_k(const __half* __restrict__ Ah, const __half* __restrict__ Al,
          const __half* __restrict__ Bm,
          const float* __restrict__ bias, const float* __restrict__ Rres,
          float* __restrict__ C, __half* __restrict__ Ch, __half* __restrict__ Cl,
          int K, int lda, int ldb, int ldc,
          long sA1, long sA2, long sB1, long sB2, long sC1, long sC2, int HZ)
{
    extern __shared__ char sm[];
    uint32_t sb = smem_to_u32(sm);

    int tid = threadIdx.x, wid = tid >> 5, lid = tid & 31;
    int wm = wid >> 1, wn = wid & 1;
    int z = blockIdx.z, zb = z / HZ, zh = z - zb * HZ;
    long aoff = (long)zb * sA2 + (long)zh * sA1;
    long boff = (long)zb * sB2 + (long)zh * sB1;
    long coff = (long)zb * sC2 + (long)zh * sC1;

    int bx, by;
    if (TRIU) {
        int p = blockIdx.x;
        by = 0;
        while (p >= 8 - by) { p -= 8 - by; by++; }
        bx = by + p;
    } else {
        bx = blockIdx.x; by = blockIdx.y;
    }
    int m0 = by * 128, n0 = bx * 128;

    const __half* Ahp = Ah + aoff + (long)m0 * lda;
    const __half* Alp = ALO ? (Al + aoff + (long)m0 * lda) : Ahp;
    const __half* Bp  = Bm + boff + (long)n0 * ldb;

    int lrow = tid >> 1, c0 = (tid & 1) * 2;
    const char* pAh = (const char*)(Ahp + (long)lrow * lda) + c0 * 16;
    const char* pAl = (const char*)(Alp + (long)lrow * lda) + c0 * 16;
    const char* pB  = (const char*)(Bp  + (long)lrow * ldb) + c0 * 16;
    uint32_t d0 = SWZ(lrow, c0), d1 = SWZ(lrow, c0 + 1);

#define ISSUE(stg, c) do { long ob = (long)(c) * 64; uint32_t bp = sb + (stg) * STAGEB; \
    cpa16(bp + d0,            pAh + ob); cpa16(bp + d1,            pAh + ob + 16); \
    if (ALO) { cpa16(bp + ATILEB + d0, pAl + ob); cpa16(bp + ATILEB + d1, pAl + ob + 16); } \
    cpa16(bp + 2*ATILEB + d0, pB  + ob); cpa16(bp + 2*ATILEB + d1, pB  + ob + 16); } while (0)

    int arow = wm * 32 + ((lid >> 3) & 1) * 8 + (lid & 7);
    int acsel = (lid >> 4) & 1;
    uint32_t axor = (uint32_t)((arow >> 1) & 3);
    int brow = wn * 64 + ((lid >> 4) & 1) * 8 + (lid & 7);
    int bcsel = (lid >> 3) & 1;
    uint32_t bxor = (uint32_t)((brow >> 1) & 3);

    float d[2][8][4];
#pragma unroll
    for (int i = 0; i < 2; i++)
#pragma unroll
        for (int j = 0; j < 8; j++)
#pragma unroll
            for (int q = 0; q < 4; q++) d[i][j][q] = 0.f;

    const int nCh = K >> 5;
    ISSUE(0, 0); cpcommit();
    ISSUE(1, 1); cpcommit();
    ISSUE(2, 2); cpcommit();

    int stg = 0;
    for (int c = 0; c < nCh; c++) {
        cpwait<2>();
        __syncthreads();
        if (c + 3 < nCh) {
            int ns = stg + 3; if (ns >= NSTG) ns -= NSTG;
            ISSUE(ns, c + 3);
        }
        cpcommit();

        uint32_t cb = sb + stg * STAGEB;
#pragma unroll
        for (int ks = 0; ks < 2; ks++) {
            uint32_t fah[2][4], fal[2][4], fb[4][4];
#pragma unroll
            for (int mf = 0; mf < 2; mf++) {
                uint32_t ad = cb + (uint32_t)(arow + mf * 16) * 64u
                            + (((uint32_t)(ks * 2 + acsel) ^ axor) * 16u);
                ldsm4(fah[mf], ad);
                if (ALO) ldsm4(fal[mf], ad + ATILEB);
            }
#pragma unroll
            for (int np = 0; np < 4; np++) {
                uint32_t bd = cb + 2 * ATILEB + (uint32_t)(brow + np * 16) * 64u
                            + (((uint32_t)(ks * 2 + bcsel) ^ bxor) * 16u);
                ldsm4(fb[np], bd);
            }
#pragma unroll
            for (int mf = 0; mf < 2; mf++)
#pragma unroll
                for (int nf = 0; nf < 8; nf++)
                    mma16816(d[mf][nf], fah[mf], &fb[nf >> 1][(nf & 1) * 2]);
            if (ALO) {
#pragma unroll
                for (int mf = 0; mf < 2; mf++)
#pragma unroll
                    for (int nf = 0; nf < 8; nf++)
                        mma16816(d[mf][nf], fal[mf], &fb[nf >> 1][(nf & 1) * 2]);
            }
        }
        if (++stg >= NSTG) stg = 0;
    }
#undef ISSUE

    int g = lid >> 2, tg = lid & 3;
#pragma unroll
    for (int mf = 0; mf < 2; mf++) {
#pragma unroll
        for (int cp = 0; cp < 2; cp++) {
            int m = m0 + wm * 32 + mf * 16 + cp * 8 + g;
            long rb = (long)m * ldc + coff;
#pragma unroll
            for (int nf = 0; nf < 8; nf++) {
                int n = n0 + wn * 64 + nf * 8 + tg * 2;
                float v0 = d[mf][nf][cp * 2];
                float v1 = d[mf][nf][cp * 2 + 1];
                if (bias) { v0 += bias[n]; v1 += bias[n + 1]; }
                if (ACT) { v0 = fmaxf(v0, 0.f); v1 = fmaxf(v1, 0.f); }
                if (RES) { v0 += Rres[rb + n]; v1 += Rres[rb + n + 1]; }
                if (WFP32)
                    *reinterpret_cast<float2*>(C + rb + n) = make_float2(v0, v1);
                if (WSPLIT) {
                    __half h0 = __float2half_rn(v0);
                    __half h1 = __float2half_rn(v1);
                    __half2 hh; hh.x = h0; hh.y = h1;
                    *reinterpret_cast<__half2*>(Ch + rb + n) = hh;
                    if (Cl) {
                        __half2 ll;
                        ll.x = __float2half_rn(v0 - __half2float(h0));
                        ll.y = __float2half_rn(v1 - __half2float(h1));
                        *reinterpret_cast<__half2*>(Cl + rb + n) = ll;
                    }
                }
            }
        }
    }
}

// mirror upper-triangle 128-blocks of symmetric sim into lower triangle
__global__ void mirror_k(float* __restrict__ sc)
{
    int b = blockIdx.y;
    int p = blockIdx.x;               // [0, 28*16)
    int pair = p >> 4, t = p & 15;
    int BI = 1, acc = 0;
    while (pair >= acc + BI) { acc += BI; BI++; }
    int BJ = pair - acc;              // BI in 1..7, BJ < BI
    int tr = t >> 2, tc = t & 3;
    int r0 = BI * 128 + tr * 32;
    int c0 = BJ * 128 + tc * 32;
    long base = (long)b * NS * NS;
    __shared__ float tile[32][33];
    int tx = threadIdx.x, ty = threadIdx.y;   // (32, 8)
#pragma unroll
    for (int i = 0; i < 4; i++)
        tile[ty + i * 8][tx] = sc[base + (long)(c0 + ty + i * 8) * NS + r0 + tx];
    __syncthreads();
#pragma unroll
    for (int i = 0; i < 4; i++)
        sc[base + (long)(r0 + ty + i * 8) * NS + c0 + tx] = tile[tx][ty + i * 8];
}

// ============================ SIMT GEMM (small final only) ============================
template<int TB, int ACT, int RES>
__global__ void gemm_k(const float* __restrict__ A, const float* __restrict__ Bm,
                       const float* __restrict__ bias, const float* __restrict__ R,
                       float* __restrict__ C,
                       int M, int N, int K, int lda, int ldb, int ldc)
{
    __shared__ float As[16][65];
    __shared__ float Bs[16][65];
    int tid = threadIdx.x;
    int tx = tid & 15, ty = tid >> 4;
    int m0 = blockIdx.y * 64, n0 = blockIdx.x * 64;
    float acc[4][4];
#pragma unroll
    for (int i = 0; i < 4; i++)
#pragma unroll
        for (int j = 0; j < 4; j++) acc[i][j] = 0.f;

    for (int k0 = 0; k0 < K; k0 += 16) {
#pragma unroll
        for (int i = 0; i < 4; i++) {
            int idx = tid + i * 256;
            int r = idx >> 4, kk = idx & 15;
            int m = m0 + r;
            As[kk][r] = (m < M) ? A[(long)m * lda + (k0 + kk)] : 0.f;
        }
#pragma unroll
        for (int i = 0; i < 4; i++) {
            int idx = tid + i * 256;
            int r = idx >> 4, kk = idx & 15;
            Bs[kk][r] = Bm[(long)(n0 + r) * ldb + (k0 + kk)];
        }
        __syncthreads();
#pragma unroll
        for (int kk = 0; kk < 16; kk++) {
            float a[4], b[4];
#pragma unroll
            for (int i = 0; i < 4; i++) a[i] = As[kk][ty + 16 * i];
#pragma unroll
            for (int j = 0; j < 4; j++) b[j] = Bs[kk][tx + 16 * j];
#pragma unroll
            for (int i = 0; i < 4; i++)
#pragma unroll
                for (int j = 0; j < 4; j++) acc[i][j] += a[i] * b[j];
        }
        __syncthreads();
    }
#pragma unroll
    for (int i = 0; i < 4; i++) {
        int m = m0 + ty + 16 * i;
        if (m >= M) continue;
#pragma unroll
        for (int j = 0; j < 4; j++) {
            int n = n0 + tx + 16 * j;
            float v = acc[i][j];
            if (bias) v += bias[n];
            if (ACT) v = fmaxf(v, 0.f);
            C[(long)m * ldc + n] = v;
        }
    }
}

// ============================ elementwise / reduction kernels ============================
// fp32 -> fp16 hi-only conversion
__global__ void splith_k(const float* __restrict__ s, __half* __restrict__ h, long n4)
{
    long i = (long)blockIdx.x * blockDim.x + threadIdx.x;
    if (i >= n4) return;
    float4 v = reinterpret_cast<const float4*>(s)[i];
    __half2 h0, h1;
    h0.x = __float2half_rn(v.x); h0.y = __float2half_rn(v.y);
    h1.x = __float2half_rn(v.z); h1.y = __float2half_rn(v.w);
    reinterpret_cast<__half2*>(h)[2 * i] = h0;
    reinterpret_cast<__half2*>(h)[2 * i + 1] = h1;
}

__global__ void wsplit_k(const float* __restrict__ w0, const float* __restrict__ w1,
                         const float* __restrict__ w2, const float* __restrict__ w3,
                         const float* __restrict__ w4, const float* __restrict__ w5,
                         __half* __restrict__ h)
{
    long i = (long)blockIdx.x * blockDim.x + threadIdx.x;
    const float* src; long base;
    if      (i < 65536)  { src = w0; base = 0;      }
    else if (i < 262144) { src = w1; base = 65536;  }
    else if (i < 327680) { src = w2; base = 262144; }
    else if (i < 458752) { src = w3; base = 327680; }
    else if (i < 589824) { src = w4; base = 458752; }
    else if (i < 720896) { src = w5; base = 589824; }
    else return;
    float4 v = reinterpret_cast<const float4*>(src)[i - base];
    __half2 h0, h1;
    h0.x = __float2half_rn(v.x); h0.y = __float2half_rn(v.y);
    h1.x = __float2half_rn(v.z); h1.y = __float2half_rn(v.w);
    reinterpret_cast<__half2*>(h)[2 * i] = h0;
    reinterpret_cast<__half2*>(h)[2 * i + 1] = h1;
}

// transpose v from qkv hi: vT[z][d][k] = qh[b, k, 1024 + h*256 + d]
__global__ void vtrans_k(const __half* __restrict__ qh, __half* __restrict__ vth)
{
    int z = blockIdx.z, zb = z >> 1, zh = z & 1;
    int d0 = blockIdx.x * 32, k0 = blockIdx.y * 32;
    __shared__ __half t[32][34];
    int tx = threadIdx.x, ty = threadIdx.y;
    long base = (long)zb * NS * 1536 + 1024 + zh * 256;
#pragma unroll
    for (int i = 0; i < 4; i++) {
        int k = k0 + ty + i * 8;
        t[ty + i * 8][tx] = qh[base + (long)k * 1536 + d0 + tx];
    }
    __syncthreads();
    __half* oh = vth + (long)z * DHH * NS;
#pragma unroll
    for (int i = 0; i < 4; i++) {
        int d = d0 + ty + i * 8;
        oh[(long)d * NS + k0 + tx] = t[tx][ty + i * 8];
    }
}

// in-place softmax over fp16 score rows (1/16 scale); writes fp16 probs
__global__ void softmax_split_k(__half* __restrict__ sp)
{
    long row = blockIdx.x;
    __half* p = sp + row * 1024;
    int t = threadIdx.x;              // 256
    uint2 raw = *reinterpret_cast<const uint2*>(p + t * 4);
    __half2 h01 = *reinterpret_cast<__half2*>(&raw.x);
    __half2 h23 = *reinterpret_cast<__half2*>(&raw.y);
    float v[4] = { __half2float(h01.x) * 0.0625f, __half2float(h01.y) * 0.0625f,
                   __half2float(h23.x) * 0.0625f, __half2float(h23.y) * 0.0625f };
    float mx = fmaxf(fmaxf(v[0], v[1]), fmaxf(v[2], v[3]));
    __shared__ float red[256];
    red[t] = mx; __syncthreads();
    for (int o = 128; o > 0; o >>= 1) { if (t < o) red[t] = fmaxf(red[t], red[t + o]); __syncthreads(); }
    mx = red[0]; __syncthreads();
    float sum = 0.f;
#pragma unroll
    for (int i = 0; i < 4; i++) { v[i] = __expf(v[i] - mx); sum += v[i]; }
    red[t] = sum; __syncthreads();
    for (int o = 128; o > 0; o >>= 1) { if (t < o) red[t] += red[t + o]; __syncthreads(); }
    float inv = 1.f / red[0];
    __half2 o01, o23;
    o01.x = __float2half_rn(v[0] * inv); o01.y = __float2half_rn(v[1] * inv);
    o23.x = __float2half_rn(v[2] * inv); o23.y = __float2half_rn(v[3] * inv);
    uint2 ow;
    ow.x = *reinterpret_cast<uint32_t*>(&o01);
    ow.y = *reinterpret_cast<uint32_t*>(&o23);
    *reinterpret_cast<uint2*>(p + t * 4) = ow;
}

__global__ void addln_k(const float* __restrict__ a, const float* __restrict__ r,
                        const float* __restrict__ g, const float* __restrict__ be,
                        float* __restrict__ o, __half* __restrict__ oh)
{
    long row = blockIdx.x;
    int t = threadIdx.x;
    long base = row * 512;
    float v0 = a[base + t]       + r[base + t];
    float v1 = a[base + t + 256] + r[base + t + 256];
    __shared__ float rs[256], rq[256];
    rs[t] = v0 + v1; rq[t] = v0 * v0 + v1 * v1;
    __syncthreads();
    for (int off = 128; off > 0; off >>= 1) {
        if (t < off) { rs[t] += rs[t + off]; rq[t] += rq[t + off]; }
        __syncthreads();
    }
    float mu  = rs[0] * (1.f / 512.f);
    float var = rq[0] * (1.f / 512.f) - mu * mu;
    float inv = rsqrtf(var + 1e-5f);
    float o0 = (v0 - mu) * inv * g[t]       + be[t];
    float o1 = (v1 - mu) * inv * g[t + 256] + be[t + 256];
    o[base + t] = o0; o[base + t + 256] = o1;
    if (oh) {
        oh[base + t]       = __float2half_rn(o0);
        oh[base + t + 256] = __float2half_rn(o1);
    }
}

// row L2-normalize, fp16 hi output only
__global__ void rownorm_k(const float* __restrict__ x, __half* __restrict__ nh)
{
    long row = blockIdx.x;
    int t = threadIdx.x;
    long base = row * 512;
    float v0 = x[base + t], v1 = x[base + t + 256];
    __shared__ float rq[256];
    rq[t] = v0 * v0 + v1 * v1;
    __syncthreads();
    for (int off = 128; off > 0; off >>= 1) {
        if (t < off) rq[t] += rq[t + off];
        __syncthreads();
    }
    float s = 1.f / fmaxf(sqrtf(rq[0]), 1e-12f);
    nh[base + t]       = __float2half_rn(v0 * s);
    nh[base + t + 256] = __float2half_rn(v1 * s);
}

// single-pass exact top-4 per row (comparator: value desc, index asc — jax tie rule)
__global__ void topk_k(const float* __restrict__ sim, int* __restrict__ idxo)
{
    int row = blockIdx.x;
    const float* p = sim + (long)row * 1024;
    int t = threadIdx.x;              // 128
    float v[4] = {-1e30f, -1e30f, -1e30f, -1e30f};
    int   ix[4] = {1 << 30, 1 << 30, 1 << 30, 1 << 30};
#pragma unroll
    for (int r = 0; r < 8; r++) {
        int j = t + r * 128;
        float val = p[j];
        if (val > v[3] || (val == v[3] && j < ix[3])) {
            v[3] = val; ix[3] = j;
#pragma unroll
            for (int q = 3; q > 0; q--) {
                bool up = v[q] > v[q-1] || (v[q] == v[q-1] && ix[q] < ix[q-1]);
                if (up) {
                    float tv = v[q]; v[q] = v[q-1]; v[q-1] = tv;
                    int ti = ix[q]; ix[q] = ix[q-1]; ix[q-1] = ti;
                }
            }
        }
    }
    __shared__ float sv[128][4];
    __shared__ int   si[128][4];
#pragma unroll
    for (int q = 0; q < 4; q++) { sv[t][q] = v[q]; si[t][q] = ix[q]; }
    __syncthreads();
    for (int off = 64; off > 0; off >>= 1) {
        if (t < off) {
            float mv[4]; int mi[4];
            int a = 0, b = 0;
#pragma unroll
            for (int q = 0; q < 4; q++) {
                float av = sv[t][a], bv = sv[t + off][b];
                int   ai = si[t][a], bi = si[t + off][b];
                bool ta = av > bv || (av == bv && ai < bi);
                if (ta) { mv[q] = av; mi[q] = ai; a++; }
                else    { mv[q] = bv; mi[q] = bi; b++; }
            }
#pragma unroll
            for (int q = 0; q < 4; q++) { sv[t][q] = mv[q]; si[t][q] = mi[q]; }
        }
        __syncthreads();
    }
    if (t < 4) idxo[row * 4 + t] = si[0][t];
}

__global__ void zero_k(float4* __restrict__ p, long n)
{
    long i = (long)blockIdx.x * blockDim.x + threadIdx.x;
    if (i < n) p[i] = make_float4(0.f, 0.f, 0.f, 0.f);
}

__global__ void scatter_k(const int* __restrict__ idx, unsigned int* __restrict__ mskw)
{
    int rr = blockIdx.x * blockDim.x + threadIdx.x;
    if (rr >= ROWS) return;
    int b = rr >> 10, i = rr & 1023;
    unsigned int* mb = mskw + (long)b * NS * 32;
#pragma unroll
    for (int t = 0; t < 4; t++) {
        int j = idx[rr * 4 + t];
        if (j != i) {
            atomicOr(&mb[i * 32 + (j >> 5)], 1u << (j & 31));
            atomicOr(&mb[j * 32 + (i >> 5)], 1u << (i & 31));
        }
    }
}

// combined = [x1 | nsum/cnt] -> fp16 hi only
__global__ void combine_k(const float* __restrict__ x1, const float* __restrict__ sim,
                          const unsigned int* __restrict__ mskw,
                          __half* __restrict__ ch)
{
    int rr = blockIdx.x;
    int b = rr >> 10, i = rr & 1023;
    int d = threadIdx.x;              // 512
    __shared__ unsigned int smk[32];
    if (d < 32) smk[d] = mskw[(long)b * NS * 32 + i * 32 + d];
    __syncthreads();
    const float* srow = sim + (long)rr * 1024;
    float acc = 0.f, cnt = 0.f;
#pragma unroll 4
    for (int w = 0; w < 32; w++) {
        unsigned int m = smk[w];
        while (m) {
            int bi = __ffs(m) - 1;
            m &= m - 1;
            int j = w * 32 + bi;
            float wgt = srow[j];
            acc += wgt * x1[((long)(b * NS + j)) * 512 + d];
            cnt += wgt;
        }
    }
    float xv = x1[(long)rr * 512 + d];
    float nv = acc / fmaxf(cnt, 1.0f);
    long ob = (long)rr * 1024;
    ch[ob + d]       = __float2half_rn(xv);
    ch[ob + 512 + d] = __float2half_rn(nv);
}

__global__ void pool1_k(const float* __restrict__ x2, float* __restrict__ part)
{
    int b = blockIdx.x, chunk = blockIdx.y;
    int d = threadIdx.x;
    const float* src = x2 + ((long)b * NS + chunk * 128) * 512;
    float s = 0.f;
#pragma unroll 8
    for (int sdx = 0; sdx < 128; sdx++)
        s += src[(long)sdx * 512 + d];
    part[((long)b * 8 + chunk) * 512 + d] = s;
}

__global__ void pool2_k(const float* __restrict__ part, float* __restrict__ pool)
{
    int b = blockIdx.x;
    int d = threadIdx.x;
    float s = 0.f;
#pragma unroll
    for (int c = 0; c < 8; c++)
        s += part[((long)b * 8 + c) * 512 + d];
    pool[b * 512 + d] = s * (1.f / 1024.f);
}

// =================================================================================
extern "C" void kernel_launch(void* const* d_in, const int* in_sizes, int n_in,
                              void* d_out, int out_size)
{
    const float* x      = (const float*)d_in[0];
    const float* enc_w  = (const float*)d_in[1];
    const float* enc_b  = (const float*)d_in[2];
    const float* in_w   = (const float*)d_in[3];
    const float* in_b   = (const float*)d_in[4];
    const float* out_w  = (const float*)d_in[5];
    const float* out_b  = (const float*)d_in[6];
    const float* ln1_g  = (const float*)d_in[7];
    const float* ln1_b  = (const float*)d_in[8];
    const float* ffn_w1 = (const float*)d_in[9];
    const float* ffn_b1 = (const float*)d_in[10];
    const float* ffn_w2 = (const float*)d_in[11];
    const float* ffn_b2 = (const float*)d_in[12];
    const float* gc_w   = (const float*)d_in[13];
    const float* gc_b   = (const float*)d_in[14];
    const float* ln2_g  = (const float*)d_in[15];
    const float* ln2_b  = (const float*)d_in[16];
    const float* dec_w  = (const float*)d_in[17];
    const float* dec_b  = (const float*)d_in[18];
    float* out = (float*)d_out;

    float *h_, *sc_, *t1_, *x1_, *x2_, *poolp_, *pool_;
    int* idx_;
    unsigned int* mskw_;
    __half *xh_, *hh_, *qkvh_, *ah_, *vth_;
    __half *ctxh_, *x1h_, *midh_, *nh_, *cbh_, *wh_;
    cudaGetSymbolAddress((void**)&h_,    g_h);
    cudaGetSymbolAddress((void**)&sc_,   g_sc);
    cudaGetSymbolAddress((void**)&t1_,   g_t1);
    cudaGetSymbolAddress((void**)&x1_,   g_x1);
    cudaGetSymbolAddress((void**)&x2_,   g_x2);
    cudaGetSymbolAddress((void**)&poolp_,g_poolp);
    cudaGetSymbolAddress((void**)&pool_, g_pool);
    cudaGetSymbolAddress((void**)&idx_,  g_idx);
    cudaGetSymbolAddress((void**)&mskw_, g_mskw);
    cudaGetSymbolAddress((void**)&xh_,   g_xh);
    cudaGetSymbolAddress((void**)&hh_,   g_hh);
    cudaGetSymbolAddress((void**)&qkvh_, g_qkvh);
    cudaGetSymbolAddress((void**)&ah_,   g_ah);
    cudaGetSymbolAddress((void**)&vth_,  g_vth);
    cudaGetSymbolAddress((void**)&ctxh_, g_ctxh);
    cudaGetSymbolAddress((void**)&x1h_,  g_x1h);
    cudaGetSymbolAddress((void**)&midh_, g_midh);
    cudaGetSymbolAddress((void**)&nh_,   g_nh);
    cudaGetSymbolAddress((void**)&cbh_,  g_cbh);
    cudaGetSymbolAddress((void**)&wh_,   g_wh);

    cudaFuncSetAttribute(mmagemm_k<1,0,1,1,0,0>, cudaFuncAttributeMaxDynamicSharedMemorySize, MMSMEM);
    cudaFuncSetAttribute(mmagemm_k<0,0,1,0,0,0>, cudaFuncAttributeMaxDynamicSharedMemorySize, MMSMEM);
    cudaFuncSetAttribute(mmagemm_k<0,0,0,1,0,0>, cudaFuncAttributeMaxDynamicSharedMemorySize, MMSMEM);
    cudaFuncSetAttribute(mmagemm_k<1,0,1,0,0,0>, cudaFuncAttributeMaxDynamicSharedMemorySize, MMSMEM);
    cudaFuncSetAttribute(mmagemm_k<0,1,0,1,0,0>, cudaFuncAttributeMaxDynamicSharedMemorySize, MMSMEM);
    cudaFuncSetAttribute(mmagemm_k<0,0,0,1,1,0>, cudaFuncAttributeMaxDynamicSharedMemorySize, MMSMEM);

    dim3 blk(256);

    // input conversion (hi only) + fused weight conversion
    splith_k<<<(ROWS*DIN/4 + 255)/256, blk>>>(x, xh_, (long)ROWS*DIN/4);
    wsplit_k<<<(720896 + 255)/256, blk>>>(enc_w, in_w, out_w, ffn_w1, ffn_w2, gc_w, wh_);

    // G1: h = relu(x @ enc_w^T + b), x hi-only (ALO=0), fp32 + fp16 hi
    mmagemm_k<1,0,1,1,0,0><<<dim3(4,256,1), blk, MMSMEM>>>(xh_, nullptr, wh_+WO_ENC,
        enc_b, nullptr, h_, hh_, nullptr, 512, 512, 512, 512, 0,0,0,0,0,0, 1);

    // G2: qkv = h @ in_w^T + b, h hi-only, fp16 hi output only
    mmagemm_k<0,0,1,0,0,0><<<dim3(12,256,1), blk, MMSMEM>>>(hh_, nullptr, wh_+WO_IN,
        in_b, nullptr, nullptr, qkvh_, nullptr, 512, 512, 512, 1536, 0,0,0,0,0,0, 1);

    // v transpose (reads qkv hi) -> vT fp16
    vtrans_k<<<dim3(8,32,64), dim3(32,8)>>>(qkvh_, vth_);

    // G3: scores = q @ k^T (batched z=64), q hi-only, fp16 hi output -> g_ah
    mmagemm_k<0,0,1,0,0,0><<<dim3(8,8,64), blk, MMSMEM>>>(qkvh_, nullptr, qkvh_+512,
        nullptr, nullptr, nullptr, ah_, nullptr, 256, 1536, 1536, 1024,
        256, (long)NS*1536, 256, (long)NS*1536, (long)NS*NS, 2L*NS*NS, 2);

    // in-place fp16 softmax (1/16 scale)
    softmax_split_k<<<NB*NHD*NS, 256>>>(ah_);

    // G4: ctx = attn @ vT^T (batched z=64), probs hi-only, ctx hi output only
    mmagemm_k<0,0,1,0,0,0><<<dim3(2,8,64), blk, MMSMEM>>>(ah_, nullptr, vth_,
        nullptr, nullptr, nullptr, ctxh_, nullptr, 1024, 1024, 1024, 512,
        (long)NS*NS, 2L*NS*NS, (long)DHH*NS, 2L*DHH*NS, 256, (long)NS*512, 2);

    // G5: attn_out = ctx @ out_w^T + b -> t1 fp32, ctx hi-only
    mmagemm_k<0,0,0,1,0,0><<<dim3(4,256,1), blk, MMSMEM>>>(ctxh_, nullptr, wh_+WO_OUT,
        out_b, nullptr, t1_, nullptr, nullptr, 512, 512, 512, 512, 0,0,0,0,0,0, 1);

    // x1 = LN(h + attn_out), fp32 + fp16 hi
    addln_k<<<ROWS, 256>>>(h_, t1_, ln1_g, ln1_b, x1_, x1h_);

    // G6: mid = relu(x1 @ ffn_w1^T + b1), x1 hi-only, mid hi output only
    mmagemm_k<1,0,1,0,0,0><<<dim3(8,256,1), blk, MMSMEM>>>(x1h_, nullptr, wh_+WO_F1,
        ffn_b1, nullptr, nullptr, midh_, nullptr, 512, 512, 512, 1024, 0,0,0,0,0,0, 1);

    // G7: x1 = x1 + mid @ ffn_w2^T + b2 (residual), mid hi-only, fp32
    mmagemm_k<0,1,0,1,0,0><<<dim3(4,256,1), blk, MMSMEM>>>(midh_, nullptr, wh_+WO_F2,
        ffn_b2, x1_, x1_, nullptr, nullptr, 1024, 1024, 1024, 512, 0,0,0,0,0,0, 1);

    // nrm = rownorm(x1), fp16 hi only
    rownorm_k<<<ROWS, 256>>>(x1_, nh_);

    // sim = nrm @ nrm^T (batched z=32), nrm hi-only (ALO=0), upper-triangle blocks
    mmagemm_k<0,0,0,1,1,0><<<dim3(36,1,32), blk, MMSMEM>>>(nh_, nullptr, nh_,
        nullptr, nullptr, sc_, nullptr, nullptr, 512, 512, 512, 1024,
        0, (long)NS*512, 0, (long)NS*512, 0, (long)NS*NS, 1);

    // mirror upper -> lower triangle
    mirror_k<<<dim3(28*16, NB), dim3(32,8)>>>(sc_);

    // adjacency (1-bit mask)
    zero_k<<<(int)(((long)NB*NS*32*4/16 + 255)/256), blk>>>((float4*)mskw_, (long)NB*NS*32*4/16);
    topk_k<<<ROWS, 128>>>(sc_, idx_);
    scatter_k<<<(ROWS+255)/256, blk>>>(idx_, mskw_);

    // combined = [x1 | nsum/cnt] -> fp16 hi only
    combine_k<<<ROWS, 512>>>(x1_, sc_, mskw_, cbh_);

    // G8: gco = combined @ gc_w^T + b -> t1 fp32, combined hi-only
    mmagemm_k<0,0,0,1,0,0><<<dim3(4,256,1), blk, MMSMEM>>>(cbh_, nullptr, wh_+WO_GC,
        gc_b, nullptr, t1_, nullptr, nullptr, 1024, 1024, 1024, 512, 0,0,0,0,0,0, 1);

    // x2 = LN(x1 + gco), fp32 only
    addln_k<<<ROWS, 256>>>(x1_, t1_, ln2_g, ln2_b, x2_, nullptr);

    // pool (two-stage) + decoder
    pool1_k<<<dim3(NB,8), 512>>>(x2_, poolp_);
    pool2_k<<<NB, 512>>>(poolp_, pool_);
    gemm_k<1,0,0><<<dim3(8,1,1), blk>>>(pool_, dec_w, dec_b, nullptr, out,
        32, 512, 512, 512, 512, 512);
}